// round 4
// baseline (speedup 1.0000x reference)
#include <cuda_runtime.h>
#include <cuda_bf16.h>
#include <cstdint>
#include <math.h>

// ---------------- problem constants ----------------
constexpr int cB = 16, cT = 1024, cD = 256, cH = 2, cDK = 64, cC = 1024;
constexpr int cNT = cB * cT;            // 16384 tokens
constexpr long cTT = (long)cT * cT;     // 1M
constexpr float LN_EPS = 1e-5f;

// ---------------- device scratch (no allocs allowed) ----------------
__device__ float g_q  [cNT * 128];
__device__ float g_k  [cNT * 128];
__device__ float g_v  [cNT * 128];
__device__ float g_ctx[cNT * 128];
__device__ float g_apre[cNT * cD];
__device__ float g_a   [cNT * cD];
__device__ float g_h  [cNT * cC];
__device__ float g_o2 [cNT * cD];
__device__ float g_dwn[cB * 9];
__device__ float g_pwn[cB * cC];
// bf16 split buffers
__device__ __nv_bfloat16 g_ah [cNT * cD];
__device__ __nv_bfloat16 g_al [cNT * cD];
__device__ __nv_bfloat16 g_deph[cNT * cC];
__device__ __nv_bfloat16 g_depl[cNT * cC];
__device__ __nv_bfloat16 g_pth [cNT * cC];
__device__ __nv_bfloat16 g_ptl [cNT * cC];
__device__ __nv_bfloat16 g_pwTh[(long)cB * cC * cC];
__device__ __nv_bfloat16 g_pwTl[(long)cB * cC * cC];
__device__ __nv_bfloat16 g_w1h [cC * cD];
__device__ __nv_bfloat16 g_w1l [cC * cD];
__device__ __nv_bfloat16 g_w2h [cD * cC];
__device__ __nv_bfloat16 g_w2l [cD * cC];

// ---------------- helpers ----------------
__device__ __forceinline__ uint32_t smem_u32(const void* p) {
    uint32_t a;
    asm("{ .reg .u64 t; cvta.to.shared.u64 t, %1; cvt.u32.u64 %0, t; }" : "=r"(a) : "l"(p));
    return a;
}
#define SW128(off) ((off) ^ (((off) >> 3) & 0x70))

__device__ __forceinline__ void split_bf16(float v, __nv_bfloat16& h, __nv_bfloat16& l) {
    h = __float2bfloat16(v);
    l = __float2bfloat16(v - __bfloat162float(h));
}

__device__ __forceinline__ void ldsm4(uint32_t* r, uint32_t addr) {
    asm volatile("ldmatrix.sync.aligned.m8n8.x4.shared.b16 {%0,%1,%2,%3}, [%4];"
        : "=r"(r[0]), "=r"(r[1]), "=r"(r[2]), "=r"(r[3]) : "r"(addr));
}
__device__ __forceinline__ void mma16816(float* d, const uint32_t* a, const uint32_t* b) {
    asm volatile("mma.sync.aligned.m16n8k16.row.col.f32.bf16.bf16.f32 "
        "{%0,%1,%2,%3}, {%4,%5,%6,%7}, {%8,%9}, {%0,%1,%2,%3};"
        : "+f"(d[0]), "+f"(d[1]), "+f"(d[2]), "+f"(d[3])
        : "r"(a[0]), "r"(a[1]), "r"(a[2]), "r"(a[3]), "r"(b[0]), "r"(b[1]));
}

__device__ __forceinline__ float warpReduceSum(float v) {
#pragma unroll
    for (int o = 16; o > 0; o >>= 1) v += __shfl_xor_sync(0xffffffffu, v, o);
    return v;
}
__device__ __forceinline__ float warpReduceMax(float v) {
#pragma unroll
    for (int o = 16; o > 0; o >>= 1) v = fmaxf(v, __shfl_xor_sync(0xffffffffu, v, o));
    return v;
}

// ---------------- mma.sync bf16-split GEMM ----------------
// D[M,N] = A[M,K] @ B[N,K]^T, A/B given as (hi,lo) bf16 pairs.
// acc += Ah*Bh + Ah*Bl + Al*Bh  (~fp32 precision)
// EPI: 2 = +bias[n] + aux[m*ldc+n] -> f32 C
//      3 = mish(acc+bias[n])       -> f32 C
//      4 = acc*aux[n] + bias[n]    -> split bf16 (Ch, Cl)
constexpr int MM_SMEM = 65536 + 1024;

template<int EPI>
__global__ void __launch_bounds__(256) mma_gemm(
    const __nv_bfloat16* __restrict__ Ah, const __nv_bfloat16* __restrict__ Al,
    const __nv_bfloat16* __restrict__ Bh, const __nv_bfloat16* __restrict__ Bl,
    float* __restrict__ C, __nv_bfloat16* __restrict__ Ch, __nv_bfloat16* __restrict__ Cl,
    int Kd, int lda, int ldb, int ldc,
    long aZ, long bZ, long cZ, long biasZ, long auxZ,
    const float* __restrict__ bias, const float* __restrict__ aux)
{
    extern __shared__ char sm_raw[];
    uint32_t sb0 = smem_u32(sm_raw);
    uint32_t sb  = (sb0 + 1023u) & ~1023u;
    char* base   = sm_raw + (sb - sb0);
    char* pAh = base, *pAl = base + 16384, *pBh = base + 32768, *pBl = base + 49152;
    uint32_t uAh = sb, uAl = sb + 16384, uBh = sb + 32768, uBl = sb + 49152;

    int z = blockIdx.z;
    Ah += (long)z * aZ; Al += (long)z * aZ;
    Bh += (long)z * bZ; Bl += (long)z * bZ;
    const float* biasp = bias + (long)z * biasZ;
    const float* auxp  = aux ? aux + (long)z * auxZ : nullptr;

    int m0 = blockIdx.y * 128, n0 = blockIdx.x * 128;
    int tid = threadIdx.x, wid = tid >> 5, lane = tid & 31;
    int wm = wid & 3, wn = wid >> 2;

    float acc[2][8][4];
#pragma unroll
    for (int i = 0; i < 2; i++)
#pragma unroll
        for (int j = 0; j < 8; j++)
#pragma unroll
            for (int l = 0; l < 4; l++) acc[i][j][l] = 0.f;

    for (int k0 = 0; k0 < Kd; k0 += 64) {
        // load tiles: 128 rows x 64 bf16 = 1024 uint4 per tile; 4 per thread per tile
#pragma unroll
        for (int t = 0; t < 4; t++) {
            int f = tid + t * 256;
            int row = f >> 3, cq = f & 7;
            uint32_t soff = SW128((uint32_t)(row * 128 + cq * 16));
            long ga = (long)(m0 + row) * lda + k0 + cq * 8;
            long gb = (long)(n0 + row) * ldb + k0 + cq * 8;
            *reinterpret_cast<uint4*>(pAh + soff) = *reinterpret_cast<const uint4*>(Ah + ga);
            *reinterpret_cast<uint4*>(pAl + soff) = *reinterpret_cast<const uint4*>(Al + ga);
            *reinterpret_cast<uint4*>(pBh + soff) = *reinterpret_cast<const uint4*>(Bh + gb);
            *reinterpret_cast<uint4*>(pBl + soff) = *reinterpret_cast<const uint4*>(Bl + gb);
        }
        __syncthreads();

#pragma unroll
        for (int ks = 0; ks < 4; ks++) {
            uint32_t afh[2][4], afl[2][4], bfh[4][4], bfl[4][4];
#pragma unroll
            for (int mt = 0; mt < 2; mt++) {
                int r = wm * 32 + mt * 16 + (lane & 15);
                int kc = ks * 2 + (lane >> 4);
                uint32_t off = SW128((uint32_t)(r * 128 + kc * 16));
                ldsm4(afh[mt], uAh + off);
                ldsm4(afl[mt], uAl + off);
            }
#pragma unroll
            for (int bt = 0; bt < 4; bt++) {
                int r = wn * 64 + bt * 16 + (lane & 7) + ((lane >> 4) << 3);
                int kc = ks * 2 + ((lane >> 3) & 1);
                uint32_t off = SW128((uint32_t)(r * 128 + kc * 16));
                ldsm4(bfh[bt], uBh + off);
                ldsm4(bfl[bt], uBl + off);
            }
            // 3 split products; consecutive mmas hit different accumulators
#pragma unroll
            for (int p = 0; p < 3; p++) {
#pragma unroll
                for (int mt = 0; mt < 2; mt++)
#pragma unroll
                    for (int bt = 0; bt < 4; bt++)
#pragma unroll
                        for (int hh = 0; hh < 2; hh++) {
                            const uint32_t* af = (p == 2) ? afl[mt] : afh[mt];
                            const uint32_t* bf = (p == 1) ? &bfl[bt][hh * 2] : &bfh[bt][hh * 2];
                            mma16816(acc[mt][bt * 2 + hh], af, bf);
                        }
            }
        }
        __syncthreads();
    }

    // epilogue
#pragma unroll
    for (int mt = 0; mt < 2; mt++)
#pragma unroll
        for (int bt = 0; bt < 4; bt++)
#pragma unroll
            for (int hh = 0; hh < 2; hh++) {
                float* d = acc[mt][bt * 2 + hh];
                int col = n0 + wn * 64 + bt * 16 + hh * 8 + (lane & 3) * 2;
                int r0  = m0 + wm * 32 + mt * 16 + (lane >> 2);
#pragma unroll
                for (int half = 0; half < 2; half++) {
                    int row = r0 + half * 8;
                    float t0 = d[half * 2 + 0], t1 = d[half * 2 + 1];
                    if (EPI == 2) {
                        t0 += biasp[col]     + auxp[(long)row * ldc + col];
                        t1 += biasp[col + 1] + auxp[(long)row * ldc + col + 1];
                        float2 v = {t0, t1};
                        *reinterpret_cast<float2*>(C + (long)row * ldc + col) = v;
                    } else if (EPI == 3) {
                        t0 += biasp[col];
                        t1 += biasp[col + 1];
                        float sp0 = (t0 > 20.f) ? t0 : log1pf(expf(t0));
                        float sp1 = (t1 > 20.f) ? t1 : log1pf(expf(t1));
                        t0 = t0 * tanhf(sp0);
                        t1 = t1 * tanhf(sp1);
                        float2 v = {t0, t1};
                        *reinterpret_cast<float2*>(C + (long)row * ldc + col) = v;
                    } else { // EPI 4: split-bf16 output
                        t0 = t0 * auxp[col]     + biasp[col];
                        t1 = t1 * auxp[col + 1] + biasp[col + 1];
                        __nv_bfloat16 h0, l0, h1, l1;
                        split_bf16(t0, h0, l0);
                        split_bf16(t1, h1, l1);
                        __nv_bfloat162 hv = {h0, h1}, lv = {l0, l1};
                        long o = (long)z * cZ + (long)row * ldc + col;
                        *reinterpret_cast<__nv_bfloat162*>(Ch + o) = hv;
                        *reinterpret_cast<__nv_bfloat162*>(Cl + o) = lv;
                    }
                }
            }
}

// ---------------- fp32 tiled SGEMM (attention path) ----------------
template<bool BT, int EPI>
__global__ void __launch_bounds__(256) gemm_k(
    const float* __restrict__ A, const float* __restrict__ Bm, float* __restrict__ C,
    int M, int N, int Kd, int lda, int ldb, int ldc,
    long aQ, long aR, long bQ, long bR, long cQ, long cR, int zdiv,
    const float* __restrict__ bias, const float* __restrict__ aux,
    long biasQ, long auxQ)
{
    constexpr int BM = 128, BN = 64, BK = 16, TM = 8, TN = 4;
    __shared__ float As[BK][BM + 4];
    __shared__ float Bs[BK][BN + 4];

    int z  = blockIdx.z;
    int zq = z / zdiv, zr = z - zq * zdiv;
    A  += (long)zq * aQ + (long)zr * aR;
    Bm += (long)zq * bQ + (long)zr * bR;
    C  += (long)zq * cQ + (long)zr * cR;
    const float* biasp = bias ? bias + (long)zq * biasQ : nullptr;
    const float* auxp  = aux  ? aux  + (long)zq * auxQ  : nullptr;

    int bm0 = blockIdx.y * BM, bn0 = blockIdx.x * BN;
    int tid = threadIdx.x;
    int tx = tid & 15, ty = tid >> 4;

    float acc[TM][TN];
#pragma unroll
    for (int i = 0; i < TM; i++)
#pragma unroll
        for (int j = 0; j < TN; j++) acc[i][j] = 0.f;

    for (int k0 = 0; k0 < Kd; k0 += BK) {
#pragma unroll
        for (int r = 0; r < 2; r++) {
            int f   = tid + r * 256;
            int row = f >> 2;
            int kq  = f & 3;
            float4 av = *reinterpret_cast<const float4*>(A + (long)(bm0 + row) * lda + k0 + kq * 4);
            As[kq * 4 + 0][row] = av.x; As[kq * 4 + 1][row] = av.y;
            As[kq * 4 + 2][row] = av.z; As[kq * 4 + 3][row] = av.w;
        }
        if (BT) {
            int m = tid >> 2, kq = tid & 3;
            float4 bv = *reinterpret_cast<const float4*>(Bm + (long)(bn0 + m) * ldb + k0 + kq * 4);
            Bs[kq * 4 + 0][m] = bv.x; Bs[kq * 4 + 1][m] = bv.y;
            Bs[kq * 4 + 2][m] = bv.z; Bs[kq * 4 + 3][m] = bv.w;
        } else {
            int kk = tid >> 4, mq = tid & 15;
            float4 bv = *reinterpret_cast<const float4*>(Bm + (long)(k0 + kk) * ldb + bn0 + mq * 4);
            *reinterpret_cast<float4*>(&Bs[kk][mq * 4]) = bv;
        }
        __syncthreads();
#pragma unroll
        for (int kk = 0; kk < BK; kk++) {
            float4 a0 = *reinterpret_cast<const float4*>(&As[kk][ty * TM]);
            float4 a1 = *reinterpret_cast<const float4*>(&As[kk][ty * TM + 4]);
            float4 b0 = *reinterpret_cast<const float4*>(&Bs[kk][tx * TN]);
            float af[TM] = {a0.x, a0.y, a0.z, a0.w, a1.x, a1.y, a1.z, a1.w};
            float bf[TN] = {b0.x, b0.y, b0.z, b0.w};
#pragma unroll
            for (int i = 0; i < TM; i++)
#pragma unroll
                for (int j = 0; j < TN; j++) acc[i][j] += af[i] * bf[j];
        }
        __syncthreads();
    }

    int col0 = bn0 + tx * TN;
#pragma unroll
    for (int i = 0; i < TM; i++) {
        int row = bm0 + ty * TM + i;
        float r[TN];
#pragma unroll
        for (int j = 0; j < TN; j++) {
            float t = acc[i][j];
            if (EPI == 1) t += biasp[col0 + j];
            else if (EPI == 2) t += biasp[col0 + j] + auxp[(long)row * ldc + col0 + j];
            else if (EPI == 5) t *= 0.125f;
            r[j] = t;
        }
        float4 v4 = {r[0], r[1], r[2], r[3]};
        *reinterpret_cast<float4*>(C + (long)row * ldc + col0) = v4;
    }
}

// ---------------- softmax (in place on attn rows) ----------------
__global__ void __launch_bounds__(256) softmax_k(float* __restrict__ attn,
                                                 const unsigned char* __restrict__ smask)
{
    int i = blockIdx.x, h = blockIdx.y, b = blockIdx.z;
    float* row = attn + (((long)(b * cH + h)) * cT + i) * cT;
    const unsigned char* mrow = smask + ((long)b * cT + i) * cT;
    int tid = threadIdx.x, lane = tid & 31, wid = tid >> 5;
    __shared__ float red[8];
    __shared__ float bc;

    float v[4];
    float mx = -3.4e38f;
#pragma unroll
    for (int r = 0; r < 4; r++) {
        int j = tid + r * 256;
        float s = row[j];
        if (mrow[j]) s = -1e9f;
        v[r] = s;
        mx = fmaxf(mx, s);
    }
    mx = warpReduceMax(mx);
    if (lane == 0) red[wid] = mx;
    __syncthreads();
    if (wid == 0) {
        float r = (lane < 8) ? red[lane] : -3.4e38f;
        r = warpReduceMax(r);
        if (lane == 0) bc = r;
    }
    __syncthreads();
    mx = bc;
    float sum = 0.f;
#pragma unroll
    for (int r = 0; r < 4; r++) { v[r] = expf(v[r] - mx); sum += v[r]; }
    __syncthreads();
    sum = warpReduceSum(sum);
    if (lane == 0) red[wid] = sum;
    __syncthreads();
    if (wid == 0) {
        float r = (lane < 8) ? red[lane] : 0.f;
        r = warpReduceSum(r);
        if (lane == 0) bc = r;
    }
    __syncthreads();
    float inv = 1.f / bc;
#pragma unroll
    for (int r = 0; r < 4; r++) row[tid + r * 256] = v[r] * inv;
}

// ---------------- LayerNorm over D=256; optionally emits bf16 split ----------------
__global__ void __launch_bounds__(256) ln_k(const float* __restrict__ in,
                                            const float* __restrict__ g,
                                            const float* __restrict__ bta,
                                            const unsigned char* __restrict__ mask,
                                            float* __restrict__ out,
                                            __nv_bfloat16* __restrict__ oh,
                                            __nv_bfloat16* __restrict__ ol)
{
    long n = blockIdx.x;
    int tid = threadIdx.x, lane = tid & 31, wid = tid >> 5;
    __shared__ float red[8];
    __shared__ float stats[2];

    float x = in[n * cD + tid];
    float s = warpReduceSum(x);
    if (lane == 0) red[wid] = s;
    __syncthreads();
    if (wid == 0) {
        float r = (lane < 8) ? red[lane] : 0.f;
        r = warpReduceSum(r);
        if (lane == 0) stats[0] = r;
    }
    __syncthreads();
    float s2 = warpReduceSum(x * x);
    if (lane == 0) red[wid] = s2;
    __syncthreads();
    if (wid == 0) {
        float r = (lane < 8) ? red[lane] : 0.f;
        r = warpReduceSum(r);
        if (lane == 0) stats[1] = r;
    }
    __syncthreads();
    float mean = stats[0] * (1.f / cD);
    float var  = stats[1] * (1.f / cD) - mean * mean;
    float y = (x - mean) * rsqrtf(var + LN_EPS) * g[tid] + bta[tid];
    if (mask[n]) y = 0.f;
    out[n * cD + tid] = y;
    if (oh) {
        __nv_bfloat16 h, l;
        split_bf16(y, h, l);
        oh[n * cD + tid] = h;
        ol[n * cD + tid] = l;
    }
}

// ---------------- fp32 -> bf16 hi/lo split (elementwise) ----------------
__global__ void __launch_bounds__(256) cvt_split(const float* __restrict__ in,
                                                 __nv_bfloat16* __restrict__ oh,
                                                 __nv_bfloat16* __restrict__ ol, long n)
{
    long i = ((long)blockIdx.x * 256 + threadIdx.x) * 4;
    if (i >= n) return;
    float4 v = *reinterpret_cast<const float4*>(in + i);
    __nv_bfloat16 h0, h1, h2, h3, l0, l1, l2, l3;
    split_bf16(v.x, h0, l0); split_bf16(v.y, h1, l1);
    split_bf16(v.z, h2, l2); split_bf16(v.w, h3, l3);
    __nv_bfloat162 ha = {h0, h1}, hb = {h2, h3}, la = {l0, l1}, lb = {l2, l3};
    *reinterpret_cast<__nv_bfloat162*>(oh + i)     = ha;
    *reinterpret_cast<__nv_bfloat162*>(oh + i + 2) = hb;
    *reinterpret_cast<__nv_bfloat162*>(ol + i)     = la;
    *reinterpret_cast<__nv_bfloat162*>(ol + i + 2) = lb;
}

// ---------------- p_w transpose + split: in[b][c][o] -> out[b][o][c] ----------------
__global__ void __launch_bounds__(256) cvtT_k(const float* __restrict__ in,
                                              __nv_bfloat16* __restrict__ oh,
                                              __nv_bfloat16* __restrict__ ol)
{
    __shared__ float tile[32][33];
    int b = blockIdx.z;
    int o0 = blockIdx.x * 32, c0 = blockIdx.y * 32;
    int tx = threadIdx.x & 31, ty = threadIdx.x >> 5;  // 32 x 8
    const float* src = in + (long)b * cC * cC;
#pragma unroll
    for (int i = 0; i < 4; i++) {
        int c = c0 + ty + i * 8;
        tile[ty + i * 8][tx] = src[(long)c * cC + o0 + tx];
    }
    __syncthreads();
    __nv_bfloat16* dh = oh + (long)b * cC * cC;
    __nv_bfloat16* dl = ol + (long)b * cC * cC;
#pragma unroll
    for (int i = 0; i < 4; i++) {
        int o = o0 + ty + i * 8;
        float v = tile[tx][ty + i * 8];
        __nv_bfloat16 h, l;
        split_bf16(v, h, l);
        dh[(long)o * cC + c0 + tx] = h;
        dl[(long)o * cC + c0 + tx] = l;
    }
}

// ---------------- depthwise weight inverse norms ----------------
__global__ void __launch_bounds__(128) dwn_k(const float* __restrict__ d_w, float* __restrict__ dwn)
{
    int k = blockIdx.x, b = blockIdx.y;
    int tid = threadIdx.x;
    float s = 0.f;
    for (int c = tid; c < cC; c += 128) {
        float w = d_w[((long)b * cC + c) * 9 + k];
        s += w * w;
    }
    __shared__ float red[4];
    s = warpReduceSum(s);
    if ((tid & 31) == 0) red[tid >> 5] = s;
    __syncthreads();
    if (tid == 0) {
        float r = red[0] + red[1] + red[2] + red[3];
        dwn[b * 9 + k] = 1.f / fmaxf(sqrtf(r), 1e-12f);
    }
}

__global__ void __launch_bounds__(256) pwn_k(const float* __restrict__ p_w, float* __restrict__ pwn)
{
    int c1 = blockIdx.x * 256 + threadIdx.x;
    int b = blockIdx.y;
    const float* base = p_w + (long)b * cC * cC + c1;
    float s = 0.f;
    for (int c2 = 0; c2 < cC; c2++) {
        float w = base[(long)c2 * cC];
        s += w * w;
    }
    pwn[b * cC + c1] = 1.f / fmaxf(sqrtf(s), 1e-12f);
}

// ---------------- depthwise conv (K=9), fused scalings, bf16-split output ----------------
__global__ void __launch_bounds__(256) conv_k(const float* __restrict__ h,
                                              const float* __restrict__ d_w,
                                              const float* __restrict__ d_g,
                                              const float* __restrict__ d_b,
                                              const float* __restrict__ p_g,
                                              const float* __restrict__ dwn,
                                              __nv_bfloat16* __restrict__ deph,
                                              __nv_bfloat16* __restrict__ depl)
{
    int t = blockIdx.x, b = blockIdx.y;
    __shared__ float wk[9];
    if (threadIdx.x < 9) wk[threadIdx.x] = dwn[b * 9 + threadIdx.x];
    __syncthreads();
#pragma unroll
    for (int i = 0; i < 4; i++) {
        int c = threadIdx.x + i * 256;
        const float* wrow = d_w + ((long)b * cC + c) * 9;
        float acc = 0.f;
#pragma unroll
        for (int kk = 0; kk < 9; kk++) {
            int tt = t + kk - 4;
            if (tt >= 0 && tt < cT)
                acc += h[((long)b * cT + tt) * cC + c] * (wrow[kk] * wk[kk]);
        }
        long bc = (long)b * cC + c;
        float val = (acc * d_g[bc] + d_b[bc]) * p_g[bc];
        __nv_bfloat16 hi, lo;
        split_bf16(val, hi, lo);
        long o = ((long)b * cT + t) * cC + c;
        deph[o] = hi;
        depl[o] = lo;
    }
}

// ---------------- launch ----------------
extern "C" void kernel_launch(void* const* d_in, const int* in_sizes, int n_in,
                              void* d_out, int out_size)
{
    const float* x    = (const float*)d_in[0];
    const float* d_w  = (const float*)d_in[1];
    const float* d_g  = (const float*)d_in[2];
    const float* d_b  = (const float*)d_in[3];
    const float* p_w  = (const float*)d_in[4];
    const float* p_g  = (const float*)d_in[5];
    const float* p_b  = (const float*)d_in[6];
    const unsigned char* mask  = (const unsigned char*)d_in[7];
    const unsigned char* smask = (const unsigned char*)d_in[8];
    const float* Wq = (const float*)d_in[9];
    const float* bq = (const float*)d_in[10];
    const float* Wk = (const float*)d_in[11];
    const float* bk = (const float*)d_in[12];
    const float* Wv = (const float*)d_in[13];
    const float* bv = (const float*)d_in[14];
    const float* Wo = (const float*)d_in[15];
    const float* bo = (const float*)d_in[16];
    const float* g0 = (const float*)d_in[17];
    const float* b0 = (const float*)d_in[18];
    const float* w1_w = (const float*)d_in[19];
    const float* w1_b = (const float*)d_in[20];
    const float* w2_w = (const float*)d_in[21];
    const float* w2_b = (const float*)d_in[22];
    const float* g1 = (const float*)d_in[23];
    const float* b1 = (const float*)d_in[24];

    float* out  = (float*)d_out;
    float* attn = out + (long)cNT * cD;   // output tuple: (out[B,T,D], attn[B,H,T,T])

    float *q, *k, *v, *ctx, *apre, *a, *h, *o2, *dwn, *pwn;
    __nv_bfloat16 *ah, *al, *deph, *depl, *pth, *ptl, *pwTh, *pwTl, *w1h, *w1l, *w2h, *w2l;
    cudaGetSymbolAddress((void**)&q,    g_q);
    cudaGetSymbolAddress((void**)&k,    g_k);
    cudaGetSymbolAddress((void**)&v,    g_v);
    cudaGetSymbolAddress((void**)&ctx,  g_ctx);
    cudaGetSymbolAddress((void**)&apre, g_apre);
    cudaGetSymbolAddress((void**)&a,    g_a);
    cudaGetSymbolAddress((void**)&h,    g_h);
    cudaGetSymbolAddress((void**)&o2,   g_o2);
    cudaGetSymbolAddress((void**)&dwn,  g_dwn);
    cudaGetSymbolAddress((void**)&pwn,  g_pwn);
    cudaGetSymbolAddress((void**)&ah,   g_ah);
    cudaGetSymbolAddress((void**)&al,   g_al);
    cudaGetSymbolAddress((void**)&deph, g_deph);
    cudaGetSymbolAddress((void**)&depl, g_depl);
    cudaGetSymbolAddress((void**)&pth,  g_pth);
    cudaGetSymbolAddress((void**)&ptl,  g_ptl);
    cudaGetSymbolAddress((void**)&pwTh, g_pwTh);
    cudaGetSymbolAddress((void**)&pwTl, g_pwTl);
    cudaGetSymbolAddress((void**)&w1h,  g_w1h);
    cudaGetSymbolAddress((void**)&w1l,  g_w1l);
    cudaGetSymbolAddress((void**)&w2h,  g_w2h);
    cudaGetSymbolAddress((void**)&w2l,  g_w2l);

    cudaFuncSetAttribute(mma_gemm<2>, cudaFuncAttributeMaxDynamicSharedMemorySize, MM_SMEM);
    cudaFuncSetAttribute(mma_gemm<3>, cudaFuncAttributeMaxDynamicSharedMemorySize, MM_SMEM);
    cudaFuncSetAttribute(mma_gemm<4>, cudaFuncAttributeMaxDynamicSharedMemorySize, MM_SMEM);

    dim3 blk(256);

    // 1) q,k,v projections (fp32)
    gemm_k<true, 1><<<dim3(2, 128, 1), blk>>>(x, Wq, q, cNT, 128, cD, cD, cD, 128,
        0, 0, 0, 0, 0, 0, 1, bq, nullptr, 0, 0);
    gemm_k<true, 1><<<dim3(2, 128, 1), blk>>>(x, Wk, k, cNT, 128, cD, cD, cD, 128,
        0, 0, 0, 0, 0, 0, 1, bk, nullptr, 0, 0);
    gemm_k<true, 1><<<dim3(2, 128, 1), blk>>>(x, Wv, v, cNT, 128, cD, cD, cD, 128,
        0, 0, 0, 0, 0, 0, 1, bv, nullptr, 0, 0);

    // 2) scores = q k^T / 8
    gemm_k<true, 5><<<dim3(16, 8, 32), blk>>>(q, k, attn, cT, cT, cDK, 128, 128, cT,
        (long)cT * 128, 64, (long)cT * 128, 64, 2 * cTT, cTT, cH, nullptr, nullptr, 0, 0);

    // 3) masked softmax (writes final attn output)
    softmax_k<<<dim3(cT, cH, cB), blk>>>(attn, smask);

    // 4) ctx = attn @ v
    gemm_k<false, 0><<<dim3(1, 8, 32), blk>>>(attn, v, ctx, cT, cDK, cT, cT, 128, 128,
        2 * cTT, cTT, (long)cT * 128, 64, (long)cT * 128, 64, cH, nullptr, nullptr, 0, 0);

    // 5) apre = ctx @ Wo^T + bo + x
    gemm_k<true, 2><<<dim3(4, 128, 1), blk>>>(ctx, Wo, apre, cNT, cD, 128, 128, 128, cD,
        0, 0, 0, 0, 0, 0, 1, bo, x, 0, 0);

    // 6) a = LN(apre), masked; also emit bf16 split
    ln_k<<<cNT, blk>>>(apre, g0, b0, mask, a, ah, al);

    // 7) weight splits (+ transpose for p_w)
    cvt_split<<<(cC * cD) / 1024, blk>>>(w1_w, w1h, w1l, (long)cC * cD);
    cvt_split<<<(cD * cC) / 1024, blk>>>(w2_w, w2h, w2l, (long)cD * cC);
    cvtT_k<<<dim3(32, 32, cB), blk>>>(p_w, pwTh, pwTl);

    // 8) h = mish(a @ w1^T + w1_b)   [tensor]
    mma_gemm<3><<<dim3(cC / 128, cNT / 128, 1), blk, MM_SMEM>>>(
        ah, al, w1h, w1l, h, nullptr, nullptr,
        cD, cD, cD, cC, 0, 0, 0, 0, 0, w1_b, nullptr);

    // 9) weight norms + depthwise conv (emits dep split)
    dwn_k<<<dim3(9, cB), 128>>>(d_w, dwn);
    pwn_k<<<dim3(4, cB), blk>>>(p_w, pwn);
    conv_k<<<dim3(cT, cB), blk>>>(h, d_w, d_g, d_b, p_g, dwn, deph, depl);

    // 10) pt = (dep' @ pwT) * pwninv[o] + p_b  [tensor, batched over b; split output]
    mma_gemm<4><<<dim3(cC / 128, cT / 128, cB), blk, MM_SMEM>>>(
        deph, depl, pwTh, pwTl, nullptr, pth, ptl,
        cC, cC, cC, cC, (long)cT * cC, (long)cC * cC, (long)cT * cC, cC, cC, p_b, pwn);

    // 11) o2 = pt @ w2^T + w2_b + a   [tensor]
    mma_gemm<2><<<dim3(cD / 128, cNT / 128, 1), blk, MM_SMEM>>>(
        pth, ptl, w2h, w2l, o2, nullptr, nullptr,
        cC, cC, cC, cD, 0, 0, 0, 0, 0, w2_b, a);

    // 12) out = LN(o2), masked
    ln_k<<<cNT, blk>>>(o2, g1, b1, mask, out, nullptr, nullptr);
}

// round 5
// speedup vs baseline: 2.0408x; 2.0408x over previous
#include <cuda_runtime.h>
#include <cuda_fp16.h>
#include <cstdint>
#include <math.h>

// ---------------- problem constants ----------------
constexpr int cB = 16, cT = 1024, cD = 256, cH = 2, cDK = 64, cC = 1024;
constexpr int cNT = cB * cT;            // 16384 tokens
constexpr long cTT = (long)cT * cT;     // 1M
constexpr float LN_EPS = 1e-5f;

// ---------------- device scratch (no allocs allowed) ----------------
__device__ float g_q  [cNT * 128];
__device__ float g_k  [cNT * 128];
__device__ float g_v  [cNT * 128];
__device__ float g_ctx[cNT * 128];
__device__ float g_apre[cNT * cD];
__device__ float g_a   [cNT * cD];
__device__ float g_h  [cNT * cC];
__device__ float g_o2 [cNT * cD];
__device__ float g_dwn[cB * 9];
__device__ float g_pwn[cB * cC];
// fp16 split buffers (A operands: hi+lo; B operands: single)
__device__ __half g_ah  [cNT * cD];
__device__ __half g_al  [cNT * cD];
__device__ __half g_deph[cNT * cC];
__device__ __half g_depl[cNT * cC];
__device__ __half g_pth [cNT * cC];
__device__ __half g_ptl [cNT * cC];
__device__ __half g_pwT [(long)cB * cC * cC];
__device__ __half g_w1  [cC * cD];
__device__ __half g_w2  [cD * cC];

// ---------------- helpers ----------------
__device__ __forceinline__ uint32_t smem_u32(const void* p) {
    uint32_t a;
    asm("{ .reg .u64 t; cvta.to.shared.u64 t, %1; cvt.u32.u64 %0, t; }" : "=r"(a) : "l"(p));
    return a;
}
#define SW128(off) ((off) ^ (((off) >> 3) & 0x70))

__device__ __forceinline__ void split_h(float v, __half& h, __half& l) {
    h = __float2half_rn(v);
    l = __float2half_rn(v - __half2float(h));
}

__device__ __forceinline__ void ldsm4(uint32_t* r, uint32_t addr) {
    asm volatile("ldmatrix.sync.aligned.m8n8.x4.shared.b16 {%0,%1,%2,%3}, [%4];"
        : "=r"(r[0]), "=r"(r[1]), "=r"(r[2]), "=r"(r[3]) : "r"(addr));
}
__device__ __forceinline__ void mma16816(float* d, const uint32_t* a, const uint32_t* b) {
    asm volatile("mma.sync.aligned.m16n8k16.row.col.f32.f16.f16.f32 "
        "{%0,%1,%2,%3}, {%4,%5,%6,%7}, {%8,%9}, {%0,%1,%2,%3};"
        : "+f"(d[0]), "+f"(d[1]), "+f"(d[2]), "+f"(d[3])
        : "r"(a[0]), "r"(a[1]), "r"(a[2]), "r"(a[3]), "r"(b[0]), "r"(b[1]));
}
__device__ __forceinline__ void cp16(uint32_t saddr, const void* gptr) {
    asm volatile("cp.async.cg.shared.global [%0], [%1], 16;"
        :: "r"(saddr), "l"(__cvta_generic_to_global(gptr)));
}
__device__ __forceinline__ void cp_commit() {
    asm volatile("cp.async.commit_group;");
}
template<int N>
__device__ __forceinline__ void cp_wait() {
    asm volatile("cp.async.wait_group %0;" :: "n"(N));
}

__device__ __forceinline__ float warpReduceSum(float v) {
#pragma unroll
    for (int o = 16; o > 0; o >>= 1) v += __shfl_xor_sync(0xffffffffu, v, o);
    return v;
}
__device__ __forceinline__ float warpReduceMax(float v) {
#pragma unroll
    for (int o = 16; o > 0; o >>= 1) v = fmaxf(v, __shfl_xor_sync(0xffffffffu, v, o));
    return v;
}

// ---------------- mma.sync fp16-split GEMM, 2-stage cp.async pipeline ----------------
// D[M,N] = A[M,K] @ B[N,K]^T.  A = Ah + Al (fp16 split), B single fp16.
// acc += Ah*B + Al*B   (2 products; ~2^-12 relative accuracy from B rounding)
// EPI: 2 = +bias[n] + aux[m*ldc+n] -> f32 C
//      3 = mish(acc+bias[n])       -> f32 C
//      4 = acc*aux[n] + bias[n]    -> fp16 split (Ch, Cl)
constexpr int MM_STAGE = 3 * 16384;            // Ah, Al, B tiles: 128x64 fp16 each
constexpr int MM_SMEM  = 2 * MM_STAGE + 1024;  // double-buffered + align pad

template<int EPI>
__global__ void __launch_bounds__(256) mma_gemm(
    const __half* __restrict__ Ah, const __half* __restrict__ Al,
    const __half* __restrict__ Bp,
    float* __restrict__ C, __half* __restrict__ Ch, __half* __restrict__ Cl,
    int Kd, int lda, int ldb, int ldc,
    long aZ, long bZ, long cZ, long biasZ, long auxZ,
    const float* __restrict__ bias, const float* __restrict__ aux)
{
    extern __shared__ char sm_raw[];
    uint32_t sb0 = smem_u32(sm_raw);
    uint32_t sb  = (sb0 + 1023u) & ~1023u;

    int z = blockIdx.z;
    Ah += (long)z * aZ; Al += (long)z * aZ;
    Bp += (long)z * bZ;
    const float* biasp = bias + (long)z * biasZ;
    const float* auxp  = aux ? aux + (long)z * auxZ : nullptr;

    int m0 = blockIdx.y * 128, n0 = blockIdx.x * 128;
    int tid = threadIdx.x, wid = tid >> 5, lane = tid & 31;
    int wm = wid & 3, wn = wid >> 2;

    // per-thread load geometry: f = tid + ti*256 -> row = f>>3 (0..127), cq = f&7
    int lrow = tid >> 3, lcq = tid & 7;

    auto issue_stage = [&](int k0, uint32_t sbase) {
#pragma unroll
        for (int ti = 0; ti < 4; ti++) {
            int row = lrow + ti * 32;
            uint32_t soff = SW128((uint32_t)(row * 128 + lcq * 16));
            long ga = (long)(m0 + row) * lda + k0 + lcq * 8;
            long gb = (long)(n0 + row) * ldb + k0 + lcq * 8;
            cp16(sbase + soff,         Ah + ga);
            cp16(sbase + 16384 + soff, Al + ga);
            cp16(sbase + 32768 + soff, Bp + gb);
        }
        cp_commit();
    };

    float acc[2][8][4];
#pragma unroll
    for (int i = 0; i < 2; i++)
#pragma unroll
        for (int j = 0; j < 8; j++)
#pragma unroll
            for (int l = 0; l < 4; l++) acc[i][j][l] = 0.f;

    int nk = Kd >> 6;
    issue_stage(0, sb);

    for (int i = 0; i < nk; i++) {
        uint32_t cur = sb + (uint32_t)(i & 1) * MM_STAGE;
        if (i + 1 < nk) {
            issue_stage((i + 1) << 6, sb + (uint32_t)((i + 1) & 1) * MM_STAGE);
            cp_wait<1>();
        } else {
            cp_wait<0>();
        }
        __syncthreads();

        uint32_t uAh = cur, uAl = cur + 16384, uB = cur + 32768;
#pragma unroll
        for (int ks = 0; ks < 4; ks++) {
            uint32_t afh[2][4], afl[2][4], bf[4][4];
#pragma unroll
            for (int mt = 0; mt < 2; mt++) {
                int r = wm * 32 + mt * 16 + (lane & 15);
                int kc = ks * 2 + (lane >> 4);
                uint32_t off = SW128((uint32_t)(r * 128 + kc * 16));
                ldsm4(afh[mt], uAh + off);
                ldsm4(afl[mt], uAl + off);
            }
#pragma unroll
            for (int bt = 0; bt < 4; bt++) {
                int r = wn * 64 + bt * 16 + (lane & 7) + ((lane >> 4) << 3);
                int kc = ks * 2 + ((lane >> 3) & 1);
                uint32_t off = SW128((uint32_t)(r * 128 + kc * 16));
                ldsm4(bf[bt], uB + off);
            }
#pragma unroll
            for (int p = 0; p < 2; p++)
#pragma unroll
                for (int mt = 0; mt < 2; mt++)
#pragma unroll
                    for (int bt = 0; bt < 4; bt++)
#pragma unroll
                        for (int hh = 0; hh < 2; hh++) {
                            const uint32_t* af = (p == 0) ? afh[mt] : afl[mt];
                            mma16816(acc[mt][bt * 2 + hh], af, &bf[bt][hh * 2]);
                        }
        }
        __syncthreads();
    }

    // epilogue
#pragma unroll
    for (int mt = 0; mt < 2; mt++)
#pragma unroll
        for (int bt = 0; bt < 4; bt++)
#pragma unroll
            for (int hh = 0; hh < 2; hh++) {
                float* d = acc[mt][bt * 2 + hh];
                int col = n0 + wn * 64 + bt * 16 + hh * 8 + (lane & 3) * 2;
                int r0  = m0 + wm * 32 + mt * 16 + (lane >> 2);
#pragma unroll
                for (int half = 0; half < 2; half++) {
                    int row = r0 + half * 8;
                    float t0 = d[half * 2 + 0], t1 = d[half * 2 + 1];
                    if (EPI == 2) {
                        t0 += biasp[col]     + auxp[(long)row * ldc + col];
                        t1 += biasp[col + 1] + auxp[(long)row * ldc + col + 1];
                        float2 v = {t0, t1};
                        *reinterpret_cast<float2*>(C + (long)row * ldc + col) = v;
                    } else if (EPI == 3) {
                        t0 += biasp[col];
                        t1 += biasp[col + 1];
                        float sp0 = (t0 > 20.f) ? t0 : log1pf(expf(t0));
                        float sp1 = (t1 > 20.f) ? t1 : log1pf(expf(t1));
                        t0 = t0 * tanhf(sp0);
                        t1 = t1 * tanhf(sp1);
                        float2 v = {t0, t1};
                        *reinterpret_cast<float2*>(C + (long)row * ldc + col) = v;
                    } else { // EPI 4: fp16-split output
                        t0 = t0 * auxp[col]     + biasp[col];
                        t1 = t1 * auxp[col + 1] + biasp[col + 1];
                        __half h0, l0, h1, l1;
                        split_h(t0, h0, l0);
                        split_h(t1, h1, l1);
                        __half2 hv = {h0, h1}, lv = {l0, l1};
                        long o = (long)z * cZ + (long)row * ldc + col;
                        *reinterpret_cast<__half2*>(Ch + o) = hv;
                        *reinterpret_cast<__half2*>(Cl + o) = lv;
                    }
                }
            }
}

// ---------------- fp32 tiled SGEMM (attention path) ----------------
template<bool BT, int EPI>
__global__ void __launch_bounds__(256) gemm_k(
    const float* __restrict__ A, const float* __restrict__ Bm, float* __restrict__ C,
    int M, int N, int Kd, int lda, int ldb, int ldc,
    long aQ, long aR, long bQ, long bR, long cQ, long cR, int zdiv,
    const float* __restrict__ bias, const float* __restrict__ aux,
    long biasQ, long auxQ)
{
    constexpr int BM = 128, BN = 64, BK = 16, TM = 8, TN = 4;
    __shared__ float As[BK][BM + 4];
    __shared__ float Bs[BK][BN + 4];

    int z  = blockIdx.z;
    int zq = z / zdiv, zr = z - zq * zdiv;
    A  += (long)zq * aQ + (long)zr * aR;
    Bm += (long)zq * bQ + (long)zr * bR;
    C  += (long)zq * cQ + (long)zr * cR;
    const float* biasp = bias ? bias + (long)zq * biasQ : nullptr;
    const float* auxp  = aux  ? aux  + (long)zq * auxQ  : nullptr;

    int bm0 = blockIdx.y * BM, bn0 = blockIdx.x * BN;
    int tid = threadIdx.x;
    int tx = tid & 15, ty = tid >> 4;

    float acc[TM][TN];
#pragma unroll
    for (int i = 0; i < TM; i++)
#pragma unroll
        for (int j = 0; j < TN; j++) acc[i][j] = 0.f;

    for (int k0 = 0; k0 < Kd; k0 += BK) {
#pragma unroll
        for (int r = 0; r < 2; r++) {
            int f   = tid + r * 256;
            int row = f >> 2;
            int kq  = f & 3;
            float4 av = *reinterpret_cast<const float4*>(A + (long)(bm0 + row) * lda + k0 + kq * 4);
            As[kq * 4 + 0][row] = av.x; As[kq * 4 + 1][row] = av.y;
            As[kq * 4 + 2][row] = av.z; As[kq * 4 + 3][row] = av.w;
        }
        if (BT) {
            int m = tid >> 2, kq = tid & 3;
            float4 bv = *reinterpret_cast<const float4*>(Bm + (long)(bn0 + m) * ldb + k0 + kq * 4);
            Bs[kq * 4 + 0][m] = bv.x; Bs[kq * 4 + 1][m] = bv.y;
            Bs[kq * 4 + 2][m] = bv.z; Bs[kq * 4 + 3][m] = bv.w;
        } else {
            int kk = tid >> 4, mq = tid & 15;
            float4 bv = *reinterpret_cast<const float4*>(Bm + (long)(k0 + kk) * ldb + bn0 + mq * 4);
            *reinterpret_cast<float4*>(&Bs[kk][mq * 4]) = bv;
        }
        __syncthreads();
#pragma unroll
        for (int kk = 0; kk < BK; kk++) {
            float4 a0 = *reinterpret_cast<const float4*>(&As[kk][ty * TM]);
            float4 a1 = *reinterpret_cast<const float4*>(&As[kk][ty * TM + 4]);
            float4 b0 = *reinterpret_cast<const float4*>(&Bs[kk][tx * TN]);
            float af[TM] = {a0.x, a0.y, a0.z, a0.w, a1.x, a1.y, a1.z, a1.w};
            float bf[TN] = {b0.x, b0.y, b0.z, b0.w};
#pragma unroll
            for (int i = 0; i < TM; i++)
#pragma unroll
                for (int j = 0; j < TN; j++) acc[i][j] += af[i] * bf[j];
        }
        __syncthreads();
    }

    int col0 = bn0 + tx * TN;
#pragma unroll
    for (int i = 0; i < TM; i++) {
        int row = bm0 + ty * TM + i;
        float r[TN];
#pragma unroll
        for (int j = 0; j < TN; j++) {
            float t = acc[i][j];
            if (EPI == 1) t += biasp[col0 + j];
            else if (EPI == 2) t += biasp[col0 + j] + auxp[(long)row * ldc + col0 + j];
            else if (EPI == 5) t *= 0.125f;
            r[j] = t;
        }
        float4 v4 = {r[0], r[1], r[2], r[3]};
        *reinterpret_cast<float4*>(C + (long)row * ldc + col0) = v4;
    }
}

// ---------------- softmax (in place on attn rows) ----------------
__global__ void __launch_bounds__(256) softmax_k(float* __restrict__ attn,
                                                 const unsigned char* __restrict__ smask)
{
    int i = blockIdx.x, h = blockIdx.y, b = blockIdx.z;
    float* row = attn + (((long)(b * cH + h)) * cT + i) * cT;
    const unsigned char* mrow = smask + ((long)b * cT + i) * cT;
    int tid = threadIdx.x, lane = tid & 31, wid = tid >> 5;
    __shared__ float red[8];
    __shared__ float bc;

    float v[4];
    float mx = -3.4e38f;
#pragma unroll
    for (int r = 0; r < 4; r++) {
        int j = tid + r * 256;
        float s = row[j];
        if (mrow[j]) s = -1e9f;
        v[r] = s;
        mx = fmaxf(mx, s);
    }
    mx = warpReduceMax(mx);
    if (lane == 0) red[wid] = mx;
    __syncthreads();
    if (wid == 0) {
        float r = (lane < 8) ? red[lane] : -3.4e38f;
        r = warpReduceMax(r);
        if (lane == 0) bc = r;
    }
    __syncthreads();
    mx = bc;
    float sum = 0.f;
#pragma unroll
    for (int r = 0; r < 4; r++) { v[r] = expf(v[r] - mx); sum += v[r]; }
    __syncthreads();
    sum = warpReduceSum(sum);
    if (lane == 0) red[wid] = sum;
    __syncthreads();
    if (wid == 0) {
        float r = (lane < 8) ? red[lane] : 0.f;
        r = warpReduceSum(r);
        if (lane == 0) bc = r;
    }
    __syncthreads();
    float inv = 1.f / bc;
#pragma unroll
    for (int r = 0; r < 4; r++) row[tid + r * 256] = v[r] * inv;
}

// ---------------- LayerNorm over D=256; optionally emits fp16 split ----------------
__global__ void __launch_bounds__(256) ln_k(const float* __restrict__ in,
                                            const float* __restrict__ g,
                                            const float* __restrict__ bta,
                                            const unsigned char* __restrict__ mask,
                                            float* __restrict__ out,
                                            __half* __restrict__ oh,
                                            __half* __restrict__ ol)
{
    long n = blockIdx.x;
    int tid = threadIdx.x, lane = tid & 31, wid = tid >> 5;
    __shared__ float red[8];
    __shared__ float stats[2];

    float x = in[n * cD + tid];
    float s = warpReduceSum(x);
    if (lane == 0) red[wid] = s;
    __syncthreads();
    if (wid == 0) {
        float r = (lane < 8) ? red[lane] : 0.f;
        r = warpReduceSum(r);
        if (lane == 0) stats[0] = r;
    }
    __syncthreads();
    float s2 = warpReduceSum(x * x);
    if (lane == 0) red[wid] = s2;
    __syncthreads();
    if (wid == 0) {
        float r = (lane < 8) ? red[lane] : 0.f;
        r = warpReduceSum(r);
        if (lane == 0) stats[1] = r;
    }
    __syncthreads();
    float mean = stats[0] * (1.f / cD);
    float var  = stats[1] * (1.f / cD) - mean * mean;
    float y = (x - mean) * rsqrtf(var + LN_EPS) * g[tid] + bta[tid];
    if (mask[n]) y = 0.f;
    out[n * cD + tid] = y;
    if (oh) {
        __half h, l;
        split_h(y, h, l);
        oh[n * cD + tid] = h;
        ol[n * cD + tid] = l;
    }
}

// ---------------- fp32 -> fp16 (elementwise, single) ----------------
__global__ void __launch_bounds__(256) cvt_half(const float* __restrict__ in,
                                                __half* __restrict__ o, long n)
{
    long i = ((long)blockIdx.x * 256 + threadIdx.x) * 4;
    if (i >= n) return;
    float4 v = *reinterpret_cast<const float4*>(in + i);
    __half2 a = {__float2half_rn(v.x), __float2half_rn(v.y)};
    __half2 b = {__float2half_rn(v.z), __float2half_rn(v.w)};
    *reinterpret_cast<__half2*>(o + i)     = a;
    *reinterpret_cast<__half2*>(o + i + 2) = b;
}

// ---------------- p_w transpose to fp16: in[b][c][o] -> out[b][o][c] ----------------
__global__ void __launch_bounds__(256) cvtT_k(const float* __restrict__ in,
                                              __half* __restrict__ oT)
{
    __shared__ float tile[32][33];
    int b = blockIdx.z;
    int o0 = blockIdx.x * 32, c0 = blockIdx.y * 32;
    int tx = threadIdx.x & 31, ty = threadIdx.x >> 5;  // 32 x 8
    const float* src = in + (long)b * cC * cC;
#pragma unroll
    for (int i = 0; i < 4; i++) {
        int c = c0 + ty + i * 8;
        tile[ty + i * 8][tx] = src[(long)c * cC + o0 + tx];
    }
    __syncthreads();
    __half* dst = oT + (long)b * cC * cC;
#pragma unroll
    for (int i = 0; i < 4; i++) {
        int o = o0 + ty + i * 8;
        dst[(long)o * cC + c0 + tx] = __float2half_rn(tile[tx][ty + i * 8]);
    }
}

// ---------------- depthwise weight inverse norms ----------------
__global__ void __launch_bounds__(128) dwn_k(const float* __restrict__ d_w, float* __restrict__ dwn)
{
    int k = blockIdx.x, b = blockIdx.y;
    int tid = threadIdx.x;
    float s = 0.f;
    for (int c = tid; c < cC; c += 128) {
        float w = d_w[((long)b * cC + c) * 9 + k];
        s += w * w;
    }
    __shared__ float red[4];
    s = warpReduceSum(s);
    if ((tid & 31) == 0) red[tid >> 5] = s;
    __syncthreads();
    if (tid == 0) {
        float r = red[0] + red[1] + red[2] + red[3];
        dwn[b * 9 + k] = 1.f / fmaxf(sqrtf(r), 1e-12f);
    }
}

__global__ void __launch_bounds__(256) pwn_k(const float* __restrict__ p_w, float* __restrict__ pwn)
{
    int c1 = blockIdx.x * 256 + threadIdx.x;
    int b = blockIdx.y;
    const float* base = p_w + (long)b * cC * cC + c1;
    float s = 0.f;
    for (int c2 = 0; c2 < cC; c2++) {
        float w = base[(long)c2 * cC];
        s += w * w;
    }
    pwn[b * cC + c1] = 1.f / fmaxf(sqrtf(s), 1e-12f);
}

// ---------------- depthwise conv (K=9), fused scalings, fp16-split output ----------------
__global__ void __launch_bounds__(256) conv_k(const float* __restrict__ h,
                                              const float* __restrict__ d_w,
                                              const float* __restrict__ d_g,
                                              const float* __restrict__ d_b,
                                              const float* __restrict__ p_g,
                                              const float* __restrict__ dwn,
                                              __half* __restrict__ deph,
                                              __half* __restrict__ depl)
{
    int t = blockIdx.x, b = blockIdx.y;
    __shared__ float wk[9];
    if (threadIdx.x < 9) wk[threadIdx.x] = dwn[b * 9 + threadIdx.x];
    __syncthreads();
#pragma unroll
    for (int i = 0; i < 4; i++) {
        int c = threadIdx.x + i * 256;
        const float* wrow = d_w + ((long)b * cC + c) * 9;
        float acc = 0.f;
#pragma unroll
        for (int kk = 0; kk < 9; kk++) {
            int tt = t + kk - 4;
            if (tt >= 0 && tt < cT)
                acc += h[((long)b * cT + tt) * cC + c] * (wrow[kk] * wk[kk]);
        }
        long bc = (long)b * cC + c;
        float val = (acc * d_g[bc] + d_b[bc]) * p_g[bc];
        __half hi, lo;
        split_h(val, hi, lo);
        long o = ((long)b * cT + t) * cC + c;
        deph[o] = hi;
        depl[o] = lo;
    }
}

// ---------------- launch ----------------
extern "C" void kernel_launch(void* const* d_in, const int* in_sizes, int n_in,
                              void* d_out, int out_size)
{
    const float* x    = (const float*)d_in[0];
    const float* d_w  = (const float*)d_in[1];
    const float* d_g  = (const float*)d_in[2];
    const float* d_b  = (const float*)d_in[3];
    const float* p_w  = (const float*)d_in[4];
    const float* p_g  = (const float*)d_in[5];
    const float* p_b  = (const float*)d_in[6];
    const unsigned char* mask  = (const unsigned char*)d_in[7];
    const unsigned char* smask = (const unsigned char*)d_in[8];
    const float* Wq = (const float*)d_in[9];
    const float* bq = (const float*)d_in[10];
    const float* Wk = (const float*)d_in[11];
    const float* bk = (const float*)d_in[12];
    const float* Wv = (const float*)d_in[13];
    const float* bv = (const float*)d_in[14];
    const float* Wo = (const float*)d_in[15];
    const float* bo = (const float*)d_in[16];
    const float* g0 = (const float*)d_in[17];
    const float* b0 = (const float*)d_in[18];
    const float* w1_w = (const float*)d_in[19];
    const float* w1_b = (const float*)d_in[20];
    const float* w2_w = (const float*)d_in[21];
    const float* w2_b = (const float*)d_in[22];
    const float* g1 = (const float*)d_in[23];
    const float* b1 = (const float*)d_in[24];

    float* out  = (float*)d_out;
    float* attn = out + (long)cNT * cD;   // output tuple: (out[B,T,D], attn[B,H,T,T])

    float *q, *k, *v, *ctx, *apre, *a, *h, *o2, *dwn, *pwn;
    __half *ah, *al, *deph, *depl, *pth, *ptl, *pwT, *w1h, *w2h;
    cudaGetSymbolAddress((void**)&q,    g_q);
    cudaGetSymbolAddress((void**)&k,    g_k);
    cudaGetSymbolAddress((void**)&v,    g_v);
    cudaGetSymbolAddress((void**)&ctx,  g_ctx);
    cudaGetSymbolAddress((void**)&apre, g_apre);
    cudaGetSymbolAddress((void**)&a,    g_a);
    cudaGetSymbolAddress((void**)&h,    g_h);
    cudaGetSymbolAddress((void**)&o2,   g_o2);
    cudaGetSymbolAddress((void**)&dwn,  g_dwn);
    cudaGetSymbolAddress((void**)&pwn,  g_pwn);
    cudaGetSymbolAddress((void**)&ah,   g_ah);
    cudaGetSymbolAddress((void**)&al,   g_al);
    cudaGetSymbolAddress((void**)&deph, g_deph);
    cudaGetSymbolAddress((void**)&depl, g_depl);
    cudaGetSymbolAddress((void**)&pth,  g_pth);
    cudaGetSymbolAddress((void**)&ptl,  g_ptl);
    cudaGetSymbolAddress((void**)&pwT,  g_pwT);
    cudaGetSymbolAddress((void**)&w1h,  g_w1);
    cudaGetSymbolAddress((void**)&w2h,  g_w2);

    cudaFuncSetAttribute(mma_gemm<2>, cudaFuncAttributeMaxDynamicSharedMemorySize, MM_SMEM);
    cudaFuncSetAttribute(mma_gemm<3>, cudaFuncAttributeMaxDynamicSharedMemorySize, MM_SMEM);
    cudaFuncSetAttribute(mma_gemm<4>, cudaFuncAttributeMaxDynamicSharedMemorySize, MM_SMEM);

    dim3 blk(256);

    // 0) weight prep (independent of activation path)
    cvt_half<<<(cC * cD) / 1024, blk>>>(w1_w, w1h, (long)cC * cD);
    cvt_half<<<(cD * cC) / 1024, blk>>>(w2_w, w2h, (long)cD * cC);
    cvtT_k<<<dim3(32, 32, cB), blk>>>(p_w, pwT);
    dwn_k<<<dim3(9, cB), 128>>>(d_w, dwn);
    pwn_k<<<dim3(4, cB), blk>>>(p_w, pwn);

    // 1) q,k,v projections (fp32)
    gemm_k<true, 1><<<dim3(2, 128, 1), blk>>>(x, Wq, q, cNT, 128, cD, cD, cD, 128,
        0, 0, 0, 0, 0, 0, 1, bq, nullptr, 0, 0);
    gemm_k<true, 1><<<dim3(2, 128, 1), blk>>>(x, Wk, k, cNT, 128, cD, cD, cD, 128,
        0, 0, 0, 0, 0, 0, 1, bk, nullptr, 0, 0);
    gemm_k<true, 1><<<dim3(2, 128, 1), blk>>>(x, Wv, v, cNT, 128, cD, cD, cD, 128,
        0, 0, 0, 0, 0, 0, 1, bv, nullptr, 0, 0);

    // 2) scores = q k^T / 8
    gemm_k<true, 5><<<dim3(16, 8, 32), blk>>>(q, k, attn, cT, cT, cDK, 128, 128, cT,
        (long)cT * 128, 64, (long)cT * 128, 64, 2 * cTT, cTT, cH, nullptr, nullptr, 0, 0);

    // 3) masked softmax (writes final attn output)
    softmax_k<<<dim3(cT, cH, cB), blk>>>(attn, smask);

    // 4) ctx = attn @ v
    gemm_k<false, 0><<<dim3(1, 8, 32), blk>>>(attn, v, ctx, cT, cDK, cT, cT, 128, 128,
        2 * cTT, cTT, (long)cT * 128, 64, (long)cT * 128, 64, cH, nullptr, nullptr, 0, 0);

    // 5) apre = ctx @ Wo^T + bo + x
    gemm_k<true, 2><<<dim3(4, 128, 1), blk>>>(ctx, Wo, apre, cNT, cD, 128, 128, 128, cD,
        0, 0, 0, 0, 0, 0, 1, bo, x, 0, 0);

    // 6) a = LN(apre), masked; also emit fp16 split
    ln_k<<<cNT, blk>>>(apre, g0, b0, mask, a, ah, al);

    // 7) h = mish(a @ w1^T + w1_b)   [tensor fp16 2-product]
    mma_gemm<3><<<dim3(cC / 128, cNT / 128, 1), blk, MM_SMEM>>>(
        ah, al, w1h, h, nullptr, nullptr,
        cD, cD, cD, cC, 0, 0, 0, 0, 0, w1_b, nullptr);

    // 8) depthwise conv (emits dep fp16 split)
    conv_k<<<dim3(cT, cB), blk>>>(h, d_w, d_g, d_b, p_g, dwn, deph, depl);

    // 9) pt = (dep' @ pwT) * pwninv[o] + p_b  [tensor, batched over b; fp16-split output]
    mma_gemm<4><<<dim3(cC / 128, cT / 128, cB), blk, MM_SMEM>>>(
        deph, depl, pwT, nullptr, pth, ptl,
        cC, cC, cC, cC, (long)cT * cC, (long)cC * cC, (long)cT * cC, cC, cC, p_b, pwn);

    // 10) o2 = pt @ w2^T + w2_b + a   [tensor]
    mma_gemm<2><<<dim3(cD / 128, cNT / 128, 1), blk, MM_SMEM>>>(
        pth, ptl, w2h, o2, nullptr, nullptr,
        cC, cC, cC, cD, 0, 0, 0, 0, 0, w2_b, a);

    // 11) out = LN(o2), masked
    ln_k<<<cNT, blk>>>(o2, g1, b1, mask, out, nullptr, nullptr);
}

// round 6
// speedup vs baseline: 2.3736x; 1.1630x over previous
#include <cuda_runtime.h>
#include <cuda_fp16.h>
#include <cstdint>
#include <math.h>

// ---------------- problem constants ----------------
constexpr int cB = 16, cT = 1024, cD = 256, cH = 2, cDK = 64, cC = 1024;
constexpr int cNT = cB * cT;            // 16384 tokens
constexpr long cTT = (long)cT * cT;     // 1M
constexpr float LN_EPS = 1e-5f;

// ---------------- device scratch (no allocs allowed) ----------------
__device__ float g_apre[cNT * cD];
__device__ float g_a   [cNT * cD];
__device__ float g_h  [cNT * cC];
__device__ float g_o2 [cNT * cD];
__device__ float g_dwn[cB * 9];
__device__ float g_pwn[cB * cC];
// fp16 buffers
__device__ __half g_xh  [cNT * cD];
__device__ __half g_xl  [cNT * cD];
__device__ __half g_qh  [cNT * 128];
__device__ __half g_ql  [cNT * 128];
__device__ __half g_kh  [cNT * 128];
__device__ __half g_vh  [cNT * 128];
__device__ __half g_vT  [(long)cB * cH * 128 * cT];   // padded to 128 rows per (b,h)
__device__ __half g_atth[(long)cB * cH * cTT];
__device__ __half g_attl[(long)cB * cH * cTT];
__device__ __half g_ctxh[cNT * 128];
__device__ __half g_ctxl[cNT * 128];
__device__ __half g_ah  [cNT * cD];
__device__ __half g_al  [cNT * cD];
__device__ __half g_deph[cNT * cC];
__device__ __half g_depl[cNT * cC];
__device__ __half g_pth [cNT * cC];
__device__ __half g_ptl [cNT * cC];
__device__ __half g_pwT [(long)cB * cC * cC];
__device__ __half g_w1  [cC * cD];
__device__ __half g_w2  [cD * cC];
__device__ __half g_wq  [128 * cD];
__device__ __half g_wk  [128 * cD];
__device__ __half g_wv  [128 * cD];
__device__ __half g_wo  [cD * 128];

// ---------------- helpers ----------------
__device__ __forceinline__ uint32_t smem_u32(const void* p) {
    uint32_t a;
    asm("{ .reg .u64 t; cvta.to.shared.u64 t, %1; cvt.u32.u64 %0, t; }" : "=r"(a) : "l"(p));
    return a;
}
#define SW128(off) ((off) ^ (((off) >> 3) & 0x70))

__device__ __forceinline__ void split_h(float v, __half& h, __half& l) {
    h = __float2half_rn(v);
    l = __float2half_rn(v - __half2float(h));
}

__device__ __forceinline__ void ldsm4(uint32_t* r, uint32_t addr) {
    asm volatile("ldmatrix.sync.aligned.m8n8.x4.shared.b16 {%0,%1,%2,%3}, [%4];"
        : "=r"(r[0]), "=r"(r[1]), "=r"(r[2]), "=r"(r[3]) : "r"(addr));
}
__device__ __forceinline__ void mma16816(float* d, const uint32_t* a, const uint32_t* b) {
    asm volatile("mma.sync.aligned.m16n8k16.row.col.f32.f16.f16.f32 "
        "{%0,%1,%2,%3}, {%4,%5,%6,%7}, {%8,%9}, {%0,%1,%2,%3};"
        : "+f"(d[0]), "+f"(d[1]), "+f"(d[2]), "+f"(d[3])
        : "r"(a[0]), "r"(a[1]), "r"(a[2]), "r"(a[3]), "r"(b[0]), "r"(b[1]));
}
__device__ __forceinline__ void cp16(uint32_t saddr, const void* gptr) {
    asm volatile("cp.async.cg.shared.global [%0], [%1], 16;"
        :: "r"(saddr), "l"(__cvta_generic_to_global(gptr)));
}
__device__ __forceinline__ void cp_commit() {
    asm volatile("cp.async.commit_group;");
}
template<int N>
__device__ __forceinline__ void cp_wait() {
    asm volatile("cp.async.wait_group %0;" :: "n"(N));
}

__device__ __forceinline__ float warpReduceSum(float v) {
#pragma unroll
    for (int o = 16; o > 0; o >>= 1) v += __shfl_xor_sync(0xffffffffu, v, o);
    return v;
}
__device__ __forceinline__ float warpReduceMax(float v) {
#pragma unroll
    for (int o = 16; o > 0; o >>= 1) v = fmaxf(v, __shfl_xor_sync(0xffffffffu, v, o));
    return v;
}

// ---------------- mma.sync fp16-split GEMM, 2-stage cp.async pipeline ----------------
// D[M,N] = A[M,K] @ B[N,K]^T.  A = Ah + Al (fp16 split), B single fp16.
// Batched: z -> zq=z/zdiv, zr=z%zdiv; operand offsets zq*Q + zr*R.
// EPI: 2 = +bias[n]+aux residual -> f32 | 3 = mish(acc+bias) -> f32
//      4 = acc*aux[n]+bias[n] -> fp16 split | 5 = acc*0.125 -> f32
//      6 = +bias -> fp16 split | 7 = +bias -> fp16 single | 8 = raw -> fp16 split
constexpr int MM_STAGE = 3 * 16384;
constexpr int MM_SMEM  = 2 * MM_STAGE + 1024;

template<int EPI>
__global__ void __launch_bounds__(256) mma_gemm(
    const __half* __restrict__ Ah, const __half* __restrict__ Al,
    const __half* __restrict__ Bp,
    float* __restrict__ C, __half* __restrict__ Ch, __half* __restrict__ Cl,
    int Kd, int lda, int ldb, int ldc, int nLim, int zdiv,
    long aQ, long aR, long bQ, long bR, long cQ, long cR,
    long biasZ, long auxZ,
    const float* __restrict__ bias, const float* __restrict__ aux)
{
    extern __shared__ char sm_raw[];
    uint32_t sb0 = smem_u32(sm_raw);
    uint32_t sb  = (sb0 + 1023u) & ~1023u;

    int z = blockIdx.z;
    int zq = z / zdiv, zr = z - zq * zdiv;
    long aoff = (long)zq * aQ + (long)zr * aR;
    long boff = (long)zq * bQ + (long)zr * bR;
    long coff = (long)zq * cQ + (long)zr * cR;
    Ah += aoff; Al += aoff;
    Bp += boff;
    if (C)  C  += coff;
    if (Ch) Ch += coff;
    if (Cl) Cl += coff;
    const float* biasp = bias ? bias + (long)zq * biasZ : nullptr;
    const float* auxp  = aux  ? aux  + (long)zq * auxZ  : nullptr;

    int m0 = blockIdx.y * 128, n0 = blockIdx.x * 128;
    int tid = threadIdx.x, wid = tid >> 5, lane = tid & 31;
    int wm = wid & 3, wn = wid >> 2;

    int lrow = tid >> 3, lcq = tid & 7;

    auto issue_stage = [&](int k0, uint32_t sbase) {
#pragma unroll
        for (int ti = 0; ti < 4; ti++) {
            int row = lrow + ti * 32;
            uint32_t soff = SW128((uint32_t)(row * 128 + lcq * 16));
            long ga = (long)(m0 + row) * lda + k0 + lcq * 8;
            long gb = (long)(n0 + row) * ldb + k0 + lcq * 8;
            cp16(sbase + soff,         Ah + ga);
            cp16(sbase + 16384 + soff, Al + ga);
            cp16(sbase + 32768 + soff, Bp + gb);
        }
        cp_commit();
    };

    float acc[2][8][4];
#pragma unroll
    for (int i = 0; i < 2; i++)
#pragma unroll
        for (int j = 0; j < 8; j++)
#pragma unroll
            for (int l = 0; l < 4; l++) acc[i][j][l] = 0.f;

    int nk = Kd >> 6;
    issue_stage(0, sb);

    for (int i = 0; i < nk; i++) {
        uint32_t cur = sb + (uint32_t)(i & 1) * MM_STAGE;
        if (i + 1 < nk) {
            issue_stage((i + 1) << 6, sb + (uint32_t)((i + 1) & 1) * MM_STAGE);
            cp_wait<1>();
        } else {
            cp_wait<0>();
        }
        __syncthreads();

        uint32_t uAh = cur, uAl = cur + 16384, uB = cur + 32768;
#pragma unroll
        for (int ks = 0; ks < 4; ks++) {
            uint32_t afh[2][4], afl[2][4], bf[4][4];
#pragma unroll
            for (int mt = 0; mt < 2; mt++) {
                int r = wm * 32 + mt * 16 + (lane & 15);
                int kc = ks * 2 + (lane >> 4);
                uint32_t off = SW128((uint32_t)(r * 128 + kc * 16));
                ldsm4(afh[mt], uAh + off);
                ldsm4(afl[mt], uAl + off);
            }
#pragma unroll
            for (int bt = 0; bt < 4; bt++) {
                int r = wn * 64 + bt * 16 + (lane & 7) + ((lane >> 4) << 3);
                int kc = ks * 2 + ((lane >> 3) & 1);
                uint32_t off = SW128((uint32_t)(r * 128 + kc * 16));
                ldsm4(bf[bt], uB + off);
            }
#pragma unroll
            for (int p = 0; p < 2; p++)
#pragma unroll
                for (int mt = 0; mt < 2; mt++)
#pragma unroll
                    for (int bt = 0; bt < 4; bt++)
#pragma unroll
                        for (int hh = 0; hh < 2; hh++) {
                            const uint32_t* af = (p == 0) ? afh[mt] : afl[mt];
                            mma16816(acc[mt][bt * 2 + hh], af, &bf[bt][hh * 2]);
                        }
        }
        __syncthreads();
    }

    // epilogue
#pragma unroll
    for (int mt = 0; mt < 2; mt++)
#pragma unroll
        for (int bt = 0; bt < 4; bt++)
#pragma unroll
            for (int hh = 0; hh < 2; hh++) {
                float* d = acc[mt][bt * 2 + hh];
                int col = n0 + wn * 64 + bt * 16 + hh * 8 + (lane & 3) * 2;
                int r0  = m0 + wm * 32 + mt * 16 + (lane >> 2);
                if (col >= nLim) continue;
#pragma unroll
                for (int half = 0; half < 2; half++) {
                    int row = r0 + half * 8;
                    float t0 = d[half * 2 + 0], t1 = d[half * 2 + 1];
                    if (EPI == 2) {
                        t0 += biasp[col]     + auxp[(long)row * ldc + col];
                        t1 += biasp[col + 1] + auxp[(long)row * ldc + col + 1];
                        float2 v = {t0, t1};
                        *reinterpret_cast<float2*>(C + (long)row * ldc + col) = v;
                    } else if (EPI == 3) {
                        t0 += biasp[col];
                        t1 += biasp[col + 1];
                        float sp0 = (t0 > 20.f) ? t0 : log1pf(expf(t0));
                        float sp1 = (t1 > 20.f) ? t1 : log1pf(expf(t1));
                        t0 = t0 * tanhf(sp0);
                        t1 = t1 * tanhf(sp1);
                        float2 v = {t0, t1};
                        *reinterpret_cast<float2*>(C + (long)row * ldc + col) = v;
                    } else if (EPI == 5) {
                        float2 v = {t0 * 0.125f, t1 * 0.125f};
                        *reinterpret_cast<float2*>(C + (long)row * ldc + col) = v;
                    } else if (EPI == 7) {
                        t0 += biasp[col];
                        t1 += biasp[col + 1];
                        __half2 hv = {__float2half_rn(t0), __float2half_rn(t1)};
                        *reinterpret_cast<__half2*>(Ch + (long)row * ldc + col) = hv;
                    } else { // 4, 6, 8: fp16 split outputs
                        if (EPI == 4) {
                            t0 = t0 * auxp[col]     + biasp[col];
                            t1 = t1 * auxp[col + 1] + biasp[col + 1];
                        } else if (EPI == 6) {
                            t0 += biasp[col];
                            t1 += biasp[col + 1];
                        }
                        __half h0, l0, h1, l1;
                        split_h(t0, h0, l0);
                        split_h(t1, h1, l1);
                        __half2 hv = {h0, h1}, lv = {l0, l1};
                        *reinterpret_cast<__half2*>(Ch + (long)row * ldc + col) = hv;
                        *reinterpret_cast<__half2*>(Cl + (long)row * ldc + col) = lv;
                    }
                }
            }
}

// ---------------- softmax (in place on attn rows; emits fp16 split) ----------------
__global__ void __launch_bounds__(256) softmax_k(float* __restrict__ attn,
                                                 const unsigned char* __restrict__ smask,
                                                 __half* __restrict__ ath,
                                                 __half* __restrict__ atl)
{
    int i = blockIdx.x, h = blockIdx.y, b = blockIdx.z;
    long rbase = (((long)(b * cH + h)) * cT + i) * cT;
    float* row = attn + rbase;
    const unsigned char* mrow = smask + ((long)b * cT + i) * cT;
    int tid = threadIdx.x, lane = tid & 31, wid = tid >> 5;
    __shared__ float red[8];
    __shared__ float bc;

    float v[4];
    float mx = -3.4e38f;
#pragma unroll
    for (int r = 0; r < 4; r++) {
        int j = tid + r * 256;
        float s = row[j];
        if (mrow[j]) s = -1e9f;
        v[r] = s;
        mx = fmaxf(mx, s);
    }
    mx = warpReduceMax(mx);
    if (lane == 0) red[wid] = mx;
    __syncthreads();
    if (wid == 0) {
        float r = (lane < 8) ? red[lane] : -3.4e38f;
        r = warpReduceMax(r);
        if (lane == 0) bc = r;
    }
    __syncthreads();
    mx = bc;
    float sum = 0.f;
#pragma unroll
    for (int r = 0; r < 4; r++) { v[r] = expf(v[r] - mx); sum += v[r]; }
    __syncthreads();
    sum = warpReduceSum(sum);
    if (lane == 0) red[wid] = sum;
    __syncthreads();
    if (wid == 0) {
        float r = (lane < 8) ? red[lane] : 0.f;
        r = warpReduceSum(r);
        if (lane == 0) bc = r;
    }
    __syncthreads();
    float inv = 1.f / bc;
#pragma unroll
    for (int r = 0; r < 4; r++) {
        int j = tid + r * 256;
        float y = v[r] * inv;
        row[j] = y;
        __half hh, ll;
        split_h(y, hh, ll);
        ath[rbase + j] = hh;
        atl[rbase + j] = ll;
    }
}

// ---------------- LayerNorm over D=256; optionally emits fp16 split ----------------
__global__ void __launch_bounds__(256) ln_k(const float* __restrict__ in,
                                            const float* __restrict__ g,
                                            const float* __restrict__ bta,
                                            const unsigned char* __restrict__ mask,
                                            float* __restrict__ out,
                                            __half* __restrict__ oh,
                                            __half* __restrict__ ol)
{
    long n = blockIdx.x;
    int tid = threadIdx.x, lane = tid & 31, wid = tid >> 5;
    __shared__ float red[8];
    __shared__ float stats[2];

    float x = in[n * cD + tid];
    float s = warpReduceSum(x);
    if (lane == 0) red[wid] = s;
    __syncthreads();
    if (wid == 0) {
        float r = (lane < 8) ? red[lane] : 0.f;
        r = warpReduceSum(r);
        if (lane == 0) stats[0] = r;
    }
    __syncthreads();
    float s2 = warpReduceSum(x * x);
    if (lane == 0) red[wid] = s2;
    __syncthreads();
    if (wid == 0) {
        float r = (lane < 8) ? red[lane] : 0.f;
        r = warpReduceSum(r);
        if (lane == 0) stats[1] = r;
    }
    __syncthreads();
    float mean = stats[0] * (1.f / cD);
    float var  = stats[1] * (1.f / cD) - mean * mean;
    float y = (x - mean) * rsqrtf(var + LN_EPS) * g[tid] + bta[tid];
    if (mask[n]) y = 0.f;
    out[n * cD + tid] = y;
    if (oh) {
        __half h, l;
        split_h(y, h, l);
        oh[n * cD + tid] = h;
        ol[n * cD + tid] = l;
    }
}

// ---------------- fp32 -> fp16 single ----------------
__global__ void __launch_bounds__(256) cvt_half(const float* __restrict__ in,
                                                __half* __restrict__ o, long n)
{
    long i = ((long)blockIdx.x * 256 + threadIdx.x) * 4;
    if (i >= n) return;
    float4 v = *reinterpret_cast<const float4*>(in + i);
    __half2 a = {__float2half_rn(v.x), __float2half_rn(v.y)};
    __half2 b = {__float2half_rn(v.z), __float2half_rn(v.w)};
    *reinterpret_cast<__half2*>(o + i)     = a;
    *reinterpret_cast<__half2*>(o + i + 2) = b;
}

// ---------------- fp32 -> fp16 hi/lo split ----------------
__global__ void __launch_bounds__(256) cvt_split_h(const float* __restrict__ in,
                                                   __half* __restrict__ oh,
                                                   __half* __restrict__ ol, long n)
{
    long i = ((long)blockIdx.x * 256 + threadIdx.x) * 4;
    if (i >= n) return;
    float4 v = *reinterpret_cast<const float4*>(in + i);
    __half h0, h1, h2, h3, l0, l1, l2, l3;
    split_h(v.x, h0, l0); split_h(v.y, h1, l1);
    split_h(v.z, h2, l2); split_h(v.w, h3, l3);
    __half2 ha = {h0, h1}, hb = {h2, h3}, la = {l0, l1}, lb = {l2, l3};
    *reinterpret_cast<__half2*>(oh + i)     = ha;
    *reinterpret_cast<__half2*>(oh + i + 2) = hb;
    *reinterpret_cast<__half2*>(ol + i)     = la;
    *reinterpret_cast<__half2*>(ol + i + 2) = lb;
}

// ---------------- v [b][t][h*64+n] -> vT [(b,h)][n][t] fp16, rows 64..127 zeroed ----------------
__global__ void __launch_bounds__(256) vT_k(const __half* __restrict__ v,
                                            __half* __restrict__ vT)
{
    __shared__ __half tile[32][33];
    int b = blockIdx.z;
    int t0 = blockIdx.x * 32, c0 = blockIdx.y * 32;
    int tx = threadIdx.x & 31, ty = threadIdx.x >> 5;  // 32 x 8
#pragma unroll
    for (int i = 0; i < 4; i++) {
        int t = t0 + ty + i * 8;
        tile[ty + i * 8][tx] = v[((long)b * cT + t) * 128 + c0 + tx];
    }
    __syncthreads();
#pragma unroll
    for (int i = 0; i < 4; i++) {
        int c = c0 + ty + i * 8;
        int h = c >> 6, n = c & 63;
        long base = ((long)((b << 1) | h) * 128 + n) * cT;
        vT[base + t0 + tx] = tile[tx][ty + i * 8];
        vT[base + (long)64 * cT + t0 + tx] = __float2half_rn(0.f);
    }
}

// ---------------- p_w transpose to fp16: in[b][c][o] -> out[b][o][c] ----------------
__global__ void __launch_bounds__(256) cvtT_k(const float* __restrict__ in,
                                              __half* __restrict__ oT)
{
    __shared__ float tile[32][33];
    int b = blockIdx.z;
    int o0 = blockIdx.x * 32, c0 = blockIdx.y * 32;
    int tx = threadIdx.x & 31, ty = threadIdx.x >> 5;  // 32 x 8
    const float* src = in + (long)b * cC * cC;
#pragma unroll
    for (int i = 0; i < 4; i++) {
        int c = c0 + ty + i * 8;
        tile[ty + i * 8][tx] = src[(long)c * cC + o0 + tx];
    }
    __syncthreads();
    __half* dst = oT + (long)b * cC * cC;
#pragma unroll
    for (int i = 0; i < 4; i++) {
        int o = o0 + ty + i * 8;
        dst[(long)o * cC + c0 + tx] = __float2half_rn(tile[tx][ty + i * 8]);
    }
}

// ---------------- depthwise weight inverse norms ----------------
__global__ void __launch_bounds__(128) dwn_k(const float* __restrict__ d_w, float* __restrict__ dwn)
{
    int k = blockIdx.x, b = blockIdx.y;
    int tid = threadIdx.x;
    float s = 0.f;
    for (int c = tid; c < cC; c += 128) {
        float w = d_w[((long)b * cC + c) * 9 + k];
        s += w * w;
    }
    __shared__ float red[4];
    s = warpReduceSum(s);
    if ((tid & 31) == 0) red[tid >> 5] = s;
    __syncthreads();
    if (tid == 0) {
        float r = red[0] + red[1] + red[2] + red[3];
        dwn[b * 9 + k] = 1.f / fmaxf(sqrtf(r), 1e-12f);
    }
}

__global__ void __launch_bounds__(256) pwn_k(const float* __restrict__ p_w, float* __restrict__ pwn)
{
    int c1 = blockIdx.x * 256 + threadIdx.x;
    int b = blockIdx.y;
    const float* base = p_w + (long)b * cC * cC + c1;
    float s = 0.f;
    for (int c2 = 0; c2 < cC; c2++) {
        float w = base[(long)c2 * cC];
        s += w * w;
    }
    pwn[b * cC + c1] = 1.f / fmaxf(sqrtf(s), 1e-12f);
}

// ---------------- depthwise conv (K=9), fused scalings, fp16-split output ----------------
__global__ void __launch_bounds__(256) conv_k(const float* __restrict__ h,
                                              const float* __restrict__ d_w,
                                              const float* __restrict__ d_g,
                                              const float* __restrict__ d_b,
                                              const float* __restrict__ p_g,
                                              const float* __restrict__ dwn,
                                              __half* __restrict__ deph,
                                              __half* __restrict__ depl)
{
    int t = blockIdx.x, b = blockIdx.y;
    __shared__ float wk[9];
    if (threadIdx.x < 9) wk[threadIdx.x] = dwn[b * 9 + threadIdx.x];
    __syncthreads();
#pragma unroll
    for (int i = 0; i < 4; i++) {
        int c = threadIdx.x + i * 256;
        const float* wrow = d_w + ((long)b * cC + c) * 9;
        float acc = 0.f;
#pragma unroll
        for (int kk = 0; kk < 9; kk++) {
            int tt = t + kk - 4;
            if (tt >= 0 && tt < cT)
                acc += h[((long)b * cT + tt) * cC + c] * (wrow[kk] * wk[kk]);
        }
        long bc = (long)b * cC + c;
        float val = (acc * d_g[bc] + d_b[bc]) * p_g[bc];
        __half hi, lo;
        split_h(val, hi, lo);
        long o = ((long)b * cT + t) * cC + c;
        deph[o] = hi;
        depl[o] = lo;
    }
}

// ---------------- launch ----------------
extern "C" void kernel_launch(void* const* d_in, const int* in_sizes, int n_in,
                              void* d_out, int out_size)
{
    const float* x    = (const float*)d_in[0];
    const float* d_w  = (const float*)d_in[1];
    const float* d_g  = (const float*)d_in[2];
    const float* d_b  = (const float*)d_in[3];
    const float* p_w  = (const float*)d_in[4];
    const float* p_g  = (const float*)d_in[5];
    const float* p_b  = (const float*)d_in[6];
    const unsigned char* mask  = (const unsigned char*)d_in[7];
    const unsigned char* smask = (const unsigned char*)d_in[8];
    const float* Wq = (const float*)d_in[9];
    const float* bq = (const float*)d_in[10];
    const float* Wk = (const float*)d_in[11];
    const float* bk = (const float*)d_in[12];
    const float* Wv = (const float*)d_in[13];
    const float* bv = (const float*)d_in[14];
    const float* Wo = (const float*)d_in[15];
    const float* bo = (const float*)d_in[16];
    const float* g0 = (const float*)d_in[17];
    const float* b0 = (const float*)d_in[18];
    const float* w1_w = (const float*)d_in[19];
    const float* w1_b = (const float*)d_in[20];
    const float* w2_w = (const float*)d_in[21];
    const float* w2_b = (const float*)d_in[22];
    const float* g1 = (const float*)d_in[23];
    const float* b1 = (const float*)d_in[24];

    float* out  = (float*)d_out;
    float* attn = out + (long)cNT * cD;   // output tuple: (out[B,T,D], attn[B,H,T,T])

    float *apre, *a, *h, *o2, *dwn, *pwn;
    __half *xh, *xl, *qh, *ql, *kh, *vh, *vT, *atth, *attl, *ctxh, *ctxl;
    __half *ah, *al, *deph, *depl, *pth, *ptl, *pwT, *w1h, *w2h, *wqh, *wkh, *wvh, *woh;
    cudaGetSymbolAddress((void**)&apre, g_apre);
    cudaGetSymbolAddress((void**)&a,    g_a);
    cudaGetSymbolAddress((void**)&h,    g_h);
    cudaGetSymbolAddress((void**)&o2,   g_o2);
    cudaGetSymbolAddress((void**)&dwn,  g_dwn);
    cudaGetSymbolAddress((void**)&pwn,  g_pwn);
    cudaGetSymbolAddress((void**)&xh,   g_xh);
    cudaGetSymbolAddress((void**)&xl,   g_xl);
    cudaGetSymbolAddress((void**)&qh,   g_qh);
    cudaGetSymbolAddress((void**)&ql,   g_ql);
    cudaGetSymbolAddress((void**)&kh,   g_kh);
    cudaGetSymbolAddress((void**)&vh,   g_vh);
    cudaGetSymbolAddress((void**)&vT,   g_vT);
    cudaGetSymbolAddress((void**)&atth, g_atth);
    cudaGetSymbolAddress((void**)&attl, g_attl);
    cudaGetSymbolAddress((void**)&ctxh, g_ctxh);
    cudaGetSymbolAddress((void**)&ctxl, g_ctxl);
    cudaGetSymbolAddress((void**)&ah,   g_ah);
    cudaGetSymbolAddress((void**)&al,   g_al);
    cudaGetSymbolAddress((void**)&deph, g_deph);
    cudaGetSymbolAddress((void**)&depl, g_depl);
    cudaGetSymbolAddress((void**)&pth,  g_pth);
    cudaGetSymbolAddress((void**)&ptl,  g_ptl);
    cudaGetSymbolAddress((void**)&pwT,  g_pwT);
    cudaGetSymbolAddress((void**)&w1h,  g_w1);
    cudaGetSymbolAddress((void**)&w2h,  g_w2);
    cudaGetSymbolAddress((void**)&wqh,  g_wq);
    cudaGetSymbolAddress((void**)&wkh,  g_wk);
    cudaGetSymbolAddress((void**)&wvh,  g_wv);
    cudaGetSymbolAddress((void**)&woh,  g_wo);

    cudaFuncSetAttribute(mma_gemm<2>, cudaFuncAttributeMaxDynamicSharedMemorySize, MM_SMEM);
    cudaFuncSetAttribute(mma_gemm<3>, cudaFuncAttributeMaxDynamicSharedMemorySize, MM_SMEM);
    cudaFuncSetAttribute(mma_gemm<4>, cudaFuncAttributeMaxDynamicSharedMemorySize, MM_SMEM);
    cudaFuncSetAttribute(mma_gemm<5>, cudaFuncAttributeMaxDynamicSharedMemorySize, MM_SMEM);
    cudaFuncSetAttribute(mma_gemm<6>, cudaFuncAttributeMaxDynamicSharedMemorySize, MM_SMEM);
    cudaFuncSetAttribute(mma_gemm<7>, cudaFuncAttributeMaxDynamicSharedMemorySize, MM_SMEM);
    cudaFuncSetAttribute(mma_gemm<8>, cudaFuncAttributeMaxDynamicSharedMemorySize, MM_SMEM);

    dim3 blk(256);

    // 0) prep: weight conversions, norms, x split
    cvt_half<<<(128 * cD) / 1024, blk>>>(Wq, wqh, (long)128 * cD);
    cvt_half<<<(128 * cD) / 1024, blk>>>(Wk, wkh, (long)128 * cD);
    cvt_half<<<(128 * cD) / 1024, blk>>>(Wv, wvh, (long)128 * cD);
    cvt_half<<<(cD * 128) / 1024, blk>>>(Wo, woh, (long)cD * 128);
    cvt_half<<<(cC * cD) / 1024, blk>>>(w1_w, w1h, (long)cC * cD);
    cvt_half<<<(cD * cC) / 1024, blk>>>(w2_w, w2h, (long)cD * cC);
    cvtT_k<<<dim3(32, 32, cB), blk>>>(p_w, pwT);
    dwn_k<<<dim3(9, cB), 128>>>(d_w, dwn);
    pwn_k<<<dim3(4, cB), blk>>>(p_w, pwn);
    cvt_split_h<<<(cNT * cD) / 1024, blk>>>(x, xh, xl, (long)cNT * cD);

    // 1) q (split out), k (single), v (single): [16384,256] @ [128,256]^T
    mma_gemm<6><<<dim3(1, cNT / 128, 1), blk, MM_SMEM>>>(
        xh, xl, wqh, nullptr, qh, ql, cD, cD, cD, 128, 128, 1,
        0, 0, 0, 0, 0, 0, 0, 0, bq, nullptr);
    mma_gemm<7><<<dim3(1, cNT / 128, 1), blk, MM_SMEM>>>(
        xh, xl, wkh, nullptr, kh, nullptr, cD, cD, cD, 128, 128, 1,
        0, 0, 0, 0, 0, 0, 0, 0, bk, nullptr);
    mma_gemm<7><<<dim3(1, cNT / 128, 1), blk, MM_SMEM>>>(
        xh, xl, wvh, nullptr, vh, nullptr, cD, cD, cD, 128, 128, 1,
        0, 0, 0, 0, 0, 0, 0, 0, bv, nullptr);

    // 2) v -> vT (padded 128 rows per (b,h))
    vT_k<<<dim3(32, 4, cB), blk>>>(vh, vT);

    // 3) scores = q k^T / 8  [tensor, z=(b,h) with zdiv=2]
    mma_gemm<5><<<dim3(8, 8, 32), blk, MM_SMEM>>>(
        qh, ql, kh, attn, nullptr, nullptr, cDK, 128, 128, cT, 1024, 2,
        (long)cT * 128, 64, (long)cT * 128, 64, 2 * cTT, cTT, 0, 0, nullptr, nullptr);

    // 4) masked softmax (writes final attn + fp16 split)
    softmax_k<<<dim3(cT, cH, cB), blk>>>(attn, smask, atth, attl);

    // 5) ctx = attn @ v  -> fp16 split, col guard 64
    mma_gemm<8><<<dim3(1, 8, 32), blk, MM_SMEM>>>(
        atth, attl, vT, nullptr, ctxh, ctxl, cT, cT, cT, 128, 64, 2,
        2 * cTT, cTT, (long)2 * 128 * cT, (long)128 * cT, (long)cT * 128, 64,
        0, 0, nullptr, nullptr);

    // 6) apre = ctx @ Wo^T + bo + x
    mma_gemm<2><<<dim3(2, cNT / 128, 1), blk, MM_SMEM>>>(
        ctxh, ctxl, woh, apre, nullptr, nullptr, 128, 128, 128, cD, 256, 1,
        0, 0, 0, 0, 0, 0, 0, 0, bo, x);

    // 7) a = LN(apre), masked; emit fp16 split
    ln_k<<<cNT, blk>>>(apre, g0, b0, mask, a, ah, al);

    // 8) h = mish(a @ w1^T + w1_b)
    mma_gemm<3><<<dim3(cC / 128, cNT / 128, 1), blk, MM_SMEM>>>(
        ah, al, w1h, h, nullptr, nullptr, cD, cD, cD, cC, 1024, 1,
        0, 0, 0, 0, 0, 0, 0, 0, w1_b, nullptr);

    // 9) depthwise conv (emits dep fp16 split)
    conv_k<<<dim3(cT, cB), blk>>>(h, d_w, d_g, d_b, p_g, dwn, deph, depl);

    // 10) pt = (dep' @ pwT) * pwninv[o] + p_b  [batched over b; fp16-split output]
    mma_gemm<4><<<dim3(cC / 128, cT / 128, cB), blk, MM_SMEM>>>(
        deph, depl, pwT, nullptr, pth, ptl, cC, cC, cC, cC, 1024, 1,
        (long)cT * cC, 0, (long)cC * cC, 0, (long)cT * cC, 0, cC, cC, p_b, pwn);

    // 11) o2 = pt @ w2^T + w2_b + a
    mma_gemm<2><<<dim3(cD / 128, cNT / 128, 1), blk, MM_SMEM>>>(
        pth, ptl, w2h, o2, nullptr, nullptr, cC, cC, cC, cD, 256, 1,
        0, 0, 0, 0, 0, 0, 0, 0, w2_b, a);

    // 12) out = LN(o2), masked
    ln_k<<<cNT, blk>>>(o2, g1, b1, mask, out, nullptr, nullptr);
}

// round 7
// speedup vs baseline: 2.4530x; 1.0335x over previous
#include <cuda_runtime.h>
#include <cuda_fp16.h>
#include <cstdint>
#include <math.h>

// ---------------- problem constants ----------------
constexpr int cB = 16, cT = 1024, cD = 256, cH = 2, cDK = 64, cC = 1024;
constexpr int cNT = cB * cT;            // 16384 tokens
constexpr long cTT = (long)cT * cT;     // 1M
constexpr float LN_EPS = 1e-5f;

// ---------------- device scratch (no allocs allowed) ----------------
__device__ float g_apre[cNT * cD];
__device__ float g_a   [cNT * cD];
__device__ float g_h  [cNT * cC];
__device__ float g_o2 [cNT * cD];
__device__ float g_dwn[cB * 9];
__device__ float g_pwn[cB * cC];
__device__ float g_bkv[256];
// fp16 buffers
__device__ __half g_xh  [cNT * cD];
__device__ __half g_xl  [cNT * cD];
__device__ __half g_qh  [cNT * 128];
__device__ __half g_ql  [cNT * 128];
__device__ __half g_kvh [cNT * 256];
__device__ __half g_kvl [cNT * 256];
__device__ __half g_vTh [(long)cB * cH * 128 * cT];   // padded to 128 rows per (b,h)
__device__ __half g_vTl [(long)cB * cH * 128 * cT];
__device__ __half g_atth[(long)cB * cH * cTT];
__device__ __half g_attl[(long)cB * cH * cTT];
__device__ __half g_ctxh[cNT * 128];
__device__ __half g_ctxl[cNT * 128];
__device__ __half g_ah  [cNT * cD];
__device__ __half g_al  [cNT * cD];
__device__ __half g_deph[cNT * cC];
__device__ __half g_depl[cNT * cC];
__device__ __half g_pth [cNT * cC];
__device__ __half g_ptl [cNT * cC];
__device__ __half g_pwT [(long)cB * cC * cC];
__device__ __half g_w1  [cC * cD];
__device__ __half g_w2  [cD * cC];
__device__ __half g_wq  [128 * cD];
__device__ __half g_wkv [256 * cD];
__device__ __half g_wo  [cD * 128];

// ---------------- helpers ----------------
__device__ __forceinline__ uint32_t smem_u32(const void* p) {
    uint32_t a;
    asm("{ .reg .u64 t; cvta.to.shared.u64 t, %1; cvt.u32.u64 %0, t; }" : "=r"(a) : "l"(p));
    return a;
}
#define SW128(off) ((off) ^ (((off) >> 3) & 0x70))

__device__ __forceinline__ void split_h(float v, __half& h, __half& l) {
    h = __float2half_rn(v);
    l = __float2half_rn(v - __half2float(h));
}

__device__ __forceinline__ void ldsm4(uint32_t* r, uint32_t addr) {
    asm volatile("ldmatrix.sync.aligned.m8n8.x4.shared.b16 {%0,%1,%2,%3}, [%4];"
        : "=r"(r[0]), "=r"(r[1]), "=r"(r[2]), "=r"(r[3]) : "r"(addr));
}
__device__ __forceinline__ void mma16816(float* d, const uint32_t* a, const uint32_t* b) {
    asm volatile("mma.sync.aligned.m16n8k16.row.col.f32.f16.f16.f32 "
        "{%0,%1,%2,%3}, {%4,%5,%6,%7}, {%8,%9}, {%0,%1,%2,%3};"
        : "+f"(d[0]), "+f"(d[1]), "+f"(d[2]), "+f"(d[3])
        : "r"(a[0]), "r"(a[1]), "r"(a[2]), "r"(a[3]), "r"(b[0]), "r"(b[1]));
}
__device__ __forceinline__ void cp16(uint32_t saddr, const void* gptr) {
    asm volatile("cp.async.cg.shared.global [%0], [%1], 16;"
        :: "r"(saddr), "l"(__cvta_generic_to_global(gptr)));
}
__device__ __forceinline__ void cp_commit() {
    asm volatile("cp.async.commit_group;");
}
template<int N>
__device__ __forceinline__ void cp_wait() {
    asm volatile("cp.async.wait_group %0;" :: "n"(N));
}

__device__ __forceinline__ float warpReduceSum(float v) {
#pragma unroll
    for (int o = 16; o > 0; o >>= 1) v += __shfl_xor_sync(0xffffffffu, v, o);
    return v;
}
__device__ __forceinline__ float warpReduceMax(float v) {
#pragma unroll
    for (int o = 16; o > 0; o >>= 1) v = fmaxf(v, __shfl_xor_sync(0xffffffffu, v, o));
    return v;
}

// ---------------- mma.sync fp16-split GEMM body ----------------
// D[M,N] = A[M,K] @ B[N,K]^T.  A = Ah + Al (fp16 split).
// NPROD=2: acc += Ah*Bh + Al*Bh (B single).  NPROD=3: + Ah*Bl (B split too).
// EPI: 2 = +bias[n]+aux residual -> f32 | 3 = mish(acc+bias) -> f32
//      4 = acc*aux[n]+bias[n] -> fp16 split | 5 = acc*0.125 -> f32
//      6 = +bias -> fp16 split | 8 = raw -> fp16 split
constexpr int MM_SMEM2 = 2 * 49152 + 1024;
constexpr int MM_SMEM3 = 2 * 65536 + 1024;

template<int EPI, int NPROD>
__device__ __forceinline__ void mma_body(
    const __half* __restrict__ Ah, const __half* __restrict__ Al,
    const __half* __restrict__ Bh, const __half* __restrict__ Bl,
    float* __restrict__ C, __half* __restrict__ Ch, __half* __restrict__ Cl,
    int Kd, int lda, int ldb, int ldc, int nLim, int zdiv,
    long aQ, long aR, long bQ, long bR, long cQ, long cR,
    long biasZ, long auxZ,
    const float* __restrict__ bias, const float* __restrict__ aux)
{
    constexpr int STAGE = (NPROD == 3) ? 65536 : 49152;
    extern __shared__ char sm_raw[];
    uint32_t sb0 = smem_u32(sm_raw);
    uint32_t sb  = (sb0 + 1023u) & ~1023u;

    int z = blockIdx.z;
    int zq = z / zdiv, zr = z - zq * zdiv;
    long aoff = (long)zq * aQ + (long)zr * aR;
    long boff = (long)zq * bQ + (long)zr * bR;
    long coff = (long)zq * cQ + (long)zr * cR;
    Ah += aoff; Al += aoff;
    Bh += boff;
    if (NPROD == 3) Bl += boff;
    if (C)  C  += coff;
    if (Ch) Ch += coff;
    if (Cl) Cl += coff;
    const float* biasp = bias ? bias + (long)zq * biasZ : nullptr;
    const float* auxp  = aux  ? aux  + (long)zq * auxZ  : nullptr;

    int m0 = blockIdx.y * 128, n0 = blockIdx.x * 128;
    int tid = threadIdx.x, wid = tid >> 5, lane = tid & 31;
    int wm = wid & 3, wn = wid >> 2;

    int lrow = tid >> 3, lcq = tid & 7;

    auto issue_stage = [&](int k0, uint32_t sbase) {
#pragma unroll
        for (int ti = 0; ti < 4; ti++) {
            int row = lrow + ti * 32;
            uint32_t soff = SW128((uint32_t)(row * 128 + lcq * 16));
            long ga = (long)(m0 + row) * lda + k0 + lcq * 8;
            long gb = (long)(n0 + row) * ldb + k0 + lcq * 8;
            cp16(sbase + soff,         Ah + ga);
            cp16(sbase + 16384 + soff, Al + ga);
            cp16(sbase + 32768 + soff, Bh + gb);
            if (NPROD == 3) cp16(sbase + 49152 + soff, Bl + gb);
        }
        cp_commit();
    };

    float acc[2][8][4];
#pragma unroll
    for (int i = 0; i < 2; i++)
#pragma unroll
        for (int j = 0; j < 8; j++)
#pragma unroll
            for (int l = 0; l < 4; l++) acc[i][j][l] = 0.f;

    int nk = Kd >> 6;
    issue_stage(0, sb);

    for (int i = 0; i < nk; i++) {
        uint32_t cur = sb + (uint32_t)(i & 1) * STAGE;
        if (i + 1 < nk) {
            issue_stage((i + 1) << 6, sb + (uint32_t)((i + 1) & 1) * STAGE);
            cp_wait<1>();
        } else {
            cp_wait<0>();
        }
        __syncthreads();

        uint32_t uAh = cur, uAl = cur + 16384, uBh = cur + 32768, uBl = cur + 49152;
#pragma unroll
        for (int ks = 0; ks < 4; ks++) {
            uint32_t afh[2][4], afl[2][4], bfh[4][4], bfl[4][4];
#pragma unroll
            for (int mt = 0; mt < 2; mt++) {
                int r = wm * 32 + mt * 16 + (lane & 15);
                int kc = ks * 2 + (lane >> 4);
                uint32_t off = SW128((uint32_t)(r * 128 + kc * 16));
                ldsm4(afh[mt], uAh + off);
                ldsm4(afl[mt], uAl + off);
            }
#pragma unroll
            for (int bt = 0; bt < 4; bt++) {
                int r = wn * 64 + bt * 16 + (lane & 7) + ((lane >> 4) << 3);
                int kc = ks * 2 + ((lane >> 3) & 1);
                uint32_t off = SW128((uint32_t)(r * 128 + kc * 16));
                ldsm4(bfh[bt], uBh + off);
                if (NPROD == 3) ldsm4(bfl[bt], uBl + off);
            }
#pragma unroll
            for (int p = 0; p < NPROD; p++)
#pragma unroll
                for (int mt = 0; mt < 2; mt++)
#pragma unroll
                    for (int bt = 0; bt < 4; bt++)
#pragma unroll
                        for (int hh = 0; hh < 2; hh++) {
                            const uint32_t* af  = (p == 1) ? afl[mt] : afh[mt];
                            const uint32_t* bfp = (p == 2) ? &bfl[bt][hh * 2] : &bfh[bt][hh * 2];
                            mma16816(acc[mt][bt * 2 + hh], af, bfp);
                        }
        }
        __syncthreads();
    }

    // epilogue
#pragma unroll
    for (int mt = 0; mt < 2; mt++)
#pragma unroll
        for (int bt = 0; bt < 4; bt++)
#pragma unroll
            for (int hh = 0; hh < 2; hh++) {
                float* d = acc[mt][bt * 2 + hh];
                int col = n0 + wn * 64 + bt * 16 + hh * 8 + (lane & 3) * 2;
                int r0  = m0 + wm * 32 + mt * 16 + (lane >> 2);
                if (col >= nLim) continue;
#pragma unroll
                for (int half = 0; half < 2; half++) {
                    int row = r0 + half * 8;
                    float t0 = d[half * 2 + 0], t1 = d[half * 2 + 1];
                    if (EPI == 2) {
                        t0 += biasp[col]     + auxp[(long)row * ldc + col];
                        t1 += biasp[col + 1] + auxp[(long)row * ldc + col + 1];
                        float2 v = {t0, t1};
                        *reinterpret_cast<float2*>(C + (long)row * ldc + col) = v;
                    } else if (EPI == 3) {
                        t0 += biasp[col];
                        t1 += biasp[col + 1];
                        float sp0 = (t0 > 20.f) ? t0 : log1pf(expf(t0));
                        float sp1 = (t1 > 20.f) ? t1 : log1pf(expf(t1));
                        t0 = t0 * tanhf(sp0);
                        t1 = t1 * tanhf(sp1);
                        float2 v = {t0, t1};
                        *reinterpret_cast<float2*>(C + (long)row * ldc + col) = v;
                    } else if (EPI == 5) {
                        float2 v = {t0 * 0.125f, t1 * 0.125f};
                        *reinterpret_cast<float2*>(C + (long)row * ldc + col) = v;
                    } else { // 4, 6, 8: fp16 split outputs
                        if (EPI == 4) {
                            t0 = t0 * auxp[col]     + biasp[col];
                            t1 = t1 * auxp[col + 1] + biasp[col + 1];
                        } else if (EPI == 6) {
                            t0 += biasp[col];
                            t1 += biasp[col + 1];
                        }
                        __half h0, l0, h1, l1;
                        split_h(t0, h0, l0);
                        split_h(t1, h1, l1);
                        __half2 hv = {h0, h1}, lv = {l0, l1};
                        *reinterpret_cast<__half2*>(Ch + (long)row * ldc + col) = hv;
                        *reinterpret_cast<__half2*>(Cl + (long)row * ldc + col) = lv;
                    }
                }
            }
}

template<int EPI>
__global__ void __launch_bounds__(256, 2) mma_gemm2(
    const __half* __restrict__ Ah, const __half* __restrict__ Al,
    const __half* __restrict__ Bh,
    float* __restrict__ C, __half* __restrict__ Ch, __half* __restrict__ Cl,
    int Kd, int lda, int ldb, int ldc, int nLim, int zdiv,
    long aQ, long aR, long bQ, long bR, long cQ, long cR,
    long biasZ, long auxZ,
    const float* __restrict__ bias, const float* __restrict__ aux)
{
    mma_body<EPI, 2>(Ah, Al, Bh, nullptr, C, Ch, Cl, Kd, lda, ldb, ldc, nLim, zdiv,
                     aQ, aR, bQ, bR, cQ, cR, biasZ, auxZ, bias, aux);
}

template<int EPI>
__global__ void __launch_bounds__(256) mma_gemm3(
    const __half* __restrict__ Ah, const __half* __restrict__ Al,
    const __half* __restrict__ Bh, const __half* __restrict__ Bl,
    float* __restrict__ C, __half* __restrict__ Ch, __half* __restrict__ Cl,
    int Kd, int lda, int ldb, int ldc, int nLim, int zdiv,
    long aQ, long aR, long bQ, long bR, long cQ, long cR,
    long biasZ, long auxZ,
    const float* __restrict__ bias, const float* __restrict__ aux)
{
    mma_body<EPI, 3>(Ah, Al, Bh, Bl, C, Ch, Cl, Kd, lda, ldb, ldc, nLim, zdiv,
                     aQ, aR, bQ, bR, cQ, cR, biasZ, auxZ, bias, aux);
}

// ---------------- softmax (in place on attn rows; emits fp16 split) ----------------
__global__ void __launch_bounds__(256) softmax_k(float* __restrict__ attn,
                                                 const unsigned char* __restrict__ smask,
                                                 __half* __restrict__ ath,
                                                 __half* __restrict__ atl)
{
    int i = blockIdx.x, h = blockIdx.y, b = blockIdx.z;
    long rbase = (((long)(b * cH + h)) * cT + i) * cT;
    float* row = attn + rbase;
    const unsigned char* mrow = smask + ((long)b * cT + i) * cT;
    int tid = threadIdx.x, lane = tid & 31, wid = tid >> 5;
    __shared__ float red[8];
    __shared__ float bc;

    float v[4];
    float mx = -3.4e38f;
#pragma unroll
    for (int r = 0; r < 4; r++) {
        int j = tid + r * 256;
        float s = row[j];
        if (mrow[j]) s = -1e9f;
        v[r] = s;
        mx = fmaxf(mx, s);
    }
    mx = warpReduceMax(mx);
    if (lane == 0) red[wid] = mx;
    __syncthreads();
    if (wid == 0) {
        float r = (lane < 8) ? red[lane] : -3.4e38f;
        r = warpReduceMax(r);
        if (lane == 0) bc = r;
    }
    __syncthreads();
    mx = bc;
    float sum = 0.f;
#pragma unroll
    for (int r = 0; r < 4; r++) { v[r] = expf(v[r] - mx); sum += v[r]; }
    __syncthreads();
    sum = warpReduceSum(sum);
    if (lane == 0) red[wid] = sum;
    __syncthreads();
    if (wid == 0) {
        float r = (lane < 8) ? red[lane] : 0.f;
        r = warpReduceSum(r);
        if (lane == 0) bc = r;
    }
    __syncthreads();
    float inv = 1.f / bc;
#pragma unroll
    for (int r = 0; r < 4; r++) {
        int j = tid + r * 256;
        float y = v[r] * inv;
        row[j] = y;
        __half hh, ll;
        split_h(y, hh, ll);
        ath[rbase + j] = hh;
        atl[rbase + j] = ll;
    }
}

// ---------------- LayerNorm over D=256; optionally emits fp16 split ----------------
__global__ void __launch_bounds__(256) ln_k(const float* __restrict__ in,
                                            const float* __restrict__ g,
                                            const float* __restrict__ bta,
                                            const unsigned char* __restrict__ mask,
                                            float* __restrict__ out,
                                            __half* __restrict__ oh,
                                            __half* __restrict__ ol)
{
    long n = blockIdx.x;
    int tid = threadIdx.x, lane = tid & 31, wid = tid >> 5;
    __shared__ float red[8];
    __shared__ float stats[2];

    float x = in[n * cD + tid];
    float s = warpReduceSum(x);
    if (lane == 0) red[wid] = s;
    __syncthreads();
    if (wid == 0) {
        float r = (lane < 8) ? red[lane] : 0.f;
        r = warpReduceSum(r);
        if (lane == 0) stats[0] = r;
    }
    __syncthreads();
    float s2 = warpReduceSum(x * x);
    if (lane == 0) red[wid] = s2;
    __syncthreads();
    if (wid == 0) {
        float r = (lane < 8) ? red[lane] : 0.f;
        r = warpReduceSum(r);
        if (lane == 0) stats[1] = r;
    }
    __syncthreads();
    float mean = stats[0] * (1.f / cD);
    float var  = stats[1] * (1.f / cD) - mean * mean;
    float y = (x - mean) * rsqrtf(var + LN_EPS) * g[tid] + bta[tid];
    if (mask[n]) y = 0.f;
    out[n * cD + tid] = y;
    if (oh) {
        __half h, l;
        split_h(y, h, l);
        oh[n * cD + tid] = h;
        ol[n * cD + tid] = l;
    }
}

// ---------------- fp32 -> fp16 single ----------------
__global__ void __launch_bounds__(256) cvt_half(const float* __restrict__ in,
                                                __half* __restrict__ o, long n)
{
    long i = ((long)blockIdx.x * 256 + threadIdx.x) * 4;
    if (i >= n) return;
    float4 v = *reinterpret_cast<const float4*>(in + i);
    __half2 a = {__float2half_rn(v.x), __float2half_rn(v.y)};
    __half2 b = {__float2half_rn(v.z), __float2half_rn(v.w)};
    *reinterpret_cast<__half2*>(o + i)     = a;
    *reinterpret_cast<__half2*>(o + i + 2) = b;
}

// ---------------- fp32 -> fp16 hi/lo split ----------------
__global__ void __launch_bounds__(256) cvt_split_h(const float* __restrict__ in,
                                                   __half* __restrict__ oh,
                                                   __half* __restrict__ ol, long n)
{
    long i = ((long)blockIdx.x * 256 + threadIdx.x) * 4;
    if (i >= n) return;
    float4 v = *reinterpret_cast<const float4*>(in + i);
    __half h0, h1, h2, h3, l0, l1, l2, l3;
    split_h(v.x, h0, l0); split_h(v.y, h1, l1);
    split_h(v.z, h2, l2); split_h(v.w, h3, l3);
    __half2 ha = {h0, h1}, hb = {h2, h3}, la = {l0, l1}, lb = {l2, l3};
    *reinterpret_cast<__half2*>(oh + i)     = ha;
    *reinterpret_cast<__half2*>(oh + i + 2) = hb;
    *reinterpret_cast<__half2*>(ol + i)     = la;
    *reinterpret_cast<__half2*>(ol + i + 2) = lb;
}

// ---------------- kv cols 128..255 -> vT [(b,h)][n][t] split, rows 64..127 zeroed ----------------
__global__ void __launch_bounds__(256) vT_k(const __half* __restrict__ kvh,
                                            const __half* __restrict__ kvl,
                                            __half* __restrict__ vTh,
                                            __half* __restrict__ vTl)
{
    __shared__ __half th[32][33], tl[32][33];
    int b = blockIdx.z;
    int t0 = blockIdx.x * 32, c0 = blockIdx.y * 32;
    int tx = threadIdx.x & 31, ty = threadIdx.x >> 5;  // 32 x 8
#pragma unroll
    for (int i = 0; i < 4; i++) {
        int t = t0 + ty + i * 8;
        long src = ((long)b * cT + t) * 256 + 128 + c0 + tx;
        th[ty + i * 8][tx] = kvh[src];
        tl[ty + i * 8][tx] = kvl[src];
    }
    __syncthreads();
#pragma unroll
    for (int i = 0; i < 4; i++) {
        int c = c0 + ty + i * 8;
        int h = c >> 6, n = c & 63;
        long base = ((long)((b << 1) | h) * 128 + n) * cT + t0 + tx;
        vTh[base] = th[tx][ty + i * 8];
        vTl[base] = tl[tx][ty + i * 8];
        vTh[base + (long)64 * cT] = __float2half_rn(0.f);
        vTl[base + (long)64 * cT] = __float2half_rn(0.f);
    }
}

// ---------------- p_w transpose to fp16: in[b][c][o] -> out[b][o][c] ----------------
__global__ void __launch_bounds__(256) cvtT_k(const float* __restrict__ in,
                                              __half* __restrict__ oT)
{
    __shared__ float tile[32][33];
    int b = blockIdx.z;
    int o0 = blockIdx.x * 32, c0 = blockIdx.y * 32;
    int tx = threadIdx.x & 31, ty = threadIdx.x >> 5;  // 32 x 8
    const float* src = in + (long)b * cC * cC;
#pragma unroll
    for (int i = 0; i < 4; i++) {
        int c = c0 + ty + i * 8;
        tile[ty + i * 8][tx] = src[(long)c * cC + o0 + tx];
    }
    __syncthreads();
    __half* dst = oT + (long)b * cC * cC;
#pragma unroll
    for (int i = 0; i < 4; i++) {
        int o = o0 + ty + i * 8;
        dst[(long)o * cC + c0 + tx] = __float2half_rn(tile[tx][ty + i * 8]);
    }
}

// ---------------- depthwise weight inverse norms ----------------
__global__ void __launch_bounds__(128) dwn_k(const float* __restrict__ d_w, float* __restrict__ dwn)
{
    int k = blockIdx.x, b = blockIdx.y;
    int tid = threadIdx.x;
    float s = 0.f;
    for (int c = tid; c < cC; c += 128) {
        float w = d_w[((long)b * cC + c) * 9 + k];
        s += w * w;
    }
    __shared__ float red[4];
    s = warpReduceSum(s);
    if ((tid & 31) == 0) red[tid >> 5] = s;
    __syncthreads();
    if (tid == 0) {
        float r = red[0] + red[1] + red[2] + red[3];
        dwn[b * 9 + k] = 1.f / fmaxf(sqrtf(r), 1e-12f);
    }
}

__global__ void __launch_bounds__(256) pwn_k(const float* __restrict__ p_w, float* __restrict__ pwn)
{
    int c1 = blockIdx.x * 256 + threadIdx.x;
    int b = blockIdx.y;
    const float* base = p_w + (long)b * cC * cC + c1;
    float s = 0.f;
    for (int c2 = 0; c2 < cC; c2++) {
        float w = base[(long)c2 * cC];
        s += w * w;
    }
    pwn[b * cC + c1] = 1.f / fmaxf(sqrtf(s), 1e-12f);
}

// ---------------- depthwise conv (K=9), fused scalings, fp16-split output ----------------
__global__ void __launch_bounds__(256) conv_k(const float* __restrict__ h,
                                              const float* __restrict__ d_w,
                                              const float* __restrict__ d_g,
                                              const float* __restrict__ d_b,
                                              const float* __restrict__ p_g,
                                              const float* __restrict__ dwn,
                                              __half* __restrict__ deph,
                                              __half* __restrict__ depl)
{
    int t = blockIdx.x, b = blockIdx.y;
    __shared__ float wk[9];
    if (threadIdx.x < 9) wk[threadIdx.x] = dwn[b * 9 + threadIdx.x];
    __syncthreads();
#pragma unroll
    for (int i = 0; i < 4; i++) {
        int c = threadIdx.x + i * 256;
        const float* wrow = d_w + ((long)b * cC + c) * 9;
        float acc = 0.f;
#pragma unroll
        for (int kk = 0; kk < 9; kk++) {
            int tt = t + kk - 4;
            if (tt >= 0 && tt < cT)
                acc += h[((long)b * cT + tt) * cC + c] * (wrow[kk] * wk[kk]);
        }
        long bc = (long)b * cC + c;
        float val = (acc * d_g[bc] + d_b[bc]) * p_g[bc];
        __half hi, lo;
        split_h(val, hi, lo);
        long o = ((long)b * cT + t) * cC + c;
        deph[o] = hi;
        depl[o] = lo;
    }
}

// ---------------- launch ----------------
extern "C" void kernel_launch(void* const* d_in, const int* in_sizes, int n_in,
                              void* d_out, int out_size)
{
    const float* x    = (const float*)d_in[0];
    const float* d_w  = (const float*)d_in[1];
    const float* d_g  = (const float*)d_in[2];
    const float* d_b  = (const float*)d_in[3];
    const float* p_w  = (const float*)d_in[4];
    const float* p_g  = (const float*)d_in[5];
    const float* p_b  = (const float*)d_in[6];
    const unsigned char* mask  = (const unsigned char*)d_in[7];
    const unsigned char* smask = (const unsigned char*)d_in[8];
    const float* Wq = (const float*)d_in[9];
    const float* bq = (const float*)d_in[10];
    const float* Wk = (const float*)d_in[11];
    const float* bk = (const float*)d_in[12];
    const float* Wv = (const float*)d_in[13];
    const float* bv = (const float*)d_in[14];
    const float* Wo = (const float*)d_in[15];
    const float* bo = (const float*)d_in[16];
    const float* g0 = (const float*)d_in[17];
    const float* b0 = (const float*)d_in[18];
    const float* w1_w = (const float*)d_in[19];
    const float* w1_b = (const float*)d_in[20];
    const float* w2_w = (const float*)d_in[21];
    const float* w2_b = (const float*)d_in[22];
    const float* g1 = (const float*)d_in[23];
    const float* b1 = (const float*)d_in[24];

    float* out  = (float*)d_out;
    float* attn = out + (long)cNT * cD;   // output tuple: (out[B,T,D], attn[B,H,T,T])

    float *apre, *a, *h, *o2, *dwn, *pwn, *bkv;
    __half *xh, *xl, *qh, *ql, *kvh, *kvl, *vTh, *vTl, *atth, *attl, *ctxh, *ctxl;
    __half *ah, *al, *deph, *depl, *pth, *ptl, *pwT, *w1h, *w2h, *wqh, *wkvh, *woh;
    cudaGetSymbolAddress((void**)&apre, g_apre);
    cudaGetSymbolAddress((void**)&a,    g_a);
    cudaGetSymbolAddress((void**)&h,    g_h);
    cudaGetSymbolAddress((void**)&o2,   g_o2);
    cudaGetSymbolAddress((void**)&dwn,  g_dwn);
    cudaGetSymbolAddress((void**)&pwn,  g_pwn);
    cudaGetSymbolAddress((void**)&bkv,  g_bkv);
    cudaGetSymbolAddress((void**)&xh,   g_xh);
    cudaGetSymbolAddress((void**)&xl,   g_xl);
    cudaGetSymbolAddress((void**)&qh,   g_qh);
    cudaGetSymbolAddress((void**)&ql,   g_ql);
    cudaGetSymbolAddress((void**)&kvh,  g_kvh);
    cudaGetSymbolAddress((void**)&kvl,  g_kvl);
    cudaGetSymbolAddress((void**)&vTh,  g_vTh);
    cudaGetSymbolAddress((void**)&vTl,  g_vTl);
    cudaGetSymbolAddress((void**)&atth, g_atth);
    cudaGetSymbolAddress((void**)&attl, g_attl);
    cudaGetSymbolAddress((void**)&ctxh, g_ctxh);
    cudaGetSymbolAddress((void**)&ctxl, g_ctxl);
    cudaGetSymbolAddress((void**)&ah,   g_ah);
    cudaGetSymbolAddress((void**)&al,   g_al);
    cudaGetSymbolAddress((void**)&deph, g_deph);
    cudaGetSymbolAddress((void**)&depl, g_depl);
    cudaGetSymbolAddress((void**)&pth,  g_pth);
    cudaGetSymbolAddress((void**)&ptl,  g_ptl);
    cudaGetSymbolAddress((void**)&pwT,  g_pwT);
    cudaGetSymbolAddress((void**)&w1h,  g_w1);
    cudaGetSymbolAddress((void**)&w2h,  g_w2);
    cudaGetSymbolAddress((void**)&wqh,  g_wq);
    cudaGetSymbolAddress((void**)&wkvh, g_wkv);
    cudaGetSymbolAddress((void**)&woh,  g_wo);

    cudaFuncSetAttribute(mma_gemm2<2>, cudaFuncAttributeMaxDynamicSharedMemorySize, MM_SMEM2);
    cudaFuncSetAttribute(mma_gemm2<3>, cudaFuncAttributeMaxDynamicSharedMemorySize, MM_SMEM2);
    cudaFuncSetAttribute(mma_gemm2<4>, cudaFuncAttributeMaxDynamicSharedMemorySize, MM_SMEM2);
    cudaFuncSetAttribute(mma_gemm2<6>, cudaFuncAttributeMaxDynamicSharedMemorySize, MM_SMEM2);
    cudaFuncSetAttribute(mma_gemm3<5>, cudaFuncAttributeMaxDynamicSharedMemorySize, MM_SMEM3);
    cudaFuncSetAttribute(mma_gemm3<8>, cudaFuncAttributeMaxDynamicSharedMemorySize, MM_SMEM3);

    dim3 blk(256);

    // 0) prep: weight conversions, norms, x split, packed kv bias
    cvt_half<<<(128 * cD) / 1024, blk>>>(Wq, wqh, (long)128 * cD);
    cvt_half<<<(128 * cD) / 1024, blk>>>(Wk, wkvh, (long)128 * cD);
    cvt_half<<<(128 * cD) / 1024, blk>>>(Wv, wkvh + 128 * cD, (long)128 * cD);
    cvt_half<<<(cD * 128) / 1024, blk>>>(Wo, woh, (long)cD * 128);
    cvt_half<<<(cC * cD) / 1024, blk>>>(w1_w, w1h, (long)cC * cD);
    cvt_half<<<(cD * cC) / 1024, blk>>>(w2_w, w2h, (long)cD * cC);
    cudaMemcpyAsync(bkv,       bk, 128 * sizeof(float), cudaMemcpyDeviceToDevice);
    cudaMemcpyAsync(bkv + 128, bv, 128 * sizeof(float), cudaMemcpyDeviceToDevice);
    cvtT_k<<<dim3(32, 32, cB), blk>>>(p_w, pwT);
    dwn_k<<<dim3(9, cB), 128>>>(d_w, dwn);
    pwn_k<<<dim3(4, cB), blk>>>(p_w, pwn);
    cvt_split_h<<<(cNT * cD) / 1024, blk>>>(x, xh, xl, (long)cNT * cD);

    // 1) q (split out): [16384,256] @ [128,256]^T
    mma_gemm2<6><<<dim3(1, cNT / 128, 1), blk, MM_SMEM2>>>(
        xh, xl, wqh, nullptr, qh, ql, cD, cD, cD, 128, 128, 1,
        0, 0, 0, 0, 0, 0, 0, 0, bq, nullptr);
    // 2) kv fused (split out): [16384,256] @ [256,256]^T
    mma_gemm2<6><<<dim3(2, cNT / 128, 1), blk, MM_SMEM2>>>(
        xh, xl, wkvh, nullptr, kvh, kvl, cD, cD, cD, 256, 256, 1,
        0, 0, 0, 0, 0, 0, 0, 0, bkv, nullptr);

    // 3) v -> vT split (padded 128 rows per (b,h))
    vT_k<<<dim3(32, 4, cB), blk>>>(kvh, kvl, vTh, vTl);

    // 4) scores = q k^T / 8  [3-product, z=(b,h) zdiv=2]
    mma_gemm3<5><<<dim3(8, 8, 32), blk, MM_SMEM3>>>(
        qh, ql, kvh, kvl, attn, nullptr, nullptr, cDK, 128, 256, cT, 1024, 2,
        (long)cT * 128, 64, (long)cT * 256, 64, 2 * cTT, cTT, 0, 0, nullptr, nullptr);

    // 5) masked softmax (writes final attn + fp16 split)
    softmax_k<<<dim3(cT, cH, cB), blk>>>(attn, smask, atth, attl);

    // 6) ctx = attn @ v  [3-product] -> fp16 split, col guard 64
    mma_gemm3<8><<<dim3(1, 8, 32), blk, MM_SMEM3>>>(
        atth, attl, vTh, vTl, nullptr, ctxh, ctxl, cT, cT, cT, 128, 64, 2,
        2 * cTT, cTT, (long)256 * cT, (long)128 * cT, (long)cT * 128, 64,
        0, 0, nullptr, nullptr);

    // 7) apre = ctx @ Wo^T + bo + x
    mma_gemm2<2><<<dim3(2, cNT / 128, 1), blk, MM_SMEM2>>>(
        ctxh, ctxl, woh, apre, nullptr, nullptr, 128, 128, 128, cD, 256, 1,
        0, 0, 0, 0, 0, 0, 0, 0, bo, x);

    // 8) a = LN(apre), masked; emit fp16 split
    ln_k<<<cNT, blk>>>(apre, g0, b0, mask, a, ah, al);

    // 9) h = mish(a @ w1^T + w1_b)
    mma_gemm2<3><<<dim3(cC / 128, cNT / 128, 1), blk, MM_SMEM2>>>(
        ah, al, w1h, h, nullptr, nullptr, cD, cD, cD, cC, 1024, 1,
        0, 0, 0, 0, 0, 0, 0, 0, w1_b, nullptr);

    // 10) depthwise conv (emits dep fp16 split)
    conv_k<<<dim3(cT, cB), blk>>>(h, d_w, d_g, d_b, p_g, dwn, deph, depl);

    // 11) pt = (dep' @ pwT) * pwninv[o] + p_b  [batched over b; fp16-split output]
    mma_gemm2<4><<<dim3(cC / 128, cT / 128, cB), blk, MM_SMEM2>>>(
        deph, depl, pwT, nullptr, pth, ptl, cC, cC, cC, cC, 1024, 1,
        (long)cT * cC, 0, (long)cC * cC, 0, (long)cT * cC, 0, cC, cC, p_b, pwn);

    // 12) o2 = pt @ w2^T + w2_b + a
    mma_gemm2<2><<<dim3(cD / 128, cNT / 128, 1), blk, MM_SMEM2>>>(
        pth, ptl, w2h, o2, nullptr, nullptr, cC, cC, cC, cD, 256, 1,
        0, 0, 0, 0, 0, 0, 0, 0, w2_b, a);

    // 13) out = LN(o2), masked
    ln_k<<<cNT, blk>>>(o2, g1, b1, mask, out, nullptr, nullptr);
}

// round 8
// speedup vs baseline: 2.6343x; 1.0739x over previous
#include <cuda_runtime.h>
#include <cuda_fp16.h>
#include <cstdint>
#include <math.h>

// ---------------- problem constants ----------------
constexpr int cB = 16, cT = 1024, cD = 256, cH = 2, cDK = 64, cC = 1024;
constexpr int cNT = cB * cT;            // 16384 tokens
constexpr long cTT = (long)cT * cT;     // 1M
constexpr float LN_EPS = 1e-5f;

// ---------------- device scratch (no allocs allowed) ----------------
__device__ float g_apre[cNT * cD];
__device__ float g_a   [cNT * cD];
__device__ float g_h  [cNT * cC];
__device__ float g_o2 [cNT * cD];
__device__ float g_dwn[cB * 9];
__device__ float g_pwn[cB * cC];
__device__ float g_bkv[256];
// fp16 buffers
__device__ __half g_xh  [cNT * cD];
__device__ __half g_xl  [cNT * cD];
__device__ __half g_qh  [cNT * 128];
__device__ __half g_ql  [cNT * 128];
__device__ __half g_kvh [cNT * 256];
__device__ __half g_kvl [cNT * 256];
__device__ __half g_vTh [(long)cB * cH * 128 * cT];   // padded to 128 rows per (b,h)
__device__ __half g_vTl [(long)cB * cH * 128 * cT];
__device__ __half g_atth[(long)cB * cH * cTT];
__device__ __half g_attl[(long)cB * cH * cTT];
__device__ __half g_ctxh[cNT * 128];
__device__ __half g_ctxl[cNT * 128];
__device__ __half g_ah  [cNT * cD];
__device__ __half g_al  [cNT * cD];
__device__ __half g_deph[cNT * cC];
__device__ __half g_depl[cNT * cC];
__device__ __half g_pth [cNT * cC];
__device__ __half g_ptl [cNT * cC];
__device__ __half g_pwT [(long)cB * cC * cC];
__device__ __half g_w1  [cC * cD];
__device__ __half g_w2  [cD * cC];
__device__ __half g_wq  [128 * cD];
__device__ __half g_wql [128 * cD];
__device__ __half g_wkv [256 * cD];
__device__ __half g_wkvl[256 * cD];
__device__ __half g_wo  [cD * 128];
__device__ __half g_wol [cD * 128];

// ---------------- helpers ----------------
__device__ __forceinline__ uint32_t smem_u32(const void* p) {
    uint32_t a;
    asm("{ .reg .u64 t; cvta.to.shared.u64 t, %1; cvt.u32.u64 %0, t; }" : "=r"(a) : "l"(p));
    return a;
}
#define SW128(off) ((off) ^ (((off) >> 3) & 0x70))

__device__ __forceinline__ void split_h(float v, __half& h, __half& l) {
    h = __float2half_rn(v);
    l = __float2half_rn(v - __half2float(h));
}

__device__ __forceinline__ void ldsm4(uint32_t* r, uint32_t addr) {
    asm volatile("ldmatrix.sync.aligned.m8n8.x4.shared.b16 {%0,%1,%2,%3}, [%4];"
        : "=r"(r[0]), "=r"(r[1]), "=r"(r[2]), "=r"(r[3]) : "r"(addr));
}
__device__ __forceinline__ void mma16816(float* d, const uint32_t* a, const uint32_t* b) {
    asm volatile("mma.sync.aligned.m16n8k16.row.col.f32.f16.f16.f32 "
        "{%0,%1,%2,%3}, {%4,%5,%6,%7}, {%8,%9}, {%0,%1,%2,%3};"
        : "+f"(d[0]), "+f"(d[1]), "+f"(d[2]), "+f"(d[3])
        : "r"(a[0]), "r"(a[1]), "r"(a[2]), "r"(a[3]), "r"(b[0]), "r"(b[1]));
}
__device__ __forceinline__ void cp16(uint32_t saddr, const void* gptr) {
    asm volatile("cp.async.cg.shared.global [%0], [%1], 16;"
        :: "r"(saddr), "l"(__cvta_generic_to_global(gptr)));
}
__device__ __forceinline__ void cp_commit() {
    asm volatile("cp.async.commit_group;");
}
template<int N>
__device__ __forceinline__ void cp_wait() {
    asm volatile("cp.async.wait_group %0;" :: "n"(N));
}

__device__ __forceinline__ float warpReduceSum(float v) {
#pragma unroll
    for (int o = 16; o > 0; o >>= 1) v += __shfl_xor_sync(0xffffffffu, v, o);
    return v;
}
__device__ __forceinline__ float warpReduceMax(float v) {
#pragma unroll
    for (int o = 16; o > 0; o >>= 1) v = fmaxf(v, __shfl_xor_sync(0xffffffffu, v, o));
    return v;
}

// ---------------- mma.sync fp16-split GEMM body ----------------
// D[M,N] = A[M,K] @ B[N,K]^T.  A = Ah + Al (fp16 split).
// NPROD=2: acc += Ah*Bh + Al*Bh (B single).  NPROD=3: + Ah*Bl (B split too).
// EPI: 2 = +bias[n]+aux residual -> f32 | 3 = mish(acc+bias) -> f32
//      4 = acc*aux[n]+bias[n] -> fp16 split | 5 = acc*0.125 -> f32
//      6 = +bias -> fp16 split | 8 = raw -> fp16 split
constexpr int MM_SMEM2 = 2 * 49152 + 1024;
constexpr int MM_SMEM3 = 2 * 65536 + 1024;

template<int EPI, int NPROD>
__device__ __forceinline__ void mma_body(
    const __half* __restrict__ Ah, const __half* __restrict__ Al,
    const __half* __restrict__ Bh, const __half* __restrict__ Bl,
    float* __restrict__ C, __half* __restrict__ Ch, __half* __restrict__ Cl,
    int Kd, int lda, int ldb, int ldc, int nLim, int zdiv,
    long aQ, long aR, long bQ, long bR, long cQ, long cR,
    long biasZ, long auxZ,
    const float* __restrict__ bias, const float* __restrict__ aux)
{
    constexpr int STAGE = (NPROD == 3) ? 65536 : 49152;
    extern __shared__ char sm_raw[];
    uint32_t sb0 = smem_u32(sm_raw);
    uint32_t sb  = (sb0 + 1023u) & ~1023u;

    int z = blockIdx.z;
    int zq = z / zdiv, zr = z - zq * zdiv;
    long aoff = (long)zq * aQ + (long)zr * aR;
    long boff = (long)zq * bQ + (long)zr * bR;
    long coff = (long)zq * cQ + (long)zr * cR;
    Ah += aoff; Al += aoff;
    Bh += boff;
    if (NPROD == 3) Bl += boff;
    if (C)  C  += coff;
    if (Ch) Ch += coff;
    if (Cl) Cl += coff;
    const float* biasp = bias ? bias + (long)zq * biasZ : nullptr;
    const float* auxp  = aux  ? aux  + (long)zq * auxZ  : nullptr;

    int m0 = blockIdx.y * 128, n0 = blockIdx.x * 128;
    int tid = threadIdx.x, wid = tid >> 5, lane = tid & 31;
    int wm = wid & 3, wn = wid >> 2;

    int lrow = tid >> 3, lcq = tid & 7;

    auto issue_stage = [&](int k0, uint32_t sbase) {
#pragma unroll
        for (int ti = 0; ti < 4; ti++) {
            int row = lrow + ti * 32;
            uint32_t soff = SW128((uint32_t)(row * 128 + lcq * 16));
            long ga = (long)(m0 + row) * lda + k0 + lcq * 8;
            long gb = (long)(n0 + row) * ldb + k0 + lcq * 8;
            cp16(sbase + soff,         Ah + ga);
            cp16(sbase + 16384 + soff, Al + ga);
            cp16(sbase + 32768 + soff, Bh + gb);
            if (NPROD == 3) cp16(sbase + 49152 + soff, Bl + gb);
        }
        cp_commit();
    };

    float acc[2][8][4];
#pragma unroll
    for (int i = 0; i < 2; i++)
#pragma unroll
        for (int j = 0; j < 8; j++)
#pragma unroll
            for (int l = 0; l < 4; l++) acc[i][j][l] = 0.f;

    int nk = Kd >> 6;
    issue_stage(0, sb);

    for (int i = 0; i < nk; i++) {
        uint32_t cur = sb + (uint32_t)(i & 1) * STAGE;
        if (i + 1 < nk) {
            issue_stage((i + 1) << 6, sb + (uint32_t)((i + 1) & 1) * STAGE);
            cp_wait<1>();
        } else {
            cp_wait<0>();
        }
        __syncthreads();

        uint32_t uAh = cur, uAl = cur + 16384, uBh = cur + 32768, uBl = cur + 49152;
#pragma unroll
        for (int ks = 0; ks < 4; ks++) {
            uint32_t afh[2][4], afl[2][4], bfh[4][4], bfl[4][4];
#pragma unroll
            for (int mt = 0; mt < 2; mt++) {
                int r = wm * 32 + mt * 16 + (lane & 15);
                int kc = ks * 2 + (lane >> 4);
                uint32_t off = SW128((uint32_t)(r * 128 + kc * 16));
                ldsm4(afh[mt], uAh + off);
                ldsm4(afl[mt], uAl + off);
            }
#pragma unroll
            for (int bt = 0; bt < 4; bt++) {
                int r = wn * 64 + bt * 16 + (lane & 7) + ((lane >> 4) << 3);
                int kc = ks * 2 + ((lane >> 3) & 1);
                uint32_t off = SW128((uint32_t)(r * 128 + kc * 16));
                ldsm4(bfh[bt], uBh + off);
                if (NPROD == 3) ldsm4(bfl[bt], uBl + off);
            }
#pragma unroll
            for (int p = 0; p < NPROD; p++)
#pragma unroll
                for (int mt = 0; mt < 2; mt++)
#pragma unroll
                    for (int bt = 0; bt < 4; bt++)
#pragma unroll
                        for (int hh = 0; hh < 2; hh++) {
                            const uint32_t* af  = (p == 1) ? afl[mt] : afh[mt];
                            const uint32_t* bfp = (p == 2) ? &bfl[bt][hh * 2] : &bfh[bt][hh * 2];
                            mma16816(acc[mt][bt * 2 + hh], af, bfp);
                        }
        }
        __syncthreads();
    }

    // epilogue
#pragma unroll
    for (int mt = 0; mt < 2; mt++)
#pragma unroll
        for (int bt = 0; bt < 4; bt++)
#pragma unroll
            for (int hh = 0; hh < 2; hh++) {
                float* d = acc[mt][bt * 2 + hh];
                int col = n0 + wn * 64 + bt * 16 + hh * 8 + (lane & 3) * 2;
                int r0  = m0 + wm * 32 + mt * 16 + (lane >> 2);
                if (col >= nLim) continue;
#pragma unroll
                for (int half = 0; half < 2; half++) {
                    int row = r0 + half * 8;
                    float t0 = d[half * 2 + 0], t1 = d[half * 2 + 1];
                    if (EPI == 2) {
                        t0 += biasp[col]     + auxp[(long)row * ldc + col];
                        t1 += biasp[col + 1] + auxp[(long)row * ldc + col + 1];
                        float2 v = {t0, t1};
                        *reinterpret_cast<float2*>(C + (long)row * ldc + col) = v;
                    } else if (EPI == 3) {
                        t0 += biasp[col];
                        t1 += biasp[col + 1];
                        float sp0 = (t0 > 20.f) ? t0 : log1pf(expf(t0));
                        float sp1 = (t1 > 20.f) ? t1 : log1pf(expf(t1));
                        t0 = t0 * tanhf(sp0);
                        t1 = t1 * tanhf(sp1);
                        float2 v = {t0, t1};
                        *reinterpret_cast<float2*>(C + (long)row * ldc + col) = v;
                    } else if (EPI == 5) {
                        float2 v = {t0 * 0.125f, t1 * 0.125f};
                        *reinterpret_cast<float2*>(C + (long)row * ldc + col) = v;
                    } else { // 4, 6, 8: fp16 split outputs
                        if (EPI == 4) {
                            t0 = t0 * auxp[col]     + biasp[col];
                            t1 = t1 * auxp[col + 1] + biasp[col + 1];
                        } else if (EPI == 6) {
                            t0 += biasp[col];
                            t1 += biasp[col + 1];
                        }
                        __half h0, l0, h1, l1;
                        split_h(t0, h0, l0);
                        split_h(t1, h1, l1);
                        __half2 hv = {h0, h1}, lv = {l0, l1};
                        *reinterpret_cast<__half2*>(Ch + (long)row * ldc + col) = hv;
                        *reinterpret_cast<__half2*>(Cl + (long)row * ldc + col) = lv;
                    }
                }
            }
}

template<int EPI>
__global__ void __launch_bounds__(256, 2) mma_gemm2(
    const __half* __restrict__ Ah, const __half* __restrict__ Al,
    const __half* __restrict__ Bh,
    float* __restrict__ C, __half* __restrict__ Ch, __half* __restrict__ Cl,
    int Kd, int lda, int ldb, int ldc, int nLim, int zdiv,
    long aQ, long aR, long bQ, long bR, long cQ, long cR,
    long biasZ, long auxZ,
    const float* __restrict__ bias, const float* __restrict__ aux)
{
    mma_body<EPI, 2>(Ah, Al, Bh, nullptr, C, Ch, Cl, Kd, lda, ldb, ldc, nLim, zdiv,
                     aQ, aR, bQ, bR, cQ, cR, biasZ, auxZ, bias, aux);
}

template<int EPI>
__global__ void __launch_bounds__(256) mma_gemm3(
    const __half* __restrict__ Ah, const __half* __restrict__ Al,
    const __half* __restrict__ Bh, const __half* __restrict__ Bl,
    float* __restrict__ C, __half* __restrict__ Ch, __half* __restrict__ Cl,
    int Kd, int lda, int ldb, int ldc, int nLim, int zdiv,
    long aQ, long aR, long bQ, long bR, long cQ, long cR,
    long biasZ, long auxZ,
    const float* __restrict__ bias, const float* __restrict__ aux)
{
    mma_body<EPI, 3>(Ah, Al, Bh, Bl, C, Ch, Cl, Kd, lda, ldb, ldc, nLim, zdiv,
                     aQ, aR, bQ, bR, cQ, cR, biasZ, auxZ, bias, aux);
}

// ---------------- softmax (in place on attn rows; emits fp16 split) ----------------
__global__ void __launch_bounds__(256) softmax_k(float* __restrict__ attn,
                                                 const unsigned char* __restrict__ smask,
                                                 __half* __restrict__ ath,
                                                 __half* __restrict__ atl)
{
    int i = blockIdx.x, h = blockIdx.y, b = blockIdx.z;
    long rbase = (((long)(b * cH + h)) * cT + i) * cT;
    float* row = attn + rbase;
    const unsigned char* mrow = smask + ((long)b * cT + i) * cT;
    int tid = threadIdx.x, lane = tid & 31, wid = tid >> 5;
    __shared__ float red[8];
    __shared__ float bc;

    float v[4];
    float mx = -3.4e38f;
#pragma unroll
    for (int r = 0; r < 4; r++) {
        int j = tid + r * 256;
        float s = row[j];
        if (mrow[j]) s = -1e9f;
        v[r] = s;
        mx = fmaxf(mx, s);
    }
    mx = warpReduceMax(mx);
    if (lane == 0) red[wid] = mx;
    __syncthreads();
    if (wid == 0) {
        float r = (lane < 8) ? red[lane] : -3.4e38f;
        r = warpReduceMax(r);
        if (lane == 0) bc = r;
    }
    __syncthreads();
    mx = bc;
    float sum = 0.f;
#pragma unroll
    for (int r = 0; r < 4; r++) { v[r] = expf(v[r] - mx); sum += v[r]; }
    __syncthreads();
    sum = warpReduceSum(sum);
    if (lane == 0) red[wid] = sum;
    __syncthreads();
    if (wid == 0) {
        float r = (lane < 8) ? red[lane] : 0.f;
        r = warpReduceSum(r);
        if (lane == 0) bc = r;
    }
    __syncthreads();
    float inv = 1.f / bc;
#pragma unroll
    for (int r = 0; r < 4; r++) {
        int j = tid + r * 256;
        float y = v[r] * inv;
        row[j] = y;
        __half hh, ll;
        split_h(y, hh, ll);
        ath[rbase + j] = hh;
        atl[rbase + j] = ll;
    }
}

// ---------------- LayerNorm over D=256; optionally emits fp16 split ----------------
__global__ void __launch_bounds__(256) ln_k(const float* __restrict__ in,
                                            const float* __restrict__ g,
                                            const float* __restrict__ bta,
                                            const unsigned char* __restrict__ mask,
                                            float* __restrict__ out,
                                            __half* __restrict__ oh,
                                            __half* __restrict__ ol)
{
    long n = blockIdx.x;
    int tid = threadIdx.x, lane = tid & 31, wid = tid >> 5;
    __shared__ float red[8];
    __shared__ float stats[2];

    float x = in[n * cD + tid];
    float s = warpReduceSum(x);
    if (lane == 0) red[wid] = s;
    __syncthreads();
    if (wid == 0) {
        float r = (lane < 8) ? red[lane] : 0.f;
        r = warpReduceSum(r);
        if (lane == 0) stats[0] = r;
    }
    __syncthreads();
    float s2 = warpReduceSum(x * x);
    if (lane == 0) red[wid] = s2;
    __syncthreads();
    if (wid == 0) {
        float r = (lane < 8) ? red[lane] : 0.f;
        r = warpReduceSum(r);
        if (lane == 0) stats[1] = r;
    }
    __syncthreads();
    float mean = stats[0] * (1.f / cD);
    float var  = stats[1] * (1.f / cD) - mean * mean;
    float y = (x - mean) * rsqrtf(var + LN_EPS) * g[tid] + bta[tid];
    if (mask[n]) y = 0.f;
    out[n * cD + tid] = y;
    if (oh) {
        __half h, l;
        split_h(y, h, l);
        oh[n * cD + tid] = h;
        ol[n * cD + tid] = l;
    }
}

// ---------------- fp32 -> fp16 single ----------------
__global__ void __launch_bounds__(256) cvt_half(const float* __restrict__ in,
                                                __half* __restrict__ o, long n)
{
    long i = ((long)blockIdx.x * 256 + threadIdx.x) * 4;
    if (i >= n) return;
    float4 v = *reinterpret_cast<const float4*>(in + i);
    __half2 a = {__float2half_rn(v.x), __float2half_rn(v.y)};
    __half2 b = {__float2half_rn(v.z), __float2half_rn(v.w)};
    *reinterpret_cast<__half2*>(o + i)     = a;
    *reinterpret_cast<__half2*>(o + i + 2) = b;
}

// ---------------- fp32 -> fp16 hi/lo split ----------------
__global__ void __launch_bounds__(256) cvt_split_h(const float* __restrict__ in,
                                                   __half* __restrict__ oh,
                                                   __half* __restrict__ ol, long n)
{
    long i = ((long)blockIdx.x * 256 + threadIdx.x) * 4;
    if (i >= n) return;
    float4 v = *reinterpret_cast<const float4*>(in + i);
    __half h0, h1, h2, h3, l0, l1, l2, l3;
    split_h(v.x, h0, l0); split_h(v.y, h1, l1);
    split_h(v.z, h2, l2); split_h(v.w, h3, l3);
    __half2 ha = {h0, h1}, hb = {h2, h3}, la = {l0, l1}, lb = {l2, l3};
    *reinterpret_cast<__half2*>(oh + i)     = ha;
    *reinterpret_cast<__half2*>(oh + i + 2) = hb;
    *reinterpret_cast<__half2*>(ol + i)     = la;
    *reinterpret_cast<__half2*>(ol + i + 2) = lb;
}

// ---------------- kv cols 128..255 -> vT [(b,h)][n][t] split, rows 64..127 zeroed ----------------
__global__ void __launch_bounds__(256) vT_k(const __half* __restrict__ kvh,
                                            const __half* __restrict__ kvl,
                                            __half* __restrict__ vTh,
                                            __half* __restrict__ vTl)
{
    __shared__ __half th[32][33], tl[32][33];
    int b = blockIdx.z;
    int t0 = blockIdx.x * 32, c0 = blockIdx.y * 32;
    int tx = threadIdx.x & 31, ty = threadIdx.x >> 5;  // 32 x 8
#pragma unroll
    for (int i = 0; i < 4; i++) {
        int t = t0 + ty + i * 8;
        long src = ((long)b * cT + t) * 256 + 128 + c0 + tx;
        th[ty + i * 8][tx] = kvh[src];
        tl[ty + i * 8][tx] = kvl[src];
    }
    __syncthreads();
#pragma unroll
    for (int i = 0; i < 4; i++) {
        int c = c0 + ty + i * 8;
        int h = c >> 6, n = c & 63;
        long base = ((long)((b << 1) | h) * 128 + n) * cT + t0 + tx;
        vTh[base] = th[tx][ty + i * 8];
        vTl[base] = tl[tx][ty + i * 8];
        vTh[base + (long)64 * cT] = __float2half_rn(0.f);
        vTl[base + (long)64 * cT] = __float2half_rn(0.f);
    }
}

// ---------------- p_w transpose to fp16: in[b][c][o] -> out[b][o][c] ----------------
__global__ void __launch_bounds__(256) cvtT_k(const float* __restrict__ in,
                                              __half* __restrict__ oT)
{
    __shared__ float tile[32][33];
    int b = blockIdx.z;
    int o0 = blockIdx.x * 32, c0 = blockIdx.y * 32;
    int tx = threadIdx.x & 31, ty = threadIdx.x >> 5;  // 32 x 8
    const float* src = in + (long)b * cC * cC;
#pragma unroll
    for (int i = 0; i < 4; i++) {
        int c = c0 + ty + i * 8;
        tile[ty + i * 8][tx] = src[(long)c * cC + o0 + tx];
    }
    __syncthreads();
    __half* dst = oT + (long)b * cC * cC;
#pragma unroll
    for (int i = 0; i < 4; i++) {
        int o = o0 + ty + i * 8;
        dst[(long)o * cC + c0 + tx] = __float2half_rn(tile[tx][ty + i * 8]);
    }
}

// ---------------- depthwise weight inverse norms ----------------
__global__ void __launch_bounds__(128) dwn_k(const float* __restrict__ d_w, float* __restrict__ dwn)
{
    int k = blockIdx.x, b = blockIdx.y;
    int tid = threadIdx.x;
    float s = 0.f;
    for (int c = tid; c < cC; c += 128) {
        float w = d_w[((long)b * cC + c) * 9 + k];
        s += w * w;
    }
    __shared__ float red[4];
    s = warpReduceSum(s);
    if ((tid & 31) == 0) red[tid >> 5] = s;
    __syncthreads();
    if (tid == 0) {
        float r = red[0] + red[1] + red[2] + red[3];
        dwn[b * 9 + k] = 1.f / fmaxf(sqrtf(r), 1e-12f);
    }
}

__global__ void __launch_bounds__(256) pwn_k(const float* __restrict__ p_w, float* __restrict__ pwn)
{
    int c1 = blockIdx.x * 256 + threadIdx.x;
    int b = blockIdx.y;
    const float* base = p_w + (long)b * cC * cC + c1;
    float s = 0.f;
    for (int c2 = 0; c2 < cC; c2++) {
        float w = base[(long)c2 * cC];
        s += w * w;
    }
    pwn[b * cC + c1] = 1.f / fmaxf(sqrtf(s), 1e-12f);
}

// ---------------- tiled depthwise conv (K=9): smem tile, 9x less h traffic ----------------
constexpr int CV_TR = 32;   // output t-rows per block
__global__ void __launch_bounds__(256) conv2_k(const float* __restrict__ h,
                                               const float* __restrict__ d_w,
                                               const float* __restrict__ d_g,
                                               const float* __restrict__ d_b,
                                               const float* __restrict__ p_g,
                                               const float* __restrict__ dwn,
                                               __half* __restrict__ deph,
                                               __half* __restrict__ depl)
{
    __shared__ float hs[CV_TR + 8][256];
    __shared__ float ws[9];
    int t0 = blockIdx.x * CV_TR, c0 = blockIdx.y * 256, b = blockIdx.z;
    int tid = threadIdx.x;
    if (tid < 9) ws[tid] = dwn[b * 9 + tid];
    __syncthreads();

    // load halo tile: rows t0-4 .. t0+CV_TR+3 (zero outside)
#pragma unroll
    for (int i = tid; i < (CV_TR + 8) * 64; i += 256) {
        int r = i >> 6, q4 = i & 63;
        int t = t0 + r - 4;
        float4 v = (t >= 0 && t < cT)
            ? *reinterpret_cast<const float4*>(h + ((long)b * cT + t) * cC + c0 + q4 * 4)
            : make_float4(0.f, 0.f, 0.f, 0.f);
        *reinterpret_cast<float4*>(&hs[r][q4 * 4]) = v;
    }

    int c = c0 + tid;
    long bc = (long)b * cC + c;
    const float* wrow = d_w + bc * 9;
    float w[9];
#pragma unroll
    for (int k = 0; k < 9; k++) w[k] = wrow[k] * ws[k];
    float dg = d_g[bc], db = d_b[bc], pg = p_g[bc];
    __syncthreads();

#pragma unroll 4
    for (int tt = 0; tt < CV_TR; tt++) {
        float acc = 0.f;
#pragma unroll
        for (int k = 0; k < 9; k++) acc += hs[tt + k][tid] * w[k];
        float val = (acc * dg + db) * pg;
        __half hi, lo;
        split_h(val, hi, lo);
        long o = ((long)b * cT + t0 + tt) * cC + c;
        deph[o] = hi;
        depl[o] = lo;
    }
}

// ---------------- launch ----------------
extern "C" void kernel_launch(void* const* d_in, const int* in_sizes, int n_in,
                              void* d_out, int out_size)
{
    const float* x    = (const float*)d_in[0];
    const float* d_w  = (const float*)d_in[1];
    const float* d_g  = (const float*)d_in[2];
    const float* d_b  = (const float*)d_in[3];
    const float* p_w  = (const float*)d_in[4];
    const float* p_g  = (const float*)d_in[5];
    const float* p_b  = (const float*)d_in[6];
    const unsigned char* mask  = (const unsigned char*)d_in[7];
    const unsigned char* smask = (const unsigned char*)d_in[8];
    const float* Wq = (const float*)d_in[9];
    const float* bq = (const float*)d_in[10];
    const float* Wk = (const float*)d_in[11];
    const float* bk = (const float*)d_in[12];
    const float* Wv = (const float*)d_in[13];
    const float* bv = (const float*)d_in[14];
    const float* Wo = (const float*)d_in[15];
    const float* bo = (const float*)d_in[16];
    const float* g0 = (const float*)d_in[17];
    const float* b0 = (const float*)d_in[18];
    const float* w1_w = (const float*)d_in[19];
    const float* w1_b = (const float*)d_in[20];
    const float* w2_w = (const float*)d_in[21];
    const float* w2_b = (const float*)d_in[22];
    const float* g1 = (const float*)d_in[23];
    const float* b1 = (const float*)d_in[24];

    float* out  = (float*)d_out;
    float* attn = out + (long)cNT * cD;   // output tuple: (out[B,T,D], attn[B,H,T,T])

    float *apre, *a, *h, *o2, *dwn, *pwn, *bkv;
    __half *xh, *xl, *qh, *ql, *kvh, *kvl, *vTh, *vTl, *atth, *attl, *ctxh, *ctxl;
    __half *ah, *al, *deph, *depl, *pth, *ptl, *pwT, *w1h, *w2h;
    __half *wqh, *wql, *wkvh, *wkvl, *woh, *wol;
    cudaGetSymbolAddress((void**)&apre, g_apre);
    cudaGetSymbolAddress((void**)&a,    g_a);
    cudaGetSymbolAddress((void**)&h,    g_h);
    cudaGetSymbolAddress((void**)&o2,   g_o2);
    cudaGetSymbolAddress((void**)&dwn,  g_dwn);
    cudaGetSymbolAddress((void**)&pwn,  g_pwn);
    cudaGetSymbolAddress((void**)&bkv,  g_bkv);
    cudaGetSymbolAddress((void**)&xh,   g_xh);
    cudaGetSymbolAddress((void**)&xl,   g_xl);
    cudaGetSymbolAddress((void**)&qh,   g_qh);
    cudaGetSymbolAddress((void**)&ql,   g_ql);
    cudaGetSymbolAddress((void**)&kvh,  g_kvh);
    cudaGetSymbolAddress((void**)&kvl,  g_kvl);
    cudaGetSymbolAddress((void**)&vTh,  g_vTh);
    cudaGetSymbolAddress((void**)&vTl,  g_vTl);
    cudaGetSymbolAddress((void**)&atth, g_atth);
    cudaGetSymbolAddress((void**)&attl, g_attl);
    cudaGetSymbolAddress((void**)&ctxh, g_ctxh);
    cudaGetSymbolAddress((void**)&ctxl, g_ctxl);
    cudaGetSymbolAddress((void**)&ah,   g_ah);
    cudaGetSymbolAddress((void**)&al,   g_al);
    cudaGetSymbolAddress((void**)&deph, g_deph);
    cudaGetSymbolAddress((void**)&depl, g_depl);
    cudaGetSymbolAddress((void**)&pth,  g_pth);
    cudaGetSymbolAddress((void**)&ptl,  g_ptl);
    cudaGetSymbolAddress((void**)&pwT,  g_pwT);
    cudaGetSymbolAddress((void**)&w1h,  g_w1);
    cudaGetSymbolAddress((void**)&w2h,  g_w2);
    cudaGetSymbolAddress((void**)&wqh,  g_wq);
    cudaGetSymbolAddress((void**)&wql,  g_wql);
    cudaGetSymbolAddress((void**)&wkvh, g_wkv);
    cudaGetSymbolAddress((void**)&wkvl, g_wkvl);
    cudaGetSymbolAddress((void**)&woh,  g_wo);
    cudaGetSymbolAddress((void**)&wol,  g_wol);

    cudaFuncSetAttribute(mma_gemm2<2>, cudaFuncAttributeMaxDynamicSharedMemorySize, MM_SMEM2);
    cudaFuncSetAttribute(mma_gemm2<3>, cudaFuncAttributeMaxDynamicSharedMemorySize, MM_SMEM2);
    cudaFuncSetAttribute(mma_gemm2<4>, cudaFuncAttributeMaxDynamicSharedMemorySize, MM_SMEM2);
    cudaFuncSetAttribute(mma_gemm3<2>, cudaFuncAttributeMaxDynamicSharedMemorySize, MM_SMEM3);
    cudaFuncSetAttribute(mma_gemm3<5>, cudaFuncAttributeMaxDynamicSharedMemorySize, MM_SMEM3);
    cudaFuncSetAttribute(mma_gemm3<6>, cudaFuncAttributeMaxDynamicSharedMemorySize, MM_SMEM3);
    cudaFuncSetAttribute(mma_gemm3<8>, cudaFuncAttributeMaxDynamicSharedMemorySize, MM_SMEM3);

    dim3 blk(256);

    // 0) prep: weight conversions (projections split for 3-product), norms, x split
    cvt_split_h<<<(128 * cD) / 1024, blk>>>(Wq, wqh, wql, (long)128 * cD);
    cvt_split_h<<<(128 * cD) / 1024, blk>>>(Wk, wkvh, wkvl, (long)128 * cD);
    cvt_split_h<<<(128 * cD) / 1024, blk>>>(Wv, wkvh + 128 * cD, wkvl + 128 * cD, (long)128 * cD);
    cvt_split_h<<<(cD * 128) / 1024, blk>>>(Wo, woh, wol, (long)cD * 128);
    cvt_half<<<(cC * cD) / 1024, blk>>>(w1_w, w1h, (long)cC * cD);
    cvt_half<<<(cD * cC) / 1024, blk>>>(w2_w, w2h, (long)cD * cC);
    cudaMemcpyAsync(bkv,       bk, 128 * sizeof(float), cudaMemcpyDeviceToDevice);
    cudaMemcpyAsync(bkv + 128, bv, 128 * sizeof(float), cudaMemcpyDeviceToDevice);
    cvtT_k<<<dim3(32, 32, cB), blk>>>(p_w, pwT);
    dwn_k<<<dim3(9, cB), 128>>>(d_w, dwn);
    pwn_k<<<dim3(4, cB), blk>>>(p_w, pwn);
    cvt_split_h<<<(cNT * cD) / 1024, blk>>>(x, xh, xl, (long)cNT * cD);

    // 1) q (split out, 3-product): [16384,256] @ [128,256]^T
    mma_gemm3<6><<<dim3(1, cNT / 128, 1), blk, MM_SMEM3>>>(
        xh, xl, wqh, wql, nullptr, qh, ql, cD, cD, cD, 128, 128, 1,
        0, 0, 0, 0, 0, 0, 0, 0, bq, nullptr);
    // 2) kv fused (split out, 3-product): [16384,256] @ [256,256]^T
    mma_gemm3<6><<<dim3(2, cNT / 128, 1), blk, MM_SMEM3>>>(
        xh, xl, wkvh, wkvl, nullptr, kvh, kvl, cD, cD, cD, 256, 256, 1,
        0, 0, 0, 0, 0, 0, 0, 0, bkv, nullptr);

    // 3) v -> vT split (padded 128 rows per (b,h))
    vT_k<<<dim3(32, 4, cB), blk>>>(kvh, kvl, vTh, vTl);

    // 4) scores = q k^T / 8  [3-product, z=(b,h) zdiv=2]
    mma_gemm3<5><<<dim3(8, 8, 32), blk, MM_SMEM3>>>(
        qh, ql, kvh, kvl, attn, nullptr, nullptr, cDK, 128, 256, cT, 1024, 2,
        (long)cT * 128, 64, (long)cT * 256, 64, 2 * cTT, cTT, 0, 0, nullptr, nullptr);

    // 5) masked softmax (writes final attn + fp16 split)
    softmax_k<<<dim3(cT, cH, cB), blk>>>(attn, smask, atth, attl);

    // 6) ctx = attn @ v  [3-product] -> fp16 split, col guard 64
    mma_gemm3<8><<<dim3(1, 8, 32), blk, MM_SMEM3>>>(
        atth, attl, vTh, vTl, nullptr, ctxh, ctxl, cT, cT, cT, 128, 64, 2,
        2 * cTT, cTT, (long)256 * cT, (long)128 * cT, (long)cT * 128, 64,
        0, 0, nullptr, nullptr);

    // 7) apre = ctx @ Wo^T + bo + x  [3-product]
    mma_gemm3<2><<<dim3(2, cNT / 128, 1), blk, MM_SMEM3>>>(
        ctxh, ctxl, woh, wol, apre, nullptr, nullptr, 128, 128, 128, cD, 256, 1,
        0, 0, 0, 0, 0, 0, 0, 0, bo, x);

    // 8) a = LN(apre), masked; emit fp16 split
    ln_k<<<cNT, blk>>>(apre, g0, b0, mask, a, ah, al);

    // 9) h = mish(a @ w1^T + w1_b)
    mma_gemm2<3><<<dim3(cC / 128, cNT / 128, 1), blk, MM_SMEM2>>>(
        ah, al, w1h, h, nullptr, nullptr, cD, cD, cD, cC, 1024, 1,
        0, 0, 0, 0, 0, 0, 0, 0, w1_b, nullptr);

    // 10) tiled depthwise conv (emits dep fp16 split)
    conv2_k<<<dim3(cT / CV_TR, cC / 256, cB), blk>>>(h, d_w, d_g, d_b, p_g, dwn, deph, depl);

    // 11) pt = (dep' @ pwT) * pwninv[o] + p_b  [batched over b; fp16-split output]
    mma_gemm2<4><<<dim3(cC / 128, cT / 128, cB), blk, MM_SMEM2>>>(
        deph, depl, pwT, nullptr, pth, ptl, cC, cC, cC, cC, 1024, 1,
        (long)cT * cC, 0, (long)cC * cC, 0, (long)cT * cC, 0, cC, cC, p_b, pwn);

    // 12) o2 = pt @ w2^T + w2_b + a
    mma_gemm2<2><<<dim3(cD / 128, cNT / 128, 1), blk, MM_SMEM2>>>(
        pth, ptl, w2h, o2, nullptr, nullptr, cC, cC, cC, cD, 256, 1,
        0, 0, 0, 0, 0, 0, 0, 0, w2_b, a);

    // 13) out = LN(o2), masked
    ln_k<<<cNT, blk>>>(o2, g1, b1, mask, out, nullptr, nullptr);
}

// round 9
// speedup vs baseline: 3.0636x; 1.1630x over previous
#include <cuda_runtime.h>
#include <cuda_fp16.h>
#include <cstdint>
#include <math.h>

// ---------------- problem constants ----------------
constexpr int cB = 16, cT = 1024, cD = 256, cH = 2, cDK = 64, cC = 1024;
constexpr int cNT = cB * cT;            // 16384 tokens
constexpr long cTT = (long)cT * cT;     // 1M
constexpr float LN_EPS = 1e-5f;

// ---------------- device scratch (no allocs allowed) ----------------
__device__ float g_apre[cNT * cD];
__device__ float g_a   [cNT * cD];
__device__ float g_o2 [cNT * cD];
__device__ float g_dwn[cB * 9];
__device__ float g_pwn[cB * cC];
__device__ float g_bkv[256];
// fp16 buffers
__device__ __half g_xh  [cNT * cD];
__device__ __half g_xl  [cNT * cD];
__device__ __half g_qh  [cNT * 128];
__device__ __half g_ql  [cNT * 128];
__device__ __half g_kvh [cNT * 256];
__device__ __half g_kvl [cNT * 256];
__device__ __half g_vTh [(long)cB * cH * 128 * cT];   // padded to 128 rows per (b,h)
__device__ __half g_vTl [(long)cB * cH * 128 * cT];
__device__ __half g_atth[(long)cB * cH * cTT];
__device__ __half g_attl[(long)cB * cH * cTT];
__device__ __half g_ctxh[cNT * 128];
__device__ __half g_ctxl[cNT * 128];
__device__ __half g_ah  [cNT * cD];
__device__ __half g_hh  [cNT * cC];
__device__ __half g_deph[cNT * cC];
__device__ __half g_pth [cNT * cC];
__device__ __half g_pwT [(long)cB * cC * cC];
__device__ __half g_w1  [cC * cD];
__device__ __half g_w2  [cD * cC];
__device__ __half g_wq  [128 * cD];
__device__ __half g_wql [128 * cD];
__device__ __half g_wkv [256 * cD];
__device__ __half g_wkvl[256 * cD];
__device__ __half g_wo  [cD * 128];
__device__ __half g_wol [cD * 128];

// ---------------- helpers ----------------
__device__ __forceinline__ uint32_t smem_u32(const void* p) {
    uint32_t a;
    asm("{ .reg .u64 t; cvta.to.shared.u64 t, %1; cvt.u32.u64 %0, t; }" : "=r"(a) : "l"(p));
    return a;
}
#define SW128(off) ((off) ^ (((off) >> 3) & 0x70))

__device__ __forceinline__ void split_h(float v, __half& h, __half& l) {
    h = __float2half_rn(v);
    l = __float2half_rn(v - __half2float(h));
}

__device__ __forceinline__ void ldsm4(uint32_t* r, uint32_t addr) {
    asm volatile("ldmatrix.sync.aligned.m8n8.x4.shared.b16 {%0,%1,%2,%3}, [%4];"
        : "=r"(r[0]), "=r"(r[1]), "=r"(r[2]), "=r"(r[3]) : "r"(addr));
}
__device__ __forceinline__ void mma16816(float* d, const uint32_t* a, const uint32_t* b) {
    asm volatile("mma.sync.aligned.m16n8k16.row.col.f32.f16.f16.f32 "
        "{%0,%1,%2,%3}, {%4,%5,%6,%7}, {%8,%9}, {%0,%1,%2,%3};"
        : "+f"(d[0]), "+f"(d[1]), "+f"(d[2]), "+f"(d[3])
        : "r"(a[0]), "r"(a[1]), "r"(a[2]), "r"(a[3]), "r"(b[0]), "r"(b[1]));
}
__device__ __forceinline__ void cp16(uint32_t saddr, const void* gptr) {
    asm volatile("cp.async.cg.shared.global [%0], [%1], 16;"
        :: "r"(saddr), "l"(__cvta_generic_to_global(gptr)));
}
__device__ __forceinline__ void cp_commit() {
    asm volatile("cp.async.commit_group;");
}
template<int N>
__device__ __forceinline__ void cp_wait() {
    asm volatile("cp.async.wait_group %0;" :: "n"(N));
}

__device__ __forceinline__ float warpReduceSum(float v) {
#pragma unroll
    for (int o = 16; o > 0; o >>= 1) v += __shfl_xor_sync(0xffffffffu, v, o);
    return v;
}
__device__ __forceinline__ float warpReduceMax(float v) {
#pragma unroll
    for (int o = 16; o > 0; o >>= 1) v = fmaxf(v, __shfl_xor_sync(0xffffffffu, v, o));
    return v;
}

// ---------------- mma.sync fp16 GEMM body ----------------
// D[M,N] = A[M,K] @ B[N,K]^T.
// NPROD=1: A,B single fp16.  NPROD=2: A split, B single.  NPROD=3: A and B split.
// EPI: 2 = +bias[n]+aux residual -> f32 | 5 = acc*0.125 -> f32
//      6 = +bias -> fp16 split | 8 = raw -> fp16 split
//      9 = mish(acc+bias) -> fp16 single | 10 = acc*aux[n]+bias[n] -> fp16 single
constexpr int MM_SMEM1 = 2 * 32768 + 1024;
constexpr int MM_SMEM3 = 2 * 65536 + 1024;

template<int EPI, int NPROD>
__device__ __forceinline__ void mma_body(
    const __half* __restrict__ Ah, const __half* __restrict__ Al,
    const __half* __restrict__ Bh, const __half* __restrict__ Bl,
    float* __restrict__ C, __half* __restrict__ Ch, __half* __restrict__ Cl,
    int Kd, int lda, int ldb, int ldc, int nLim, int zdiv,
    long aQ, long aR, long bQ, long bR, long cQ, long cR,
    long biasZ, long auxZ,
    const float* __restrict__ bias, const float* __restrict__ aux)
{
    constexpr int STAGE = (NPROD == 3) ? 65536 : (NPROD == 2 ? 49152 : 32768);
    constexpr int BOFF  = (NPROD == 1) ? 16384 : 32768;
    extern __shared__ char sm_raw[];
    uint32_t sb0 = smem_u32(sm_raw);
    uint32_t sb  = (sb0 + 1023u) & ~1023u;

    int z = blockIdx.z;
    int zq = z / zdiv, zr = z - zq * zdiv;
    long aoff = (long)zq * aQ + (long)zr * aR;
    long boff = (long)zq * bQ + (long)zr * bR;
    long coff = (long)zq * cQ + (long)zr * cR;
    Ah += aoff;
    if (NPROD >= 2) Al += aoff;
    Bh += boff;
    if (NPROD == 3) Bl += boff;
    if (C)  C  += coff;
    if (Ch) Ch += coff;
    if (Cl) Cl += coff;
    const float* biasp = bias ? bias + (long)zq * biasZ : nullptr;
    const float* auxp  = aux  ? aux  + (long)zq * auxZ  : nullptr;

    int m0 = blockIdx.y * 128, n0 = blockIdx.x * 128;
    int tid = threadIdx.x, wid = tid >> 5, lane = tid & 31;
    int wm = wid & 3, wn = wid >> 2;

    int lrow = tid >> 3, lcq = tid & 7;

    auto issue_stage = [&](int k0, uint32_t sbase) {
#pragma unroll
        for (int ti = 0; ti < 4; ti++) {
            int row = lrow + ti * 32;
            uint32_t soff = SW128((uint32_t)(row * 128 + lcq * 16));
            long ga = (long)(m0 + row) * lda + k0 + lcq * 8;
            long gb = (long)(n0 + row) * ldb + k0 + lcq * 8;
            cp16(sbase + soff, Ah + ga);
            if (NPROD >= 2) cp16(sbase + 16384 + soff, Al + ga);
            cp16(sbase + BOFF + soff, Bh + gb);
            if (NPROD == 3) cp16(sbase + 49152 + soff, Bl + gb);
        }
        cp_commit();
    };

    float acc[2][8][4];
#pragma unroll
    for (int i = 0; i < 2; i++)
#pragma unroll
        for (int j = 0; j < 8; j++)
#pragma unroll
            for (int l = 0; l < 4; l++) acc[i][j][l] = 0.f;

    int nk = Kd >> 6;
    issue_stage(0, sb);

    for (int i = 0; i < nk; i++) {
        uint32_t cur = sb + (uint32_t)(i & 1) * STAGE;
        if (i + 1 < nk) {
            issue_stage((i + 1) << 6, sb + (uint32_t)((i + 1) & 1) * STAGE);
            cp_wait<1>();
        } else {
            cp_wait<0>();
        }
        __syncthreads();

        uint32_t uAh = cur, uAl = cur + 16384, uBh = cur + BOFF, uBl = cur + 49152;
#pragma unroll
        for (int ks = 0; ks < 4; ks++) {
            uint32_t afh[2][4], afl[2][4], bfh[4][4], bfl[4][4];
#pragma unroll
            for (int mt = 0; mt < 2; mt++) {
                int r = wm * 32 + mt * 16 + (lane & 15);
                int kc = ks * 2 + (lane >> 4);
                uint32_t off = SW128((uint32_t)(r * 128 + kc * 16));
                ldsm4(afh[mt], uAh + off);
                if (NPROD >= 2) ldsm4(afl[mt], uAl + off);
            }
#pragma unroll
            for (int bt = 0; bt < 4; bt++) {
                int r = wn * 64 + bt * 16 + (lane & 7) + ((lane >> 4) << 3);
                int kc = ks * 2 + ((lane >> 3) & 1);
                uint32_t off = SW128((uint32_t)(r * 128 + kc * 16));
                ldsm4(bfh[bt], uBh + off);
                if (NPROD == 3) ldsm4(bfl[bt], uBl + off);
            }
#pragma unroll
            for (int p = 0; p < NPROD; p++)
#pragma unroll
                for (int mt = 0; mt < 2; mt++)
#pragma unroll
                    for (int bt = 0; bt < 4; bt++)
#pragma unroll
                        for (int hh = 0; hh < 2; hh++) {
                            const uint32_t* af  = (p == 1) ? afl[mt] : afh[mt];
                            const uint32_t* bfp = (p == 2) ? &bfl[bt][hh * 2] : &bfh[bt][hh * 2];
                            mma16816(acc[mt][bt * 2 + hh], af, bfp);
                        }
        }
        __syncthreads();
    }

    // epilogue
#pragma unroll
    for (int mt = 0; mt < 2; mt++)
#pragma unroll
        for (int bt = 0; bt < 4; bt++)
#pragma unroll
            for (int hh = 0; hh < 2; hh++) {
                float* d = acc[mt][bt * 2 + hh];
                int col = n0 + wn * 64 + bt * 16 + hh * 8 + (lane & 3) * 2;
                int r0  = m0 + wm * 32 + mt * 16 + (lane >> 2);
                if (col >= nLim) continue;
#pragma unroll
                for (int half = 0; half < 2; half++) {
                    int row = r0 + half * 8;
                    float t0 = d[half * 2 + 0], t1 = d[half * 2 + 1];
                    if (EPI == 2) {
                        t0 += biasp[col]     + auxp[(long)row * ldc + col];
                        t1 += biasp[col + 1] + auxp[(long)row * ldc + col + 1];
                        float2 v = {t0, t1};
                        *reinterpret_cast<float2*>(C + (long)row * ldc + col) = v;
                    } else if (EPI == 5) {
                        float2 v = {t0 * 0.125f, t1 * 0.125f};
                        *reinterpret_cast<float2*>(C + (long)row * ldc + col) = v;
                    } else if (EPI == 9) {
                        t0 += biasp[col];
                        t1 += biasp[col + 1];
                        float sp0 = (t0 > 20.f) ? t0 : log1pf(expf(t0));
                        float sp1 = (t1 > 20.f) ? t1 : log1pf(expf(t1));
                        t0 = t0 * tanhf(sp0);
                        t1 = t1 * tanhf(sp1);
                        __half2 hv = {__float2half_rn(t0), __float2half_rn(t1)};
                        *reinterpret_cast<__half2*>(Ch + (long)row * ldc + col) = hv;
                    } else if (EPI == 10) {
                        t0 = t0 * auxp[col]     + biasp[col];
                        t1 = t1 * auxp[col + 1] + biasp[col + 1];
                        __half2 hv = {__float2half_rn(t0), __float2half_rn(t1)};
                        *reinterpret_cast<__half2*>(Ch + (long)row * ldc + col) = hv;
                    } else { // 6, 8: fp16 split outputs
                        if (EPI == 6) {
                            t0 += biasp[col];
                            t1 += biasp[col + 1];
                        }
                        __half h0, l0, h1, l1;
                        split_h(t0, h0, l0);
                        split_h(t1, h1, l1);
                        __half2 hv = {h0, h1}, lv = {l0, l1};
                        *reinterpret_cast<__half2*>(Ch + (long)row * ldc + col) = hv;
                        *reinterpret_cast<__half2*>(Cl + (long)row * ldc + col) = lv;
                    }
                }
            }
}

template<int EPI>
__global__ void __launch_bounds__(256) mma_gemm1(
    const __half* __restrict__ Ah, const __half* __restrict__ Bh,
    float* __restrict__ C, __half* __restrict__ Ch,
    int Kd, int lda, int ldb, int ldc, int nLim, int zdiv,
    long aQ, long aR, long bQ, long bR, long cQ, long cR,
    long biasZ, long auxZ,
    const float* __restrict__ bias, const float* __restrict__ aux)
{
    mma_body<EPI, 1>(Ah, nullptr, Bh, nullptr, C, Ch, nullptr, Kd, lda, ldb, ldc, nLim, zdiv,
                     aQ, aR, bQ, bR, cQ, cR, biasZ, auxZ, bias, aux);
}

template<int EPI>
__global__ void __launch_bounds__(256) mma_gemm3(
    const __half* __restrict__ Ah, const __half* __restrict__ Al,
    const __half* __restrict__ Bh, const __half* __restrict__ Bl,
    float* __restrict__ C, __half* __restrict__ Ch, __half* __restrict__ Cl,
    int Kd, int lda, int ldb, int ldc, int nLim, int zdiv,
    long aQ, long aR, long bQ, long bR, long cQ, long cR,
    long biasZ, long auxZ,
    const float* __restrict__ bias, const float* __restrict__ aux)
{
    mma_body<EPI, 3>(Ah, Al, Bh, Bl, C, Ch, Cl, Kd, lda, ldb, ldc, nLim, zdiv,
                     aQ, aR, bQ, bR, cQ, cR, biasZ, auxZ, bias, aux);
}

// ---------------- softmax (in place on attn rows; emits fp16 split) ----------------
__global__ void __launch_bounds__(256) softmax_k(float* __restrict__ attn,
                                                 const unsigned char* __restrict__ smask,
                                                 __half* __restrict__ ath,
                                                 __half* __restrict__ atl)
{
    int i = blockIdx.x, h = blockIdx.y, b = blockIdx.z;
    long rbase = (((long)(b * cH + h)) * cT + i) * cT;
    float* row = attn + rbase;
    const unsigned char* mrow = smask + ((long)b * cT + i) * cT;
    int tid = threadIdx.x, lane = tid & 31, wid = tid >> 5;
    __shared__ float red[8];
    __shared__ float bc;

    float v[4];
    float mx = -3.4e38f;
#pragma unroll
    for (int r = 0; r < 4; r++) {
        int j = tid + r * 256;
        float s = row[j];
        if (mrow[j]) s = -1e9f;
        v[r] = s;
        mx = fmaxf(mx, s);
    }
    mx = warpReduceMax(mx);
    if (lane == 0) red[wid] = mx;
    __syncthreads();
    if (wid == 0) {
        float r = (lane < 8) ? red[lane] : -3.4e38f;
        r = warpReduceMax(r);
        if (lane == 0) bc = r;
    }
    __syncthreads();
    mx = bc;
    float sum = 0.f;
#pragma unroll
    for (int r = 0; r < 4; r++) { v[r] = expf(v[r] - mx); sum += v[r]; }
    __syncthreads();
    sum = warpReduceSum(sum);
    if (lane == 0) red[wid] = sum;
    __syncthreads();
    if (wid == 0) {
        float r = (lane < 8) ? red[lane] : 0.f;
        r = warpReduceSum(r);
        if (lane == 0) bc = r;
    }
    __syncthreads();
    float inv = 1.f / bc;
#pragma unroll
    for (int r = 0; r < 4; r++) {
        int j = tid + r * 256;
        float y = v[r] * inv;
        row[j] = y;
        __half hh, ll;
        split_h(y, hh, ll);
        ath[rbase + j] = hh;
        atl[rbase + j] = ll;
    }
}

// ---------------- LayerNorm over D=256; optional fp16 output ----------------
__global__ void __launch_bounds__(256) ln_k(const float* __restrict__ in,
                                            const float* __restrict__ g,
                                            const float* __restrict__ bta,
                                            const unsigned char* __restrict__ mask,
                                            float* __restrict__ out,
                                            __half* __restrict__ oh)
{
    long n = blockIdx.x;
    int tid = threadIdx.x, lane = tid & 31, wid = tid >> 5;
    __shared__ float red[8];
    __shared__ float stats[2];

    float x = in[n * cD + tid];
    float s = warpReduceSum(x);
    if (lane == 0) red[wid] = s;
    __syncthreads();
    if (wid == 0) {
        float r = (lane < 8) ? red[lane] : 0.f;
        r = warpReduceSum(r);
        if (lane == 0) stats[0] = r;
    }
    __syncthreads();
    float s2 = warpReduceSum(x * x);
    if (lane == 0) red[wid] = s2;
    __syncthreads();
    if (wid == 0) {
        float r = (lane < 8) ? red[lane] : 0.f;
        r = warpReduceSum(r);
        if (lane == 0) stats[1] = r;
    }
    __syncthreads();
    float mean = stats[0] * (1.f / cD);
    float var  = stats[1] * (1.f / cD) - mean * mean;
    float y = (x - mean) * rsqrtf(var + LN_EPS) * g[tid] + bta[tid];
    if (mask[n]) y = 0.f;
    out[n * cD + tid] = y;
    if (oh) oh[n * cD + tid] = __float2half_rn(y);
}

// ---------------- fp32 -> fp16 single ----------------
__global__ void __launch_bounds__(256) cvt_half(const float* __restrict__ in,
                                                __half* __restrict__ o, long n)
{
    long i = ((long)blockIdx.x * 256 + threadIdx.x) * 4;
    if (i >= n) return;
    float4 v = *reinterpret_cast<const float4*>(in + i);
    __half2 a = {__float2half_rn(v.x), __float2half_rn(v.y)};
    __half2 b = {__float2half_rn(v.z), __float2half_rn(v.w)};
    *reinterpret_cast<__half2*>(o + i)     = a;
    *reinterpret_cast<__half2*>(o + i + 2) = b;
}

// ---------------- fp32 -> fp16 hi/lo split ----------------
__global__ void __launch_bounds__(256) cvt_split_h(const float* __restrict__ in,
                                                   __half* __restrict__ oh,
                                                   __half* __restrict__ ol, long n)
{
    long i = ((long)blockIdx.x * 256 + threadIdx.x) * 4;
    if (i >= n) return;
    float4 v = *reinterpret_cast<const float4*>(in + i);
    __half h0, h1, h2, h3, l0, l1, l2, l3;
    split_h(v.x, h0, l0); split_h(v.y, h1, l1);
    split_h(v.z, h2, l2); split_h(v.w, h3, l3);
    __half2 ha = {h0, h1}, hb = {h2, h3}, la = {l0, l1}, lb = {l2, l3};
    *reinterpret_cast<__half2*>(oh + i)     = ha;
    *reinterpret_cast<__half2*>(oh + i + 2) = hb;
    *reinterpret_cast<__half2*>(ol + i)     = la;
    *reinterpret_cast<__half2*>(ol + i + 2) = lb;
}

// ---------------- kv cols 128..255 -> vT [(b,h)][n][t] split, rows 64..127 zeroed ----------------
__global__ void __launch_bounds__(256) vT_k(const __half* __restrict__ kvh,
                                            const __half* __restrict__ kvl,
                                            __half* __restrict__ vTh,
                                            __half* __restrict__ vTl)
{
    __shared__ __half th[32][33], tl[32][33];
    int b = blockIdx.z;
    int t0 = blockIdx.x * 32, c0 = blockIdx.y * 32;
    int tx = threadIdx.x & 31, ty = threadIdx.x >> 5;  // 32 x 8
#pragma unroll
    for (int i = 0; i < 4; i++) {
        int t = t0 + ty + i * 8;
        long src = ((long)b * cT + t) * 256 + 128 + c0 + tx;
        th[ty + i * 8][tx] = kvh[src];
        tl[ty + i * 8][tx] = kvl[src];
    }
    __syncthreads();
#pragma unroll
    for (int i = 0; i < 4; i++) {
        int c = c0 + ty + i * 8;
        int h = c >> 6, n = c & 63;
        long base = ((long)((b << 1) | h) * 128 + n) * cT + t0 + tx;
        vTh[base] = th[tx][ty + i * 8];
        vTl[base] = tl[tx][ty + i * 8];
        vTh[base + (long)64 * cT] = __float2half_rn(0.f);
        vTl[base + (long)64 * cT] = __float2half_rn(0.f);
    }
}

// ---------------- p_w transpose to fp16: in[b][c][o] -> out[b][o][c] ----------------
__global__ void __launch_bounds__(256) cvtT_k(const float* __restrict__ in,
                                              __half* __restrict__ oT)
{
    __shared__ float tile[32][33];
    int b = blockIdx.z;
    int o0 = blockIdx.x * 32, c0 = blockIdx.y * 32;
    int tx = threadIdx.x & 31, ty = threadIdx.x >> 5;  // 32 x 8
    const float* src = in + (long)b * cC * cC;
#pragma unroll
    for (int i = 0; i < 4; i++) {
        int c = c0 + ty + i * 8;
        tile[ty + i * 8][tx] = src[(long)c * cC + o0 + tx];
    }
    __syncthreads();
    __half* dst = oT + (long)b * cC * cC;
#pragma unroll
    for (int i = 0; i < 4; i++) {
        int o = o0 + ty + i * 8;
        dst[(long)o * cC + c0 + tx] = __float2half_rn(tile[tx][ty + i * 8]);
    }
}

// ---------------- depthwise weight inverse norms ----------------
__global__ void __launch_bounds__(128) dwn_k(const float* __restrict__ d_w, float* __restrict__ dwn)
{
    int k = blockIdx.x, b = blockIdx.y;
    int tid = threadIdx.x;
    float s = 0.f;
    for (int c = tid; c < cC; c += 128) {
        float w = d_w[((long)b * cC + c) * 9 + k];
        s += w * w;
    }
    __shared__ float red[4];
    s = warpReduceSum(s);
    if ((tid & 31) == 0) red[tid >> 5] = s;
    __syncthreads();
    if (tid == 0) {
        float r = red[0] + red[1] + red[2] + red[3];
        dwn[b * 9 + k] = 1.f / fmaxf(sqrtf(r), 1e-12f);
    }
}

__global__ void __launch_bounds__(256) pwn_k(const float* __restrict__ p_w, float* __restrict__ pwn)
{
    int c1 = blockIdx.x * 256 + threadIdx.x;
    int b = blockIdx.y;
    const float* base = p_w + (long)b * cC * cC + c1;
    float s = 0.f;
    for (int c2 = 0; c2 < cC; c2++) {
        float w = base[(long)c2 * cC];
        s += w * w;
    }
    pwn[b * cC + c1] = 1.f / fmaxf(sqrtf(s), 1e-12f);
}

// ---------------- tiled depthwise conv (K=9): fp16 in, fp16 out ----------------
constexpr int CV_TR = 32;   // output t-rows per block
__global__ void __launch_bounds__(256) conv2_k(const __half* __restrict__ h,
                                               const float* __restrict__ d_w,
                                               const float* __restrict__ d_g,
                                               const float* __restrict__ d_b,
                                               const float* __restrict__ p_g,
                                               const float* __restrict__ dwn,
                                               __half* __restrict__ deph)
{
    __shared__ __half hs[CV_TR + 8][256];
    __shared__ float ws[9];
    int t0 = blockIdx.x * CV_TR, c0 = blockIdx.y * 256, b = blockIdx.z;
    int tid = threadIdx.x;
    if (tid < 9) ws[tid] = dwn[b * 9 + tid];
    __syncthreads();

    // load halo tile: rows t0-4 .. t0+CV_TR+3 (zero outside); 8 halves per uint4
#pragma unroll
    for (int i = tid; i < (CV_TR + 8) * 32; i += 256) {
        int r = i >> 5, q8 = i & 31;
        int t = t0 + r - 4;
        uint4 v = make_uint4(0u, 0u, 0u, 0u);
        if (t >= 0 && t < cT)
            v = *reinterpret_cast<const uint4*>(h + ((long)b * cT + t) * cC + c0 + q8 * 8);
        *reinterpret_cast<uint4*>(&hs[r][q8 * 8]) = v;
    }

    int c = c0 + tid;
    long bc = (long)b * cC + c;
    const float* wrow = d_w + bc * 9;
    float w[9];
#pragma unroll
    for (int k = 0; k < 9; k++) w[k] = wrow[k] * ws[k];
    float dg = d_g[bc], db = d_b[bc], pg = p_g[bc];
    __syncthreads();

#pragma unroll 4
    for (int tt = 0; tt < CV_TR; tt++) {
        float acc = 0.f;
#pragma unroll
        for (int k = 0; k < 9; k++) acc += __half2float(hs[tt + k][tid]) * w[k];
        float val = (acc * dg + db) * pg;
        deph[((long)b * cT + t0 + tt) * cC + c] = __float2half_rn(val);
    }
}

// ---------------- launch ----------------
extern "C" void kernel_launch(void* const* d_in, const int* in_sizes, int n_in,
                              void* d_out, int out_size)
{
    const float* x    = (const float*)d_in[0];
    const float* d_w  = (const float*)d_in[1];
    const float* d_g  = (const float*)d_in[2];
    const float* d_b  = (const float*)d_in[3];
    const float* p_w  = (const float*)d_in[4];
    const float* p_g  = (const float*)d_in[5];
    const float* p_b  = (const float*)d_in[6];
    const unsigned char* mask  = (const unsigned char*)d_in[7];
    const unsigned char* smask = (const unsigned char*)d_in[8];
    const float* Wq = (const float*)d_in[9];
    const float* bq = (const float*)d_in[10];
    const float* Wk = (const float*)d_in[11];
    const float* bk = (const float*)d_in[12];
    const float* Wv = (const float*)d_in[13];
    const float* bv = (const float*)d_in[14];
    const float* Wo = (const float*)d_in[15];
    const float* bo = (const float*)d_in[16];
    const float* g0 = (const float*)d_in[17];
    const float* b0 = (const float*)d_in[18];
    const float* w1_w = (const float*)d_in[19];
    const float* w1_b = (const float*)d_in[20];
    const float* w2_w = (const float*)d_in[21];
    const float* w2_b = (const float*)d_in[22];
    const float* g1 = (const float*)d_in[23];
    const float* b1 = (const float*)d_in[24];

    float* out  = (float*)d_out;
    float* attn = out + (long)cNT * cD;   // output tuple: (out[B,T,D], attn[B,H,T,T])

    float *apre, *a, *o2, *dwn, *pwn, *bkv;
    __half *xh, *xl, *qh, *ql, *kvh, *kvl, *vTh, *vTl, *atth, *attl, *ctxh, *ctxl;
    __half *ah, *hh, *deph, *pth, *pwT, *w1h, *w2h;
    __half *wqh, *wql, *wkvh, *wkvl, *woh, *wol;
    cudaGetSymbolAddress((void**)&apre, g_apre);
    cudaGetSymbolAddress((void**)&a,    g_a);
    cudaGetSymbolAddress((void**)&o2,   g_o2);
    cudaGetSymbolAddress((void**)&dwn,  g_dwn);
    cudaGetSymbolAddress((void**)&pwn,  g_pwn);
    cudaGetSymbolAddress((void**)&bkv,  g_bkv);
    cudaGetSymbolAddress((void**)&xh,   g_xh);
    cudaGetSymbolAddress((void**)&xl,   g_xl);
    cudaGetSymbolAddress((void**)&qh,   g_qh);
    cudaGetSymbolAddress((void**)&ql,   g_ql);
    cudaGetSymbolAddress((void**)&kvh,  g_kvh);
    cudaGetSymbolAddress((void**)&kvl,  g_kvl);
    cudaGetSymbolAddress((void**)&vTh,  g_vTh);
    cudaGetSymbolAddress((void**)&vTl,  g_vTl);
    cudaGetSymbolAddress((void**)&atth, g_atth);
    cudaGetSymbolAddress((void**)&attl, g_attl);
    cudaGetSymbolAddress((void**)&ctxh, g_ctxh);
    cudaGetSymbolAddress((void**)&ctxl, g_ctxl);
    cudaGetSymbolAddress((void**)&ah,   g_ah);
    cudaGetSymbolAddress((void**)&hh,   g_hh);
    cudaGetSymbolAddress((void**)&deph, g_deph);
    cudaGetSymbolAddress((void**)&pth,  g_pth);
    cudaGetSymbolAddress((void**)&pwT,  g_pwT);
    cudaGetSymbolAddress((void**)&w1h,  g_w1);
    cudaGetSymbolAddress((void**)&w2h,  g_w2);
    cudaGetSymbolAddress((void**)&wqh,  g_wq);
    cudaGetSymbolAddress((void**)&wql,  g_wql);
    cudaGetSymbolAddress((void**)&wkvh, g_wkv);
    cudaGetSymbolAddress((void**)&wkvl, g_wkvl);
    cudaGetSymbolAddress((void**)&woh,  g_wo);
    cudaGetSymbolAddress((void**)&wol,  g_wol);

    cudaFuncSetAttribute(mma_gemm1<2>,  cudaFuncAttributeMaxDynamicSharedMemorySize, MM_SMEM1);
    cudaFuncSetAttribute(mma_gemm1<9>,  cudaFuncAttributeMaxDynamicSharedMemorySize, MM_SMEM1);
    cudaFuncSetAttribute(mma_gemm1<10>, cudaFuncAttributeMaxDynamicSharedMemorySize, MM_SMEM1);
    cudaFuncSetAttribute(mma_gemm3<2>, cudaFuncAttributeMaxDynamicSharedMemorySize, MM_SMEM3);
    cudaFuncSetAttribute(mma_gemm3<5>, cudaFuncAttributeMaxDynamicSharedMemorySize, MM_SMEM3);
    cudaFuncSetAttribute(mma_gemm3<6>, cudaFuncAttributeMaxDynamicSharedMemorySize, MM_SMEM3);
    cudaFuncSetAttribute(mma_gemm3<8>, cudaFuncAttributeMaxDynamicSharedMemorySize, MM_SMEM3);

    dim3 blk(256);

    // 0) prep: weight conversions (projections split for 3-product), norms, x split
    cvt_split_h<<<(128 * cD) / 1024, blk>>>(Wq, wqh, wql, (long)128 * cD);
    cvt_split_h<<<(128 * cD) / 1024, blk>>>(Wk, wkvh, wkvl, (long)128 * cD);
    cvt_split_h<<<(128 * cD) / 1024, blk>>>(Wv, wkvh + 128 * cD, wkvl + 128 * cD, (long)128 * cD);
    cvt_split_h<<<(cD * 128) / 1024, blk>>>(Wo, woh, wol, (long)cD * 128);
    cvt_half<<<(cC * cD) / 1024, blk>>>(w1_w, w1h, (long)cC * cD);
    cvt_half<<<(cD * cC) / 1024, blk>>>(w2_w, w2h, (long)cD * cC);
    cudaMemcpyAsync(bkv,       bk, 128 * sizeof(float), cudaMemcpyDeviceToDevice);
    cudaMemcpyAsync(bkv + 128, bv, 128 * sizeof(float), cudaMemcpyDeviceToDevice);
    cvtT_k<<<dim3(32, 32, cB), blk>>>(p_w, pwT);
    dwn_k<<<dim3(9, cB), 128>>>(d_w, dwn);
    pwn_k<<<dim3(4, cB), blk>>>(p_w, pwn);
    cvt_split_h<<<(cNT * cD) / 1024, blk>>>(x, xh, xl, (long)cNT * cD);

    // 1) q (split out, 3-product): [16384,256] @ [128,256]^T
    mma_gemm3<6><<<dim3(1, cNT / 128, 1), blk, MM_SMEM3>>>(
        xh, xl, wqh, wql, nullptr, qh, ql, cD, cD, cD, 128, 128, 1,
        0, 0, 0, 0, 0, 0, 0, 0, bq, nullptr);
    // 2) kv fused (split out, 3-product): [16384,256] @ [256,256]^T
    mma_gemm3<6><<<dim3(2, cNT / 128, 1), blk, MM_SMEM3>>>(
        xh, xl, wkvh, wkvl, nullptr, kvh, kvl, cD, cD, cD, 256, 256, 1,
        0, 0, 0, 0, 0, 0, 0, 0, bkv, nullptr);

    // 3) v -> vT split (padded 128 rows per (b,h))
    vT_k<<<dim3(32, 4, cB), blk>>>(kvh, kvl, vTh, vTl);

    // 4) scores = q k^T / 8  [3-product, z=(b,h) zdiv=2]
    mma_gemm3<5><<<dim3(8, 8, 32), blk, MM_SMEM3>>>(
        qh, ql, kvh, kvl, attn, nullptr, nullptr, cDK, 128, 256, cT, 1024, 2,
        (long)cT * 128, 64, (long)cT * 256, 64, 2 * cTT, cTT, 0, 0, nullptr, nullptr);

    // 5) masked softmax (writes final attn + fp16 split)
    softmax_k<<<dim3(cT, cH, cB), blk>>>(attn, smask, atth, attl);

    // 6) ctx = attn @ v  [3-product] -> fp16 split, col guard 64
    mma_gemm3<8><<<dim3(1, 8, 32), blk, MM_SMEM3>>>(
        atth, attl, vTh, vTl, nullptr, ctxh, ctxl, cT, cT, cT, 128, 64, 2,
        2 * cTT, cTT, (long)256 * cT, (long)128 * cT, (long)cT * 128, 64,
        0, 0, nullptr, nullptr);

    // 7) apre = ctx @ Wo^T + bo + x  [3-product]
    mma_gemm3<2><<<dim3(2, cNT / 128, 1), blk, MM_SMEM3>>>(
        ctxh, ctxl, woh, wol, apre, nullptr, nullptr, 128, 128, 128, cD, 256, 1,
        0, 0, 0, 0, 0, 0, 0, 0, bo, x);

    // 8) a = LN(apre), masked; emit fp16 single
    ln_k<<<cNT, blk>>>(apre, g0, b0, mask, a, ah);

    // 9) h = mish(a @ w1^T + w1_b) -> fp16 single  [1-product]
    mma_gemm1<9><<<dim3(cC / 128, cNT / 128, 1), blk, MM_SMEM1>>>(
        ah, w1h, nullptr, hh, cD, cD, cD, cC, 1024, 1,
        0, 0, 0, 0, 0, 0, 0, 0, w1_b, nullptr);

    // 10) tiled depthwise conv (fp16 in/out)
    conv2_k<<<dim3(cT / CV_TR, cC / 256, cB), blk>>>(hh, d_w, d_g, d_b, p_g, dwn, deph);

    // 11) pt = (dep @ pwT) * pwninv[o] + p_b -> fp16 single  [1-product, batched over b]
    mma_gemm1<10><<<dim3(cC / 128, cT / 128, cB), blk, MM_SMEM1>>>(
        deph, pwT, nullptr, pth, cC, cC, cC, cC, 1024, 1,
        (long)cT * cC, 0, (long)cC * cC, 0, (long)cT * cC, 0, cC, cC, p_b, pwn);

    // 12) o2 = pt @ w2^T + w2_b + a  [1-product]
    mma_gemm1<2><<<dim3(cD / 128, cNT / 128, 1), blk, MM_SMEM1>>>(
        pth, w2h, o2, nullptr, cC, cC, cC, cD, 256, 1,
        0, 0, 0, 0, 0, 0, 0, 0, w2_b, a);

    // 13) out = LN(o2), masked
    ln_k<<<cNT, blk>>>(o2, g1, b1, mask, out, nullptr);
}

// round 10
// speedup vs baseline: 3.2788x; 1.0702x over previous
#include <cuda_runtime.h>
#include <cuda_fp16.h>
#include <cstdint>
#include <math.h>

// ---------------- problem constants ----------------
constexpr int cB = 16, cT = 1024, cD = 256, cH = 2, cDK = 64, cC = 1024;
constexpr int cNT = cB * cT;            // 16384 tokens
constexpr long cTT = (long)cT * cT;     // 1M
constexpr float LN_EPS = 1e-5f;

// ---------------- device scratch (no allocs allowed) ----------------
__device__ float g_apre[cNT * cD];
__device__ float g_a   [cNT * cD];
__device__ float g_o2 [cNT * cD];
__device__ float g_dwn[cB * 9];
__device__ float g_pwn[cB * cC];
__device__ float g_bkv[256];
// fp16 buffers
__device__ __half g_xh  [cNT * cD];
__device__ __half g_xl  [cNT * cD];
__device__ __half g_qh  [cNT * 128];
__device__ __half g_ql  [cNT * 128];
__device__ __half g_kvh [cNT * 256];
__device__ __half g_kvl [cNT * 256];
__device__ __half g_vTh [(long)cB * cH * 128 * cT];   // padded to 128 rows per (b,h)
__device__ __half g_vTl [(long)cB * cH * 128 * cT];
__device__ __half g_atth[(long)cB * cH * cTT];
__device__ __half g_attl[(long)cB * cH * cTT];
__device__ __half g_ctxh[cNT * 128];
__device__ __half g_ctxl[cNT * 128];
__device__ __half g_ah  [cNT * cD];
__device__ __half g_hh  [cNT * cC];
__device__ __half g_deph[cNT * cC];
__device__ __half g_pth [cNT * cC];
__device__ __half g_pwT [(long)cB * cC * cC];
__device__ __half g_w1  [cC * cD];
__device__ __half g_w2  [cD * cC];
__device__ __half g_wq  [128 * cD];
__device__ __half g_wql [128 * cD];
__device__ __half g_wkv [256 * cD];
__device__ __half g_wkvl[256 * cD];
__device__ __half g_wo  [cD * 128];
__device__ __half g_wol [cD * 128];

// ---------------- helpers ----------------
__device__ __forceinline__ uint32_t smem_u32(const void* p) {
    uint32_t a;
    asm("{ .reg .u64 t; cvta.to.shared.u64 t, %1; cvt.u32.u64 %0, t; }" : "=r"(a) : "l"(p));
    return a;
}
#define SW128(off) ((off) ^ (((off) >> 3) & 0x70))

__device__ __forceinline__ void split_h(float v, __half& h, __half& l) {
    h = __float2half_rn(v);
    l = __float2half_rn(v - __half2float(h));
}

__device__ __forceinline__ void ldsm4(uint32_t* r, uint32_t addr) {
    asm volatile("ldmatrix.sync.aligned.m8n8.x4.shared.b16 {%0,%1,%2,%3}, [%4];"
        : "=r"(r[0]), "=r"(r[1]), "=r"(r[2]), "=r"(r[3]) : "r"(addr));
}
__device__ __forceinline__ void mma16816(float* d, const uint32_t* a, const uint32_t* b) {
    asm volatile("mma.sync.aligned.m16n8k16.row.col.f32.f16.f16.f32 "
        "{%0,%1,%2,%3}, {%4,%5,%6,%7}, {%8,%9}, {%0,%1,%2,%3};"
        : "+f"(d[0]), "+f"(d[1]), "+f"(d[2]), "+f"(d[3])
        : "r"(a[0]), "r"(a[1]), "r"(a[2]), "r"(a[3]), "r"(b[0]), "r"(b[1]));
}
__device__ __forceinline__ void cp16(uint32_t saddr, const void* gptr) {
    asm volatile("cp.async.cg.shared.global [%0], [%1], 16;"
        :: "r"(saddr), "l"(__cvta_generic_to_global(gptr)));
}
__device__ __forceinline__ void cp_commit() {
    asm volatile("cp.async.commit_group;");
}
template<int N>
__device__ __forceinline__ void cp_wait() {
    asm volatile("cp.async.wait_group %0;" :: "n"(N));
}

__device__ __forceinline__ float warpReduceSum(float v) {
#pragma unroll
    for (int o = 16; o > 0; o >>= 1) v += __shfl_xor_sync(0xffffffffu, v, o);
    return v;
}
__device__ __forceinline__ float warpReduceMax(float v) {
#pragma unroll
    for (int o = 16; o > 0; o >>= 1) v = fmaxf(v, __shfl_xor_sync(0xffffffffu, v, o));
    return v;
}

// ---------------- mma.sync fp16 GEMM body ----------------
// D[M,N] = A[M,K] @ B[N,K]^T.
// NPROD=1: A,B single fp16 (3-stage pipeline).  NPROD=3: A and B split (2-stage).
// EPI: 2 = +bias[n]+aux residual -> f32 | 5 = acc*0.125 -> f32
//      6 = +bias -> fp16 split | 8 = raw -> fp16 split
//      9 = mish(acc+bias) -> fp16 single | 10 = acc*aux[n]+bias[n] -> fp16 single
constexpr int MM_SMEM1 = 3 * 32768 + 1024;
constexpr int MM_SMEM3 = 2 * 65536 + 1024;

template<int EPI, int NPROD>
__device__ __forceinline__ void mma_body(
    const __half* __restrict__ Ah, const __half* __restrict__ Al,
    const __half* __restrict__ Bh, const __half* __restrict__ Bl,
    float* __restrict__ C, __half* __restrict__ Ch, __half* __restrict__ Cl,
    int Kd, int lda, int ldb, int ldc, int nLim, int zdiv,
    long aQ, long aR, long bQ, long bR, long cQ, long cR,
    long biasZ, long auxZ,
    const float* __restrict__ bias, const float* __restrict__ aux)
{
    constexpr int STAGE = (NPROD == 3) ? 65536 : 32768;
    constexpr int BOFF  = (NPROD == 1) ? 16384 : 32768;
    constexpr int NSTG  = (NPROD == 1) ? 3 : 2;
    extern __shared__ char sm_raw[];
    uint32_t sb0 = smem_u32(sm_raw);
    uint32_t sb  = (sb0 + 1023u) & ~1023u;

    int z = blockIdx.z;
    int zq = z / zdiv, zr = z - zq * zdiv;
    long aoff = (long)zq * aQ + (long)zr * aR;
    long boff = (long)zq * bQ + (long)zr * bR;
    long coff = (long)zq * cQ + (long)zr * cR;
    Ah += aoff;
    if (NPROD >= 2) Al += aoff;
    Bh += boff;
    if (NPROD == 3) Bl += boff;
    if (C)  C  += coff;
    if (Ch) Ch += coff;
    if (Cl) Cl += coff;
    const float* biasp = bias ? bias + (long)zq * biasZ : nullptr;
    const float* auxp  = aux  ? aux  + (long)zq * auxZ  : nullptr;

    int m0 = blockIdx.y * 128, n0 = blockIdx.x * 128;
    int tid = threadIdx.x, wid = tid >> 5, lane = tid & 31;
    int wm = wid & 3, wn = wid >> 2;

    int lrow = tid >> 3, lcq = tid & 7;

    auto issue_stage = [&](int k0, uint32_t sbase) {
#pragma unroll
        for (int ti = 0; ti < 4; ti++) {
            int row = lrow + ti * 32;
            uint32_t soff = SW128((uint32_t)(row * 128 + lcq * 16));
            long ga = (long)(m0 + row) * lda + k0 + lcq * 8;
            long gb = (long)(n0 + row) * ldb + k0 + lcq * 8;
            cp16(sbase + soff, Ah + ga);
            if (NPROD >= 2) cp16(sbase + 16384 + soff, Al + ga);
            cp16(sbase + BOFF + soff, Bh + gb);
            if (NPROD == 3) cp16(sbase + 49152 + soff, Bl + gb);
        }
        cp_commit();
    };

    float acc[2][8][4];
#pragma unroll
    for (int i = 0; i < 2; i++)
#pragma unroll
        for (int j = 0; j < 8; j++)
#pragma unroll
            for (int l = 0; l < 4; l++) acc[i][j][l] = 0.f;

    int nk = Kd >> 6;
#pragma unroll
    for (int s = 0; s < NSTG - 1; s++)
        if (s < nk) issue_stage(s << 6, sb + (uint32_t)s * STAGE);

    for (int i = 0; i < nk; i++) {
        uint32_t cur = sb + (uint32_t)(i % NSTG) * STAGE;
        int j = i + NSTG - 1;
        if (j < nk) issue_stage(j << 6, sb + (uint32_t)(j % NSTG) * STAGE);
        int rem = nk - 1 - i;
        if (NSTG == 3) {
            if (rem >= 2) cp_wait<2>();
            else if (rem == 1) cp_wait<1>();
            else cp_wait<0>();
        } else {
            if (rem >= 1) cp_wait<1>();
            else cp_wait<0>();
        }
        __syncthreads();

        uint32_t uAh = cur, uAl = cur + 16384, uBh = cur + BOFF, uBl = cur + 49152;
#pragma unroll
        for (int ks = 0; ks < 4; ks++) {
            uint32_t afh[2][4], afl[2][4], bfh[4][4], bfl[4][4];
#pragma unroll
            for (int mt = 0; mt < 2; mt++) {
                int r = wm * 32 + mt * 16 + (lane & 15);
                int kc = ks * 2 + (lane >> 4);
                uint32_t off = SW128((uint32_t)(r * 128 + kc * 16));
                ldsm4(afh[mt], uAh + off);
                if (NPROD >= 2) ldsm4(afl[mt], uAl + off);
            }
#pragma unroll
            for (int bt = 0; bt < 4; bt++) {
                int r = wn * 64 + bt * 16 + (lane & 7) + ((lane >> 4) << 3);
                int kc = ks * 2 + ((lane >> 3) & 1);
                uint32_t off = SW128((uint32_t)(r * 128 + kc * 16));
                ldsm4(bfh[bt], uBh + off);
                if (NPROD == 3) ldsm4(bfl[bt], uBl + off);
            }
#pragma unroll
            for (int p = 0; p < NPROD; p++)
#pragma unroll
                for (int mt = 0; mt < 2; mt++)
#pragma unroll
                    for (int bt = 0; bt < 4; bt++)
#pragma unroll
                        for (int hh = 0; hh < 2; hh++) {
                            const uint32_t* af  = (p == 1) ? afl[mt] : afh[mt];
                            const uint32_t* bfp = (p == 2) ? &bfl[bt][hh * 2] : &bfh[bt][hh * 2];
                            mma16816(acc[mt][bt * 2 + hh], af, bfp);
                        }
        }
        __syncthreads();
    }

    // epilogue
#pragma unroll
    for (int mt = 0; mt < 2; mt++)
#pragma unroll
        for (int bt = 0; bt < 4; bt++)
#pragma unroll
            for (int hh = 0; hh < 2; hh++) {
                float* d = acc[mt][bt * 2 + hh];
                int col = n0 + wn * 64 + bt * 16 + hh * 8 + (lane & 3) * 2;
                int r0  = m0 + wm * 32 + mt * 16 + (lane >> 2);
                if (col >= nLim) continue;
#pragma unroll
                for (int half = 0; half < 2; half++) {
                    int row = r0 + half * 8;
                    float t0 = d[half * 2 + 0], t1 = d[half * 2 + 1];
                    if (EPI == 2) {
                        t0 += biasp[col]     + auxp[(long)row * ldc + col];
                        t1 += biasp[col + 1] + auxp[(long)row * ldc + col + 1];
                        float2 v = {t0, t1};
                        *reinterpret_cast<float2*>(C + (long)row * ldc + col) = v;
                    } else if (EPI == 5) {
                        float2 v = {t0 * 0.125f, t1 * 0.125f};
                        *reinterpret_cast<float2*>(C + (long)row * ldc + col) = v;
                    } else if (EPI == 9) {
                        t0 += biasp[col];
                        t1 += biasp[col + 1];
                        float sp0 = (t0 > 20.f) ? t0 : log1pf(expf(t0));
                        float sp1 = (t1 > 20.f) ? t1 : log1pf(expf(t1));
                        t0 = t0 * tanhf(sp0);
                        t1 = t1 * tanhf(sp1);
                        __half2 hv = {__float2half_rn(t0), __float2half_rn(t1)};
                        *reinterpret_cast<__half2*>(Ch + (long)row * ldc + col) = hv;
                    } else if (EPI == 10) {
                        t0 = t0 * auxp[col]     + biasp[col];
                        t1 = t1 * auxp[col + 1] + biasp[col + 1];
                        __half2 hv = {__float2half_rn(t0), __float2half_rn(t1)};
                        *reinterpret_cast<__half2*>(Ch + (long)row * ldc + col) = hv;
                    } else { // 6, 8: fp16 split outputs
                        if (EPI == 6) {
                            t0 += biasp[col];
                            t1 += biasp[col + 1];
                        }
                        __half h0, l0, h1, l1;
                        split_h(t0, h0, l0);
                        split_h(t1, h1, l1);
                        __half2 hv = {h0, h1}, lv = {l0, l1};
                        *reinterpret_cast<__half2*>(Ch + (long)row * ldc + col) = hv;
                        *reinterpret_cast<__half2*>(Cl + (long)row * ldc + col) = lv;
                    }
                }
            }
}

template<int EPI>
__global__ void __launch_bounds__(256, 2) mma_gemm1(
    const __half* __restrict__ Ah, const __half* __restrict__ Bh,
    float* __restrict__ C, __half* __restrict__ Ch,
    int Kd, int lda, int ldb, int ldc, int nLim, int zdiv,
    long aQ, long aR, long bQ, long bR, long cQ, long cR,
    long biasZ, long auxZ,
    const float* __restrict__ bias, const float* __restrict__ aux)
{
    mma_body<EPI, 1>(Ah, nullptr, Bh, nullptr, C, Ch, nullptr, Kd, lda, ldb, ldc, nLim, zdiv,
                     aQ, aR, bQ, bR, cQ, cR, biasZ, auxZ, bias, aux);
}

template<int EPI>
__global__ void __launch_bounds__(256) mma_gemm3(
    const __half* __restrict__ Ah, const __half* __restrict__ Al,
    const __half* __restrict__ Bh, const __half* __restrict__ Bl,
    float* __restrict__ C, __half* __restrict__ Ch, __half* __restrict__ Cl,
    int Kd, int lda, int ldb, int ldc, int nLim, int zdiv,
    long aQ, long aR, long bQ, long bR, long cQ, long cR,
    long biasZ, long auxZ,
    const float* __restrict__ bias, const float* __restrict__ aux)
{
    mma_body<EPI, 3>(Ah, Al, Bh, Bl, C, Ch, Cl, Kd, lda, ldb, ldc, nLim, zdiv,
                     aQ, aR, bQ, bR, cQ, cR, biasZ, auxZ, bias, aux);
}

// ---------------- softmax (in place on attn rows; emits fp16 split) ----------------
__global__ void __launch_bounds__(256) softmax_k(float* __restrict__ attn,
                                                 const unsigned char* __restrict__ smask,
                                                 __half* __restrict__ ath,
                                                 __half* __restrict__ atl)
{
    int i = blockIdx.x, h = blockIdx.y, b = blockIdx.z;
    long rbase = (((long)(b * cH + h)) * cT + i) * cT;
    float* row = attn + rbase;
    const unsigned char* mrow = smask + ((long)b * cT + i) * cT;
    int tid = threadIdx.x, lane = tid & 31, wid = tid >> 5;
    __shared__ float red[8];
    __shared__ float bc;

    float v[4];
    float mx = -3.4e38f;
#pragma unroll
    for (int r = 0; r < 4; r++) {
        int j = tid + r * 256;
        float s = row[j];
        if (mrow[j]) s = -1e9f;
        v[r] = s;
        mx = fmaxf(mx, s);
    }
    mx = warpReduceMax(mx);
    if (lane == 0) red[wid] = mx;
    __syncthreads();
    if (wid == 0) {
        float r = (lane < 8) ? red[lane] : -3.4e38f;
        r = warpReduceMax(r);
        if (lane == 0) bc = r;
    }
    __syncthreads();
    mx = bc;
    float sum = 0.f;
#pragma unroll
    for (int r = 0; r < 4; r++) { v[r] = expf(v[r] - mx); sum += v[r]; }
    __syncthreads();
    sum = warpReduceSum(sum);
    if (lane == 0) red[wid] = sum;
    __syncthreads();
    if (wid == 0) {
        float r = (lane < 8) ? red[lane] : 0.f;
        r = warpReduceSum(r);
        if (lane == 0) bc = r;
    }
    __syncthreads();
    float inv = 1.f / bc;
#pragma unroll
    for (int r = 0; r < 4; r++) {
        int j = tid + r * 256;
        float y = v[r] * inv;
        row[j] = y;
        __half hh, ll;
        split_h(y, hh, ll);
        ath[rbase + j] = hh;
        atl[rbase + j] = ll;
    }
}

// ---------------- LayerNorm over D=256; optional fp16 output ----------------
__global__ void __launch_bounds__(256) ln_k(const float* __restrict__ in,
                                            const float* __restrict__ g,
                                            const float* __restrict__ bta,
                                            const unsigned char* __restrict__ mask,
                                            float* __restrict__ out,
                                            __half* __restrict__ oh)
{
    long n = blockIdx.x;
    int tid = threadIdx.x, lane = tid & 31, wid = tid >> 5;
    __shared__ float red[8];
    __shared__ float stats[2];

    float x = in[n * cD + tid];
    float s = warpReduceSum(x);
    if (lane == 0) red[wid] = s;
    __syncthreads();
    if (wid == 0) {
        float r = (lane < 8) ? red[lane] : 0.f;
        r = warpReduceSum(r);
        if (lane == 0) stats[0] = r;
    }
    __syncthreads();
    float s2 = warpReduceSum(x * x);
    if (lane == 0) red[wid] = s2;
    __syncthreads();
    if (wid == 0) {
        float r = (lane < 8) ? red[lane] : 0.f;
        r = warpReduceSum(r);
        if (lane == 0) stats[1] = r;
    }
    __syncthreads();
    float mean = stats[0] * (1.f / cD);
    float var  = stats[1] * (1.f / cD) - mean * mean;
    float y = (x - mean) * rsqrtf(var + LN_EPS) * g[tid] + bta[tid];
    if (mask[n]) y = 0.f;
    out[n * cD + tid] = y;
    if (oh) oh[n * cD + tid] = __float2half_rn(y);
}

// ---------------- fused small weight prep (one launch) ----------------
// tasks (blockIdx.y): 0 Wq split, 1 Wk split, 2 Wv split, 3 Wo split,
//                     4 w1 cvt, 5 w2 cvt, 6 bkv pack
__device__ __forceinline__ void split4_at(const float* in, __half* oh, __half* ol, long i) {
    float4 v = *reinterpret_cast<const float4*>(in + i);
    __half h0, h1, h2, h3, l0, l1, l2, l3;
    split_h(v.x, h0, l0); split_h(v.y, h1, l1);
    split_h(v.z, h2, l2); split_h(v.w, h3, l3);
    __half2 ha = {h0, h1}, hb = {h2, h3}, la = {l0, l1}, lb = {l2, l3};
    *reinterpret_cast<__half2*>(oh + i)     = ha;
    *reinterpret_cast<__half2*>(oh + i + 2) = hb;
    *reinterpret_cast<__half2*>(ol + i)     = la;
    *reinterpret_cast<__half2*>(ol + i + 2) = lb;
}
__device__ __forceinline__ void cvt4_at(const float* in, __half* o, long i) {
    float4 v = *reinterpret_cast<const float4*>(in + i);
    __half2 a = {__float2half_rn(v.x), __float2half_rn(v.y)};
    __half2 b = {__float2half_rn(v.z), __float2half_rn(v.w)};
    *reinterpret_cast<__half2*>(o + i)     = a;
    *reinterpret_cast<__half2*>(o + i + 2) = b;
}

__global__ void __launch_bounds__(256) wprep_k(
    const float* __restrict__ Wq, const float* __restrict__ Wk,
    const float* __restrict__ Wv, const float* __restrict__ Wo,
    const float* __restrict__ w1, const float* __restrict__ w2,
    const float* __restrict__ bk, const float* __restrict__ bv,
    __half* __restrict__ wqh, __half* __restrict__ wql,
    __half* __restrict__ wkvh, __half* __restrict__ wkvl,
    __half* __restrict__ woh, __half* __restrict__ wol,
    __half* __restrict__ w1h, __half* __restrict__ w2h,
    float* __restrict__ bkv)
{
    int task = blockIdx.y;
    long i = ((long)blockIdx.x * 256 + threadIdx.x) * 4;
    constexpr long SZp = (long)128 * cD;  // 32768
    constexpr long SZw = (long)cC * cD;   // 262144
    if (task == 0) { if (i < SZp) split4_at(Wq, wqh, wql, i); }
    else if (task == 1) { if (i < SZp) split4_at(Wk, wkvh, wkvl, i); }
    else if (task == 2) { if (i < SZp) split4_at(Wv, wkvh + SZp, wkvl + SZp, i); }
    else if (task == 3) { if (i < SZp) split4_at(Wo, woh, wol, i); }
    else if (task == 4) { if (i < SZw) cvt4_at(w1, w1h, i); }
    else if (task == 5) { if (i < SZw) cvt4_at(w2, w2h, i); }
    else {
        long t = (long)blockIdx.x * 256 + threadIdx.x;
        if (t < 128) bkv[t] = bk[t];
        else if (t < 256) bkv[t] = bv[t - 128];
    }
}

// ---------------- fp32 -> fp16 hi/lo split (x) ----------------
__global__ void __launch_bounds__(256) cvt_split_h(const float* __restrict__ in,
                                                   __half* __restrict__ oh,
                                                   __half* __restrict__ ol, long n)
{
    long i = ((long)blockIdx.x * 256 + threadIdx.x) * 4;
    if (i >= n) return;
    split4_at(in, oh, ol, i);
}

// ---------------- kv cols 128..255 -> vT [(b,h)][n][t] split, rows 64..127 zeroed ----------------
__global__ void __launch_bounds__(256) vT_k(const __half* __restrict__ kvh,
                                            const __half* __restrict__ kvl,
                                            __half* __restrict__ vTh,
                                            __half* __restrict__ vTl)
{
    __shared__ __half th[32][33], tl[32][33];
    int b = blockIdx.z;
    int t0 = blockIdx.x * 32, c0 = blockIdx.y * 32;
    int tx = threadIdx.x & 31, ty = threadIdx.x >> 5;  // 32 x 8
#pragma unroll
    for (int i = 0; i < 4; i++) {
        int t = t0 + ty + i * 8;
        long src = ((long)b * cT + t) * 256 + 128 + c0 + tx;
        th[ty + i * 8][tx] = kvh[src];
        tl[ty + i * 8][tx] = kvl[src];
    }
    __syncthreads();
#pragma unroll
    for (int i = 0; i < 4; i++) {
        int c = c0 + ty + i * 8;
        int h = c >> 6, n = c & 63;
        long base = ((long)((b << 1) | h) * 128 + n) * cT + t0 + tx;
        vTh[base] = th[tx][ty + i * 8];
        vTl[base] = tl[tx][ty + i * 8];
        vTh[base + (long)64 * cT] = __float2half_rn(0.f);
        vTl[base + (long)64 * cT] = __float2half_rn(0.f);
    }
}

// ---------------- p_w transpose to fp16: in[b][c][o] -> out[b][o][c] ----------------
__global__ void __launch_bounds__(256) cvtT_k(const float* __restrict__ in,
                                              __half* __restrict__ oT)
{
    __shared__ float tile[32][33];
    int b = blockIdx.z;
    int o0 = blockIdx.x * 32, c0 = blockIdx.y * 32;
    int tx = threadIdx.x & 31, ty = threadIdx.x >> 5;  // 32 x 8
    const float* src = in + (long)b * cC * cC;
#pragma unroll
    for (int i = 0; i < 4; i++) {
        int c = c0 + ty + i * 8;
        tile[ty + i * 8][tx] = src[(long)c * cC + o0 + tx];
    }
    __syncthreads();
    __half* dst = oT + (long)b * cC * cC;
#pragma unroll
    for (int i = 0; i < 4; i++) {
        int o = o0 + ty + i * 8;
        dst[(long)o * cC + c0 + tx] = __float2half_rn(tile[tx][ty + i * 8]);
    }
}

// ---------------- depthwise weight inverse norms ----------------
__global__ void __launch_bounds__(128) dwn_k(const float* __restrict__ d_w, float* __restrict__ dwn)
{
    int k = blockIdx.x, b = blockIdx.y;
    int tid = threadIdx.x;
    float s = 0.f;
    for (int c = tid; c < cC; c += 128) {
        float w = d_w[((long)b * cC + c) * 9 + k];
        s += w * w;
    }
    __shared__ float red[4];
    s = warpReduceSum(s);
    if ((tid & 31) == 0) red[tid >> 5] = s;
    __syncthreads();
    if (tid == 0) {
        float r = red[0] + red[1] + red[2] + red[3];
        dwn[b * 9 + k] = 1.f / fmaxf(sqrtf(r), 1e-12f);
    }
}

__global__ void __launch_bounds__(256) pwn_k(const float* __restrict__ p_w, float* __restrict__ pwn)
{
    int c1 = blockIdx.x * 256 + threadIdx.x;
    int b = blockIdx.y;
    const float* base = p_w + (long)b * cC * cC + c1;
    float s = 0.f;
    for (int c2 = 0; c2 < cC; c2++) {
        float w = base[(long)c2 * cC];
        s += w * w;
    }
    pwn[b * cC + c1] = 1.f / fmaxf(sqrtf(s), 1e-12f);
}

// ---------------- tiled depthwise conv (K=9): fp16 in, fp16 out ----------------
constexpr int CV_TR = 32;   // output t-rows per block
__global__ void __launch_bounds__(256) conv2_k(const __half* __restrict__ h,
                                               const float* __restrict__ d_w,
                                               const float* __restrict__ d_g,
                                               const float* __restrict__ d_b,
                                               const float* __restrict__ p_g,
                                               const float* __restrict__ dwn,
                                               __half* __restrict__ deph)
{
    __shared__ __half hs[CV_TR + 8][256];
    __shared__ float ws[9];
    int t0 = blockIdx.x * CV_TR, c0 = blockIdx.y * 256, b = blockIdx.z;
    int tid = threadIdx.x;
    if (tid < 9) ws[tid] = dwn[b * 9 + tid];
    __syncthreads();

    // load halo tile: rows t0-4 .. t0+CV_TR+3 (zero outside); 8 halves per uint4
#pragma unroll
    for (int i = tid; i < (CV_TR + 8) * 32; i += 256) {
        int r = i >> 5, q8 = i & 31;
        int t = t0 + r - 4;
        uint4 v = make_uint4(0u, 0u, 0u, 0u);
        if (t >= 0 && t < cT)
            v = *reinterpret_cast<const uint4*>(h + ((long)b * cT + t) * cC + c0 + q8 * 8);
        *reinterpret_cast<uint4*>(&hs[r][q8 * 8]) = v;
    }

    int c = c0 + tid;
    long bc = (long)b * cC + c;
    const float* wrow = d_w + bc * 9;
    float w[9];
#pragma unroll
    for (int k = 0; k < 9; k++) w[k] = wrow[k] * ws[k];
    float dg = d_g[bc], db = d_b[bc], pg = p_g[bc];
    __syncthreads();

#pragma unroll 4
    for (int tt = 0; tt < CV_TR; tt++) {
        float acc = 0.f;
#pragma unroll
        for (int k = 0; k < 9; k++) acc += __half2float(hs[tt + k][tid]) * w[k];
        float val = (acc * dg + db) * pg;
        deph[((long)b * cT + t0 + tt) * cC + c] = __float2half_rn(val);
    }
}

// ---------------- launch ----------------
extern "C" void kernel_launch(void* const* d_in, const int* in_sizes, int n_in,
                              void* d_out, int out_size)
{
    const float* x    = (const float*)d_in[0];
    const float* d_w  = (const float*)d_in[1];
    const float* d_g  = (const float*)d_in[2];
    const float* d_b  = (const float*)d_in[3];
    const float* p_w  = (const float*)d_in[4];
    const float* p_g  = (const float*)d_in[5];
    const float* p_b  = (const float*)d_in[6];
    const unsigned char* mask  = (const unsigned char*)d_in[7];
    const unsigned char* smask = (const unsigned char*)d_in[8];
    const float* Wq = (const float*)d_in[9];
    const float* bq = (const float*)d_in[10];
    const float* Wk = (const float*)d_in[11];
    const float* bk = (const float*)d_in[12];
    const float* Wv = (const float*)d_in[13];
    const float* bv = (const float*)d_in[14];
    const float* Wo = (const float*)d_in[15];
    const float* bo = (const float*)d_in[16];
    const float* g0 = (const float*)d_in[17];
    const float* b0 = (const float*)d_in[18];
    const float* w1_w = (const float*)d_in[19];
    const float* w1_b = (const float*)d_in[20];
    const float* w2_w = (const float*)d_in[21];
    const float* w2_b = (const float*)d_in[22];
    const float* g1 = (const float*)d_in[23];
    const float* b1 = (const float*)d_in[24];

    float* out  = (float*)d_out;
    float* attn = out + (long)cNT * cD;   // output tuple: (out[B,T,D], attn[B,H,T,T])

    float *apre, *a, *o2, *dwn, *pwn, *bkv;
    __half *xh, *xl, *qh, *ql, *kvh, *kvl, *vTh, *vTl, *atth, *attl, *ctxh, *ctxl;
    __half *ah, *hh, *deph, *pth, *pwT, *w1h, *w2h;
    __half *wqh, *wql, *wkvh, *wkvl, *woh, *wol;
    cudaGetSymbolAddress((void**)&apre, g_apre);
    cudaGetSymbolAddress((void**)&a,    g_a);
    cudaGetSymbolAddress((void**)&o2,   g_o2);
    cudaGetSymbolAddress((void**)&dwn,  g_dwn);
    cudaGetSymbolAddress((void**)&pwn,  g_pwn);
    cudaGetSymbolAddress((void**)&bkv,  g_bkv);
    cudaGetSymbolAddress((void**)&xh,   g_xh);
    cudaGetSymbolAddress((void**)&xl,   g_xl);
    cudaGetSymbolAddress((void**)&qh,   g_qh);
    cudaGetSymbolAddress((void**)&ql,   g_ql);
    cudaGetSymbolAddress((void**)&kvh,  g_kvh);
    cudaGetSymbolAddress((void**)&kvl,  g_kvl);
    cudaGetSymbolAddress((void**)&vTh,  g_vTh);
    cudaGetSymbolAddress((void**)&vTl,  g_vTl);
    cudaGetSymbolAddress((void**)&atth, g_atth);
    cudaGetSymbolAddress((void**)&attl, g_attl);
    cudaGetSymbolAddress((void**)&ctxh, g_ctxh);
    cudaGetSymbolAddress((void**)&ctxl, g_ctxl);
    cudaGetSymbolAddress((void**)&ah,   g_ah);
    cudaGetSymbolAddress((void**)&hh,   g_hh);
    cudaGetSymbolAddress((void**)&deph, g_deph);
    cudaGetSymbolAddress((void**)&pth,  g_pth);
    cudaGetSymbolAddress((void**)&pwT,  g_pwT);
    cudaGetSymbolAddress((void**)&w1h,  g_w1);
    cudaGetSymbolAddress((void**)&w2h,  g_w2);
    cudaGetSymbolAddress((void**)&wqh,  g_wq);
    cudaGetSymbolAddress((void**)&wql,  g_wql);
    cudaGetSymbolAddress((void**)&wkvh, g_wkv);
    cudaGetSymbolAddress((void**)&wkvl, g_wkvl);
    cudaGetSymbolAddress((void**)&woh,  g_wo);
    cudaGetSymbolAddress((void**)&wol,  g_wol);

    cudaFuncSetAttribute(mma_gemm1<2>,  cudaFuncAttributeMaxDynamicSharedMemorySize, MM_SMEM1);
    cudaFuncSetAttribute(mma_gemm1<9>,  cudaFuncAttributeMaxDynamicSharedMemorySize, MM_SMEM1);
    cudaFuncSetAttribute(mma_gemm1<10>, cudaFuncAttributeMaxDynamicSharedMemorySize, MM_SMEM1);
    cudaFuncSetAttribute(mma_gemm3<2>, cudaFuncAttributeMaxDynamicSharedMemorySize, MM_SMEM3);
    cudaFuncSetAttribute(mma_gemm3<5>, cudaFuncAttributeMaxDynamicSharedMemorySize, MM_SMEM3);
    cudaFuncSetAttribute(mma_gemm3<6>, cudaFuncAttributeMaxDynamicSharedMemorySize, MM_SMEM3);
    cudaFuncSetAttribute(mma_gemm3<8>, cudaFuncAttributeMaxDynamicSharedMemorySize, MM_SMEM3);

    dim3 blk(256);

    // 0) prep: fused small weight conversions (1 launch), pwT transpose, norms, x split
    wprep_k<<<dim3(256, 7), blk>>>(Wq, Wk, Wv, Wo, w1_w, w2_w, bk, bv,
                                   wqh, wql, wkvh, wkvl, woh, wol, w1h, w2h, bkv);
    cvtT_k<<<dim3(32, 32, cB), blk>>>(p_w, pwT);
    dwn_k<<<dim3(9, cB), 128>>>(d_w, dwn);
    pwn_k<<<dim3(4, cB), blk>>>(p_w, pwn);
    cvt_split_h<<<(cNT * cD) / 1024, blk>>>(x, xh, xl, (long)cNT * cD);

    // 1) q (split out, 3-product): [16384,256] @ [128,256]^T
    mma_gemm3<6><<<dim3(1, cNT / 128, 1), blk, MM_SMEM3>>>(
        xh, xl, wqh, wql, nullptr, qh, ql, cD, cD, cD, 128, 128, 1,
        0, 0, 0, 0, 0, 0, 0, 0, bq, nullptr);
    // 2) kv fused (split out, 3-product): [16384,256] @ [256,256]^T
    mma_gemm3<6><<<dim3(2, cNT / 128, 1), blk, MM_SMEM3>>>(
        xh, xl, wkvh, wkvl, nullptr, kvh, kvl, cD, cD, cD, 256, 256, 1,
        0, 0, 0, 0, 0, 0, 0, 0, bkv, nullptr);

    // 3) v -> vT split (padded 128 rows per (b,h))
    vT_k<<<dim3(32, 4, cB), blk>>>(kvh, kvl, vTh, vTl);

    // 4) scores = q k^T / 8  [3-product, z=(b,h) zdiv=2]
    mma_gemm3<5><<<dim3(8, 8, 32), blk, MM_SMEM3>>>(
        qh, ql, kvh, kvl, attn, nullptr, nullptr, cDK, 128, 256, cT, 1024, 2,
        (long)cT * 128, 64, (long)cT * 256, 64, 2 * cTT, cTT, 0, 0, nullptr, nullptr);

    // 5) masked softmax (writes final attn + fp16 split)
    softmax_k<<<dim3(cT, cH, cB), blk>>>(attn, smask, atth, attl);

    // 6) ctx = attn @ v  [3-product] -> fp16 split, col guard 64
    mma_gemm3<8><<<dim3(1, 8, 32), blk, MM_SMEM3>>>(
        atth, attl, vTh, vTl, nullptr, ctxh, ctxl, cT, cT, cT, 128, 64, 2,
        2 * cTT, cTT, (long)256 * cT, (long)128 * cT, (long)cT * 128, 64,
        0, 0, nullptr, nullptr);

    // 7) apre = ctx @ Wo^T + bo + x  [3-product]
    mma_gemm3<2><<<dim3(2, cNT / 128, 1), blk, MM_SMEM3>>>(
        ctxh, ctxl, woh, wol, apre, nullptr, nullptr, 128, 128, 128, cD, 256, 1,
        0, 0, 0, 0, 0, 0, 0, 0, bo, x);

    // 8) a = LN(apre), masked; emit fp16 single
    ln_k<<<cNT, blk>>>(apre, g0, b0, mask, a, ah);

    // 9) h = mish(a @ w1^T + w1_b) -> fp16 single  [1-product, 3-stage, occ 2]
    mma_gemm1<9><<<dim3(cC / 128, cNT / 128, 1), blk, MM_SMEM1>>>(
        ah, w1h, nullptr, hh, cD, cD, cD, cC, 1024, 1,
        0, 0, 0, 0, 0, 0, 0, 0, w1_b, nullptr);

    // 10) tiled depthwise conv (fp16 in/out)
    conv2_k<<<dim3(cT / CV_TR, cC / 256, cB), blk>>>(hh, d_w, d_g, d_b, p_g, dwn, deph);

    // 11) pt = (dep @ pwT) * pwninv[o] + p_b -> fp16 single  [1-product, batched over b]
    mma_gemm1<10><<<dim3(cC / 128, cT / 128, cB), blk, MM_SMEM1>>>(
        deph, pwT, nullptr, pth, cC, cC, cC, cC, 1024, 1,
        (long)cT * cC, 0, (long)cC * cC, 0, (long)cT * cC, 0, cC, cC, p_b, pwn);

    // 12) o2 = pt @ w2^T + w2_b + a  [1-product]
    mma_gemm1<2><<<dim3(cD / 128, cNT / 128, 1), blk, MM_SMEM1>>>(
        pth, w2h, o2, nullptr, cC, cC, cC, cD, 256, 1,
        0, 0, 0, 0, 0, 0, 0, 0, w2_b, a);

    // 13) out = LN(o2), masked
    ln_k<<<cNT, blk>>>(o2, g1, b1, mask, out, nullptr);
}

// round 12
// speedup vs baseline: 3.6940x; 1.1266x over previous
#include <cuda_runtime.h>
#include <cuda_fp16.h>
#include <cstdint>
#include <math.h>

// ---------------- problem constants ----------------
constexpr int cB = 16, cT = 1024, cD = 256, cH = 2, cDK = 64, cC = 1024;
constexpr int cNT = cB * cT;            // 16384 tokens
constexpr long cTT = (long)cT * cT;     // 1M
constexpr float LN_EPS = 1e-5f;

// ---------------- device scratch (no allocs allowed) ----------------
__device__ float g_apre[cNT * cD];
__device__ float g_a   [cNT * cD];
__device__ float g_o2 [cNT * cD];
__device__ float g_dwn[cB * 9];
__device__ float g_pwn[cB * cC];        // first: sum of squares (atomic), then inv-norm in place
__device__ float g_bkv[256];
// fp16 buffers
__device__ __half g_xh  [cNT * cD];
__device__ __half g_xl  [cNT * cD];
__device__ __half g_qh  [cNT * 128];
__device__ __half g_ql  [cNT * 128];
__device__ __half g_kvh [cNT * 256];
__device__ __half g_kvl [cNT * 256];
__device__ __half g_vTh [(long)cB * cH * 128 * cT];
__device__ __half g_vTl [(long)cB * cH * 128 * cT];
__device__ __half g_atth[(long)cB * cH * cTT];
__device__ __half g_attl[(long)cB * cH * cTT];
__device__ __half g_ctxh[cNT * 128];
__device__ __half g_ctxl[cNT * 128];
__device__ __half g_ah  [cNT * cD];
__device__ __half g_hh  [cNT * cC];
__device__ __half g_deph[cNT * cC];
__device__ __half g_pth [cNT * cC];
__device__ __half g_pwT [(long)cB * cC * cC];
__device__ __half g_w1  [cC * cD];
__device__ __half g_w2  [cD * cC];
__device__ __half g_wq  [128 * cD];
__device__ __half g_wql [128 * cD];
__device__ __half g_wkv [256 * cD];
__device__ __half g_wkvl[256 * cD];
__device__ __half g_wo  [cD * 128];
__device__ __half g_wol [cD * 128];

// ---------------- helpers ----------------
__device__ __forceinline__ uint32_t smem_u32(const void* p) {
    uint32_t a;
    asm("{ .reg .u64 t; cvta.to.shared.u64 t, %1; cvt.u32.u64 %0, t; }" : "=r"(a) : "l"(p));
    return a;
}
#define SW128(off) ((off) ^ (((off) >> 3) & 0x70))

__device__ __forceinline__ void split_h(float v, __half& h, __half& l) {
    h = __float2half_rn(v);
    l = __float2half_rn(v - __half2float(h));
}

__device__ __forceinline__ void ldsm4(uint32_t* r, uint32_t addr) {
    asm volatile("ldmatrix.sync.aligned.m8n8.x4.shared.b16 {%0,%1,%2,%3}, [%4];"
        : "=r"(r[0]), "=r"(r[1]), "=r"(r[2]), "=r"(r[3]) : "r"(addr));
}
__device__ __forceinline__ void mma16816(float* d, const uint32_t* a, const uint32_t* b) {
    asm volatile("mma.sync.aligned.m16n8k16.row.col.f32.f16.f16.f32 "
        "{%0,%1,%2,%3}, {%4,%5,%6,%7}, {%8,%9}, {%0,%1,%2,%3};"
        : "+f"(d[0]), "+f"(d[1]), "+f"(d[2]), "+f"(d[3])
        : "r"(a[0]), "r"(a[1]), "r"(a[2]), "r"(a[3]), "r"(b[0]), "r"(b[1]));
}
__device__ __forceinline__ void cp16(uint32_t saddr, const void* gptr) {
    asm volatile("cp.async.cg.shared.global [%0], [%1], 16;"
        :: "r"(saddr), "l"(__cvta_generic_to_global(gptr)));
}
__device__ __forceinline__ void cp_commit() {
    asm volatile("cp.async.commit_group;");
}
template<int N>
__device__ __forceinline__ void cp_wait() {
    asm volatile("cp.async.wait_group %0;" :: "n"(N));
}

__device__ __forceinline__ float warpReduceSum(float v) {
#pragma unroll
    for (int o = 16; o > 0; o >>= 1) v += __shfl_xor_sync(0xffffffffu, v, o);
    return v;
}
__device__ __forceinline__ float warpReduceMax(float v) {
#pragma unroll
    for (int o = 16; o > 0; o >>= 1) v = fmaxf(v, __shfl_xor_sync(0xffffffffu, v, o));
    return v;
}

// ---------------- mma.sync fp16 GEMM body ----------------
// D[M,N] = A[M,K] @ B[N,K]^T.  Tile 128 x BN (BN=128 or 64), BK=64.
// NPROD=1: A,B single fp16 (3-stage).  NPROD=3: A and B split (2-stage).
// Per-warp: wm=M quarter (32 rows), wn=N half (BN/2 cols = NBT subtiles of 16).
// EPI: 2 = +bias[n]+aux residual -> f32 | 5 = acc*0.125 -> f32
//      6 = +bias -> fp16 split | 8 = raw -> fp16 split
//      9 = mish(acc+bias) -> fp16 single | 10 = acc*aux[n]+bias[n] -> fp16 single
constexpr int MM_SMEM1  = 3 * 32768 + 1024;            // 1-prod, BN=128, 3 stages
constexpr int MM_SMEM3  = 2 * 65536 + 1024;            // 3-prod, BN=128, 2 stages
constexpr int MM_SMEM3N = 2 * 49152 + 1024;            // 3-prod, BN=64,  2 stages

template<int EPI, int NPROD, int BN>
__device__ __forceinline__ void mma_body(
    const __half* __restrict__ Ah, const __half* __restrict__ Al,
    const __half* __restrict__ Bh, const __half* __restrict__ Bl,
    float* __restrict__ C, __half* __restrict__ Ch, __half* __restrict__ Cl,
    int Kd, int lda, int ldb, int ldc, int nLim, int zdiv,
    long aQ, long aR, long bQ, long bR, long cQ, long cR,
    long biasZ, long auxZ,
    const float* __restrict__ bias, const float* __restrict__ aux)
{
    constexpr int ASZ  = 16384;            // 128 rows x 64 cols fp16
    constexpr int BSZ  = BN * 128;
    constexpr int NAt  = (NPROD >= 2) ? 2 : 1;
    constexpr int NBt  = (NPROD == 3) ? 2 : 1;
    constexpr int BOFF = NAt * ASZ;
    constexpr int STAGE = NAt * ASZ + NBt * BSZ;
    constexpr int NSTG  = (NPROD == 1) ? 3 : 2;
    constexpr int NBT   = BN / 32;         // 16-col subtiles per warp-half (4 or 2)
    extern __shared__ char sm_raw[];
    uint32_t sb0 = smem_u32(sm_raw);
    uint32_t sb  = (sb0 + 1023u) & ~1023u;

    int z = blockIdx.z;
    int zq = z / zdiv, zr = z - zq * zdiv;
    long aoff = (long)zq * aQ + (long)zr * aR;
    long boff = (long)zq * bQ + (long)zr * bR;
    long coff = (long)zq * cQ + (long)zr * cR;
    Ah += aoff;
    if (NPROD >= 2) Al += aoff;
    Bh += boff;
    if (NPROD == 3) Bl += boff;
    if (C)  C  += coff;
    if (Ch) Ch += coff;
    if (Cl) Cl += coff;
    const float* biasp = bias ? bias + (long)zq * biasZ : nullptr;
    const float* auxp  = aux  ? aux  + (long)zq * auxZ  : nullptr;

    int m0 = blockIdx.y * 128, n0 = blockIdx.x * BN;
    int tid = threadIdx.x, wid = tid >> 5, lane = tid & 31;
    int wm = wid & 3, wn = wid >> 2;

    int lrow = tid >> 3, lcq = tid & 7;

    auto issue_stage = [&](int k0, uint32_t sbase) {
#pragma unroll
        for (int ti = 0; ti < 4; ti++) {
            int row = lrow + ti * 32;
            uint32_t soff = SW128((uint32_t)(row * 128 + lcq * 16));
            long ga = (long)(m0 + row) * lda + k0 + lcq * 8;
            cp16(sbase + soff, Ah + ga);
            if (NPROD >= 2) cp16(sbase + ASZ + soff, Al + ga);
        }
#pragma unroll
        for (int ti = 0; ti < BN / 32; ti++) {
            int row = lrow + ti * 32;
            uint32_t soff = SW128((uint32_t)(row * 128 + lcq * 16));
            long gb = (long)(n0 + row) * ldb + k0 + lcq * 8;
            cp16(sbase + BOFF + soff, Bh + gb);
            if (NPROD == 3) cp16(sbase + BOFF + BSZ + soff, Bl + gb);
        }
        cp_commit();
    };

    float acc[2][BN / 16][4];
#pragma unroll
    for (int i = 0; i < 2; i++)
#pragma unroll
        for (int j = 0; j < BN / 16; j++)
#pragma unroll
            for (int l = 0; l < 4; l++) acc[i][j][l] = 0.f;

    int nk = Kd >> 6;
#pragma unroll
    for (int s = 0; s < NSTG - 1; s++)
        if (s < nk) issue_stage(s << 6, sb + (uint32_t)s * STAGE);

    for (int i = 0; i < nk; i++) {
        uint32_t cur = sb + (uint32_t)(i % NSTG) * STAGE;
        int j = i + NSTG - 1;
        if (j < nk) issue_stage(j << 6, sb + (uint32_t)(j % NSTG) * STAGE);
        int rem = nk - 1 - i;
        if (NSTG == 3) {
            if (rem >= 2) cp_wait<2>();
            else if (rem == 1) cp_wait<1>();
            else cp_wait<0>();
        } else {
            if (rem >= 1) cp_wait<1>();
            else cp_wait<0>();
        }
        __syncthreads();

        uint32_t uAh = cur, uAl = cur + ASZ, uBh = cur + BOFF, uBl = cur + BOFF + BSZ;
#pragma unroll
        for (int ks = 0; ks < 4; ks++) {
            uint32_t afh[2][4], afl[2][4], bfh[NBT][4], bfl[NBT][4];
#pragma unroll
            for (int mt = 0; mt < 2; mt++) {
                int r = wm * 32 + mt * 16 + (lane & 15);
                int kc = ks * 2 + (lane >> 4);
                uint32_t off = SW128((uint32_t)(r * 128 + kc * 16));
                ldsm4(afh[mt], uAh + off);
                if (NPROD >= 2) ldsm4(afl[mt], uAl + off);
            }
#pragma unroll
            for (int bt = 0; bt < NBT; bt++) {
                int r = wn * (BN / 2) + bt * 16 + (lane & 7) + ((lane >> 4) << 3);
                int kc = ks * 2 + ((lane >> 3) & 1);
                uint32_t off = SW128((uint32_t)(r * 128 + kc * 16));
                ldsm4(bfh[bt], uBh + off);
                if (NPROD == 3) ldsm4(bfl[bt], uBl + off);
            }
#pragma unroll
            for (int p = 0; p < NPROD; p++)
#pragma unroll
                for (int mt = 0; mt < 2; mt++)
#pragma unroll
                    for (int bt = 0; bt < NBT; bt++)
#pragma unroll
                        for (int hh = 0; hh < 2; hh++) {
                            const uint32_t* af  = (p == 1) ? afl[mt] : afh[mt];
                            const uint32_t* bfp = (p == 2) ? &bfl[bt][hh * 2] : &bfh[bt][hh * 2];
                            mma16816(acc[mt][bt * 2 + hh], af, bfp);
                        }
        }
        __syncthreads();
    }

    // epilogue
#pragma unroll
    for (int mt = 0; mt < 2; mt++)
#pragma unroll
        for (int bt = 0; bt < NBT; bt++)
#pragma unroll
            for (int hh = 0; hh < 2; hh++) {
                float* d = acc[mt][bt * 2 + hh];
                int col = n0 + wn * (BN / 2) + bt * 16 + hh * 8 + (lane & 3) * 2;
                int r0  = m0 + wm * 32 + mt * 16 + (lane >> 2);
                if (col >= nLim) continue;
#pragma unroll
                for (int half = 0; half < 2; half++) {
                    int row = r0 + half * 8;
                    float t0 = d[half * 2 + 0], t1 = d[half * 2 + 1];
                    if (EPI == 2) {
                        t0 += biasp[col]     + auxp[(long)row * ldc + col];
                        t1 += biasp[col + 1] + auxp[(long)row * ldc + col + 1];
                        float2 v = {t0, t1};
                        *reinterpret_cast<float2*>(C + (long)row * ldc + col) = v;
                    } else if (EPI == 5) {
                        float2 v = {t0 * 0.125f, t1 * 0.125f};
                        *reinterpret_cast<float2*>(C + (long)row * ldc + col) = v;
                    } else if (EPI == 9) {
                        t0 += biasp[col];
                        t1 += biasp[col + 1];
                        float sp0 = (t0 > 20.f) ? t0 : log1pf(expf(t0));
                        float sp1 = (t1 > 20.f) ? t1 : log1pf(expf(t1));
                        t0 = t0 * tanhf(sp0);
                        t1 = t1 * tanhf(sp1);
                        __half2 hv = {__float2half_rn(t0), __float2half_rn(t1)};
                        *reinterpret_cast<__half2*>(Ch + (long)row * ldc + col) = hv;
                    } else if (EPI == 10) {
                        t0 = t0 * auxp[col]     + biasp[col];
                        t1 = t1 * auxp[col + 1] + biasp[col + 1];
                        __half2 hv = {__float2half_rn(t0), __float2half_rn(t1)};
                        *reinterpret_cast<__half2*>(Ch + (long)row * ldc + col) = hv;
                    } else { // 6, 8: fp16 split outputs
                        if (EPI == 6) {
                            t0 += biasp[col];
                            t1 += biasp[col + 1];
                        }
                        __half h0, l0, h1, l1;
                        split_h(t0, h0, l0);
                        split_h(t1, h1, l1);
                        __half2 hv = {h0, h1}, lv = {l0, l1};
                        *reinterpret_cast<__half2*>(Ch + (long)row * ldc + col) = hv;
                        *reinterpret_cast<__half2*>(Cl + (long)row * ldc + col) = lv;
                    }
                }
            }
}

template<int EPI>
__global__ void __launch_bounds__(256, 2) mma_gemm1(
    const __half* __restrict__ Ah, const __half* __restrict__ Bh,
    float* __restrict__ C, __half* __restrict__ Ch,
    int Kd, int lda, int ldb, int ldc, int nLim, int zdiv,
    long aQ, long aR, long bQ, long bR, long cQ, long cR,
    long biasZ, long auxZ,
    const float* __restrict__ bias, const float* __restrict__ aux)
{
    mma_body<EPI, 1, 128>(Ah, nullptr, Bh, nullptr, C, Ch, nullptr, Kd, lda, ldb, ldc, nLim, zdiv,
                          aQ, aR, bQ, bR, cQ, cR, biasZ, auxZ, bias, aux);
}

template<int EPI>
__global__ void __launch_bounds__(256) mma_gemm3(
    const __half* __restrict__ Ah, const __half* __restrict__ Al,
    const __half* __restrict__ Bh, const __half* __restrict__ Bl,
    float* __restrict__ C, __half* __restrict__ Ch, __half* __restrict__ Cl,
    int Kd, int lda, int ldb, int ldc, int nLim, int zdiv,
    long aQ, long aR, long bQ, long bR, long cQ, long cR,
    long biasZ, long auxZ,
    const float* __restrict__ bias, const float* __restrict__ aux)
{
    mma_body<EPI, 3, 128>(Ah, Al, Bh, Bl, C, Ch, Cl, Kd, lda, ldb, ldc, nLim, zdiv,
                          aQ, aR, bQ, bR, cQ, cR, biasZ, auxZ, bias, aux);
}

template<int EPI>
__global__ void __launch_bounds__(256, 2) mma_gemm3n(
    const __half* __restrict__ Ah, const __half* __restrict__ Al,
    const __half* __restrict__ Bh, const __half* __restrict__ Bl,
    float* __restrict__ C, __half* __restrict__ Ch, __half* __restrict__ Cl,
    int Kd, int lda, int ldb, int ldc, int nLim, int zdiv,
    long aQ, long aR, long bQ, long bR, long cQ, long cR,
    long biasZ, long auxZ,
    const float* __restrict__ bias, const float* __restrict__ aux)
{
    mma_body<EPI, 3, 64>(Ah, Al, Bh, Bl, C, Ch, Cl, Kd, lda, ldb, ldc, nLim, zdiv,
                         aQ, aR, bQ, bR, cQ, cR, biasZ, auxZ, bias, aux);
}

// ---------------- softmax (in place on attn rows; emits fp16 split) ----------------
__global__ void __launch_bounds__(256) softmax_k(float* __restrict__ attn,
                                                 const unsigned char* __restrict__ smask,
                                                 __half* __restrict__ ath,
                                                 __half* __restrict__ atl)
{
    int i = blockIdx.x, h = blockIdx.y, b = blockIdx.z;
    long rbase = (((long)(b * cH + h)) * cT + i) * cT;
    float* row = attn + rbase;
    const unsigned char* mrow = smask + ((long)b * cT + i) * cT;
    int tid = threadIdx.x, lane = tid & 31, wid = tid >> 5;
    __shared__ float red[8];
    __shared__ float bc;

    float v[4];
    float mx = -3.4e38f;
#pragma unroll
    for (int r = 0; r < 4; r++) {
        int j = tid + r * 256;
        float s = row[j];
        if (mrow[j]) s = -1e9f;
        v[r] = s;
        mx = fmaxf(mx, s);
    }
    mx = warpReduceMax(mx);
    if (lane == 0) red[wid] = mx;
    __syncthreads();
    if (wid == 0) {
        float r = (lane < 8) ? red[lane] : -3.4e38f;
        r = warpReduceMax(r);
        if (lane == 0) bc = r;
    }
    __syncthreads();
    mx = bc;
    float sum = 0.f;
#pragma unroll
    for (int r = 0; r < 4; r++) { v[r] = expf(v[r] - mx); sum += v[r]; }
    __syncthreads();
    sum = warpReduceSum(sum);
    if (lane == 0) red[wid] = sum;
    __syncthreads();
    if (wid == 0) {
        float r = (lane < 8) ? red[lane] : 0.f;
        r = warpReduceSum(r);
        if (lane == 0) bc = r;
    }
    __syncthreads();
    float inv = 1.f / bc;
#pragma unroll
    for (int r = 0; r < 4; r++) {
        int j = tid + r * 256;
        float y = v[r] * inv;
        row[j] = y;
        __half hh, ll;
        split_h(y, hh, ll);
        ath[rbase + j] = hh;
        atl[rbase + j] = ll;
    }
}

// ---------------- LayerNorm over D=256; optional fp16 output ----------------
__global__ void __launch_bounds__(256) ln_k(const float* __restrict__ in,
                                            const float* __restrict__ g,
                                            const float* __restrict__ bta,
                                            const unsigned char* __restrict__ mask,
                                            float* __restrict__ out,
                                            __half* __restrict__ oh)
{
    long n = blockIdx.x;
    int tid = threadIdx.x, lane = tid & 31, wid = tid >> 5;
    __shared__ float red[8];
    __shared__ float stats[2];

    float x = in[n * cD + tid];
    float s = warpReduceSum(x);
    if (lane == 0) red[wid] = s;
    __syncthreads();
    if (wid == 0) {
        float r = (lane < 8) ? red[lane] : 0.f;
        r = warpReduceSum(r);
        if (lane == 0) stats[0] = r;
    }
    __syncthreads();
    float s2 = warpReduceSum(x * x);
    if (lane == 0) red[wid] = s2;
    __syncthreads();
    if (wid == 0) {
        float r = (lane < 8) ? red[lane] : 0.f;
        r = warpReduceSum(r);
        if (lane == 0) stats[1] = r;
    }
    __syncthreads();
    float mean = stats[0] * (1.f / cD);
    float var  = stats[1] * (1.f / cD) - mean * mean;
    float y = (x - mean) * rsqrtf(var + LN_EPS) * g[tid] + bta[tid];
    if (mask[n]) y = 0.f;
    out[n * cD + tid] = y;
    if (oh) oh[n * cD + tid] = __float2half_rn(y);
}

// ---------------- fused small weight prep (one launch) ----------------
__device__ __forceinline__ void split4_at(const float* in, __half* oh, __half* ol, long i) {
    float4 v = *reinterpret_cast<const float4*>(in + i);
    __half h0, h1, h2, h3, l0, l1, l2, l3;
    split_h(v.x, h0, l0); split_h(v.y, h1, l1);
    split_h(v.z, h2, l2); split_h(v.w, h3, l3);
    __half2 ha = {h0, h1}, hb = {h2, h3}, la = {l0, l1}, lb = {l2, l3};
    *reinterpret_cast<__half2*>(oh + i)     = ha;
    *reinterpret_cast<__half2*>(oh + i + 2) = hb;
    *reinterpret_cast<__half2*>(ol + i)     = la;
    *reinterpret_cast<__half2*>(ol + i + 2) = lb;
}
__device__ __forceinline__ void cvt4_at(const float* in, __half* o, long i) {
    float4 v = *reinterpret_cast<const float4*>(in + i);
    __half2 a = {__float2half_rn(v.x), __float2half_rn(v.y)};
    __half2 b = {__float2half_rn(v.z), __float2half_rn(v.w)};
    *reinterpret_cast<__half2*>(o + i)     = a;
    *reinterpret_cast<__half2*>(o + i + 2) = b;
}

__global__ void __launch_bounds__(256) wprep_k(
    const float* __restrict__ Wq, const float* __restrict__ Wk,
    const float* __restrict__ Wv, const float* __restrict__ Wo,
    const float* __restrict__ w1, const float* __restrict__ w2,
    const float* __restrict__ bk, const float* __restrict__ bv,
    __half* __restrict__ wqh, __half* __restrict__ wql,
    __half* __restrict__ wkvh, __half* __restrict__ wkvl,
    __half* __restrict__ woh, __half* __restrict__ wol,
    __half* __restrict__ w1h, __half* __restrict__ w2h,
    float* __restrict__ bkv, float* __restrict__ pwnsum)
{
    int task = blockIdx.y;
    long i = ((long)blockIdx.x * 256 + threadIdx.x) * 4;
    constexpr long SZp = (long)128 * cD;  // 32768
    constexpr long SZw = (long)cC * cD;   // 262144
    if (task == 0) { if (i < SZp) split4_at(Wq, wqh, wql, i); }
    else if (task == 1) { if (i < SZp) split4_at(Wk, wkvh, wkvl, i); }
    else if (task == 2) { if (i < SZp) split4_at(Wv, wkvh + SZp, wkvl + SZp, i); }
    else if (task == 3) { if (i < SZp) split4_at(Wo, woh, wol, i); }
    else if (task == 4) { if (i < SZw) cvt4_at(w1, w1h, i); }
    else if (task == 5) { if (i < SZw) cvt4_at(w2, w2h, i); }
    else {
        long t = (long)blockIdx.x * 256 + threadIdx.x;
        if (t < 128) bkv[t] = bk[t];
        else if (t < 256) bkv[t] = bv[t - 128];
        if (t < (long)cB * cC) pwnsum[t] = 0.f;
    }
}

// ---------------- fp32 -> fp16 hi/lo split (x) ----------------
__global__ void __launch_bounds__(256) cvt_split_h(const float* __restrict__ in,
                                                   __half* __restrict__ oh,
                                                   __half* __restrict__ ol, long n)
{
    long i = ((long)blockIdx.x * 256 + threadIdx.x) * 4;
    if (i >= n) return;
    split4_at(in, oh, ol, i);
}

// ---------------- kv cols 128..255 -> vT [(b,h)][n][t] split (rows 0..63 used) ----------------
__global__ void __launch_bounds__(256) vT_k(const __half* __restrict__ kvh,
                                            const __half* __restrict__ kvl,
                                            __half* __restrict__ vTh,
                                            __half* __restrict__ vTl)
{
    __shared__ __half th[32][33], tl[32][33];
    int b = blockIdx.z;
    int t0 = blockIdx.x * 32, c0 = blockIdx.y * 32;
    int tx = threadIdx.x & 31, ty = threadIdx.x >> 5;  // 32 x 8
#pragma unroll
    for (int i = 0; i < 4; i++) {
        int t = t0 + ty + i * 8;
        long src = ((long)b * cT + t) * 256 + 128 + c0 + tx;
        th[ty + i * 8][tx] = kvh[src];
        tl[ty + i * 8][tx] = kvl[src];
    }
    __syncthreads();
#pragma unroll
    for (int i = 0; i < 4; i++) {
        int c = c0 + ty + i * 8;
        int h = c >> 6, n = c & 63;
        long base = ((long)((b << 1) | h) * 128 + n) * cT + t0 + tx;
        vTh[base] = th[tx][ty + i * 8];
        vTl[base] = tl[tx][ty + i * 8];
    }
}

// ---------------- p_w transpose to fp16 + fused pwn column sums ----------------
__global__ void __launch_bounds__(256) cvtT_k(const float* __restrict__ in,
                                              __half* __restrict__ oT,
                                              float* __restrict__ pwnsum)
{
    __shared__ float tile[32][33];
    __shared__ float colsum[32];
    int b = blockIdx.z;
    int o0 = blockIdx.x * 32, c0 = blockIdx.y * 32;
    int tx = threadIdx.x & 31, ty = threadIdx.x >> 5;  // 32 x 8
    const float* src = in + (long)b * cC * cC;
    if (threadIdx.x < 32) colsum[threadIdx.x] = 0.f;
    float s = 0.f;
#pragma unroll
    for (int i = 0; i < 4; i++) {
        int c = c0 + ty + i * 8;
        float v = src[(long)c * cC + o0 + tx];
        tile[ty + i * 8][tx] = v;
        s += v * v;
    }
    __syncthreads();
    atomicAdd(&colsum[tx], s);
    __half* dst = oT + (long)b * cC * cC;
#pragma unroll
    for (int i = 0; i < 4; i++) {
        int o = o0 + ty + i * 8;
        dst[(long)o * cC + c0 + tx] = __float2half_rn(tile[tx][ty + i * 8]);
    }
    __syncthreads();
    if (ty == 0) atomicAdd(&pwnsum[(long)b * cC + o0 + tx], colsum[tx]);
}

// ---------------- finish pwn: sums -> inverse norms (in place) ----------------
__global__ void __launch_bounds__(256) pwn_fin(float* __restrict__ pwn)
{
    long i = (long)blockIdx.x * 256 + threadIdx.x;
    if (i < (long)cB * cC)
        pwn[i] = 1.f / fmaxf(sqrtf(pwn[i]), 1e-12f);
}

// ---------------- depthwise weight inverse norms ----------------
__global__ void __launch_bounds__(128) dwn_k(const float* __restrict__ d_w, float* __restrict__ dwn)
{
    int k = blockIdx.x, b = blockIdx.y;
    int tid = threadIdx.x;
    float s = 0.f;
    for (int c = tid; c < cC; c += 128) {
        float w = d_w[((long)b * cC + c) * 9 + k];
        s += w * w;
    }
    __shared__ float red[4];
    s = warpReduceSum(s);
    if ((tid & 31) == 0) red[tid >> 5] = s;
    __syncthreads();
    if (tid == 0) {
        float r = red[0] + red[1] + red[2] + red[3];
        dwn[b * 9 + k] = 1.f / fmaxf(sqrtf(r), 1e-12f);
    }
}

// ---------------- tiled depthwise conv (K=9): fp16 in, fp16 out ----------------
constexpr int CV_TR = 32;   // output t-rows per block
__global__ void __launch_bounds__(256) conv2_k(const __half* __restrict__ h,
                                               const float* __restrict__ d_w,
                                               const float* __restrict__ d_g,
                                               const float* __restrict__ d_b,
                                               const float* __restrict__ p_g,
                                               const float* __restrict__ dwn,
                                               __half* __restrict__ deph)
{
    __shared__ __half hs[CV_TR + 8][256];
    __shared__ float ws[9];
    int t0 = blockIdx.x * CV_TR, c0 = blockIdx.y * 256, b = blockIdx.z;
    int tid = threadIdx.x;
    if (tid < 9) ws[tid] = dwn[b * 9 + tid];
    __syncthreads();

#pragma unroll
    for (int i = tid; i < (CV_TR + 8) * 32; i += 256) {
        int r = i >> 5, q8 = i & 31;
        int t = t0 + r - 4;
        uint4 v = make_uint4(0u, 0u, 0u, 0u);
        if (t >= 0 && t < cT)
            v = *reinterpret_cast<const uint4*>(h + ((long)b * cT + t) * cC + c0 + q8 * 8);
        *reinterpret_cast<uint4*>(&hs[r][q8 * 8]) = v;
    }

    int c = c0 + tid;
    long bc = (long)b * cC + c;
    const float* wrow = d_w + bc * 9;
    float w[9];
#pragma unroll
    for (int k = 0; k < 9; k++) w[k] = wrow[k] * ws[k];
    float dg = d_g[bc], db = d_b[bc], pg = p_g[bc];
    __syncthreads();

#pragma unroll 4
    for (int tt = 0; tt < CV_TR; tt++) {
        float acc = 0.f;
#pragma unroll
        for (int k = 0; k < 9; k++) acc += __half2float(hs[tt + k][tid]) * w[k];
        float val = (acc * dg + db) * pg;
        deph[((long)b * cT + t0 + tt) * cC + c] = __float2half_rn(val);
    }
}

// ---------------- launch ----------------
extern "C" void kernel_launch(void* const* d_in, const int* in_sizes, int n_in,
                              void* d_out, int out_size)
{
    const float* x    = (const float*)d_in[0];
    const float* d_w  = (const float*)d_in[1];
    const float* d_g  = (const float*)d_in[2];
    const float* d_b  = (const float*)d_in[3];
    const float* p_w  = (const float*)d_in[4];
    const float* p_g  = (const float*)d_in[5];
    const float* p_b  = (const float*)d_in[6];
    const unsigned char* mask  = (const unsigned char*)d_in[7];
    const unsigned char* smask = (const unsigned char*)d_in[8];
    const float* Wq = (const float*)d_in[9];
    const float* bq = (const float*)d_in[10];
    const float* Wk = (const float*)d_in[11];
    const float* bk = (const float*)d_in[12];
    const float* Wv = (const float*)d_in[13];
    const float* bv = (const float*)d_in[14];
    const float* Wo = (const float*)d_in[15];
    const float* bo = (const float*)d_in[16];
    const float* g0 = (const float*)d_in[17];
    const float* b0 = (const float*)d_in[18];
    const float* w1_w = (const float*)d_in[19];
    const float* w1_b = (const float*)d_in[20];
    const float* w2_w = (const float*)d_in[21];
    const float* w2_b = (const float*)d_in[22];
    const float* g1 = (const float*)d_in[23];
    const float* b1 = (const float*)d_in[24];

    float* out  = (float*)d_out;
    float* attn = out + (long)cNT * cD;   // output tuple: (out[B,T,D], attn[B,H,T,T])

    float *apre, *a, *o2, *dwn, *pwn, *bkv;
    __half *xh, *xl, *qh, *ql, *kvh, *kvl, *vTh, *vTl, *atth, *attl, *ctxh, *ctxl;
    __half *ah, *hh, *deph, *pth, *pwT, *w1h, *w2h;
    __half *wqh, *wql, *wkvh, *wkvl, *woh, *wol;
    cudaGetSymbolAddress((void**)&apre, g_apre);
    cudaGetSymbolAddress((void**)&a,    g_a);
    cudaGetSymbolAddress((void**)&o2,   g_o2);
    cudaGetSymbolAddress((void**)&dwn,  g_dwn);
    cudaGetSymbolAddress((void**)&pwn,  g_pwn);
    cudaGetSymbolAddress((void**)&bkv,  g_bkv);
    cudaGetSymbolAddress((void**)&xh,   g_xh);
    cudaGetSymbolAddress((void**)&xl,   g_xl);
    cudaGetSymbolAddress((void**)&qh,   g_qh);
    cudaGetSymbolAddress((void**)&ql,   g_ql);
    cudaGetSymbolAddress((void**)&kvh,  g_kvh);
    cudaGetSymbolAddress((void**)&kvl,  g_kvl);
    cudaGetSymbolAddress((void**)&vTh,  g_vTh);
    cudaGetSymbolAddress((void**)&vTl,  g_vTl);
    cudaGetSymbolAddress((void**)&atth, g_atth);
    cudaGetSymbolAddress((void**)&attl, g_attl);
    cudaGetSymbolAddress((void**)&ctxh, g_ctxh);
    cudaGetSymbolAddress((void**)&ctxl, g_ctxl);
    cudaGetSymbolAddress((void**)&ah,   g_ah);
    cudaGetSymbolAddress((void**)&hh,   g_hh);
    cudaGetSymbolAddress((void**)&deph, g_deph);
    cudaGetSymbolAddress((void**)&pth,  g_pth);
    cudaGetSymbolAddress((void**)&pwT,  g_pwT);
    cudaGetSymbolAddress((void**)&w1h,  g_w1);
    cudaGetSymbolAddress((void**)&w2h,  g_w2);
    cudaGetSymbolAddress((void**)&wqh,  g_wq);
    cudaGetSymbolAddress((void**)&wql,  g_wql);
    cudaGetSymbolAddress((void**)&wkvh, g_wkv);
    cudaGetSymbolAddress((void**)&wkvl, g_wkvl);
    cudaGetSymbolAddress((void**)&woh,  g_wo);
    cudaGetSymbolAddress((void**)&wol,  g_wol);

    cudaFuncSetAttribute(mma_gemm1<2>,  cudaFuncAttributeMaxDynamicSharedMemorySize, MM_SMEM1);
    cudaFuncSetAttribute(mma_gemm1<9>,  cudaFuncAttributeMaxDynamicSharedMemorySize, MM_SMEM1);
    cudaFuncSetAttribute(mma_gemm1<10>, cudaFuncAttributeMaxDynamicSharedMemorySize, MM_SMEM1);
    cudaFuncSetAttribute(mma_gemm3<2>, cudaFuncAttributeMaxDynamicSharedMemorySize, MM_SMEM3);
    cudaFuncSetAttribute(mma_gemm3<5>, cudaFuncAttributeMaxDynamicSharedMemorySize, MM_SMEM3);
    cudaFuncSetAttribute(mma_gemm3<6>, cudaFuncAttributeMaxDynamicSharedMemorySize, MM_SMEM3);
    cudaFuncSetAttribute(mma_gemm3n<8>, cudaFuncAttributeMaxDynamicSharedMemorySize, MM_SMEM3N);

    dim3 blk(256);

    // 0) prep
    wprep_k<<<dim3(256, 7), blk>>>(Wq, Wk, Wv, Wo, w1_w, w2_w, bk, bv,
                                   wqh, wql, wkvh, wkvl, woh, wol, w1h, w2h, bkv, pwn);
    cvtT_k<<<dim3(32, 32, cB), blk>>>(p_w, pwT, pwn);
    pwn_fin<<<(cB * cC) / 256, blk>>>(pwn);
    dwn_k<<<dim3(9, cB), 128>>>(d_w, dwn);
    cvt_split_h<<<(cNT * cD) / 1024, blk>>>(x, xh, xl, (long)cNT * cD);

    // 1) q (split out, 3-product)
    mma_gemm3<6><<<dim3(1, cNT / 128, 1), blk, MM_SMEM3>>>(
        xh, xl, wqh, wql, nullptr, qh, ql, cD, cD, cD, 128, 128, 1,
        0, 0, 0, 0, 0, 0, 0, 0, bq, nullptr);
    // 2) kv fused (split out, 3-product)
    mma_gemm3<6><<<dim3(2, cNT / 128, 1), blk, MM_SMEM3>>>(
        xh, xl, wkvh, wkvl, nullptr, kvh, kvl, cD, cD, cD, 256, 256, 1,
        0, 0, 0, 0, 0, 0, 0, 0, bkv, nullptr);

    // 3) v -> vT split
    vT_k<<<dim3(32, 4, cB), blk>>>(kvh, kvl, vTh, vTl);

    // 4) scores = q k^T / 8  [3-product, z=(b,h) zdiv=2]
    mma_gemm3<5><<<dim3(8, 8, 32), blk, MM_SMEM3>>>(
        qh, ql, kvh, kvl, attn, nullptr, nullptr, cDK, 128, 256, cT, 1024, 2,
        (long)cT * 128, 64, (long)cT * 256, 64, 2 * cTT, cTT, 0, 0, nullptr, nullptr);

    // 5) masked softmax (writes final attn + fp16 split)
    softmax_k<<<dim3(cT, cH, cB), blk>>>(attn, smask, atth, attl);

    // 6) ctx = attn @ v  [3-product, BN=64 tile] -> fp16 split
    mma_gemm3n<8><<<dim3(1, 8, 32), blk, MM_SMEM3N>>>(
        atth, attl, vTh, vTl, nullptr, ctxh, ctxl, cT, cT, cT, 128, 64, 2,
        2 * cTT, cTT, (long)256 * cT, (long)128 * cT, (long)cT * 128, 64,
        0, 0, nullptr, nullptr);

    // 7) apre = ctx @ Wo^T + bo + x  [3-product]
    mma_gemm3<2><<<dim3(2, cNT / 128, 1), blk, MM_SMEM3>>>(
        ctxh, ctxl, woh, wol, apre, nullptr, nullptr, 128, 128, 128, cD, 256, 1,
        0, 0, 0, 0, 0, 0, 0, 0, bo, x);

    // 8) a = LN(apre), masked; emit fp16 single
    ln_k<<<cNT, blk>>>(apre, g0, b0, mask, a, ah);

    // 9) h = mish(a @ w1^T + w1_b) -> fp16 single  [1-product, 3-stage, occ 2]
    mma_gemm1<9><<<dim3(cC / 128, cNT / 128, 1), blk, MM_SMEM1>>>(
        ah, w1h, nullptr, hh, cD, cD, cD, cC, 1024, 1,
        0, 0, 0, 0, 0, 0, 0, 0, w1_b, nullptr);

    // 10) tiled depthwise conv (fp16 in/out)
    conv2_k<<<dim3(cT / CV_TR, cC / 256, cB), blk>>>(hh, d_w, d_g, d_b, p_g, dwn, deph);

    // 11) pt = (dep @ pwT) * pwninv[o] + p_b -> fp16 single  [1-product, batched over b]
    mma_gemm1<10><<<dim3(cC / 128, cT / 128, cB), blk, MM_SMEM1>>>(
        deph, pwT, nullptr, pth, cC, cC, cC, cC, 1024, 1,
        (long)cT * cC, 0, (long)cC * cC, 0, (long)cT * cC, 0, cC, cC, p_b, pwn);

    // 12) o2 = pt @ w2^T + w2_b + a  [1-product]
    mma_gemm1<2><<<dim3(cD / 128, cNT / 128, 1), blk, MM_SMEM1>>>(
        pth, w2h, o2, nullptr, cC, cC, cC, cD, 256, 1,
        0, 0, 0, 0, 0, 0, 0, 0, w2_b, a);

    // 13) out = LN(o2), masked
    ln_k<<<cNT, blk>>>(o2, g1, b1, mask, out, nullptr);
}

// round 13
// speedup vs baseline: 3.9261x; 1.0628x over previous
#include <cuda_runtime.h>
#include <cuda_fp16.h>
#include <cstdint>
#include <math.h>

// ---------------- problem constants ----------------
constexpr int cB = 16, cT = 1024, cD = 256, cH = 2, cDK = 64, cC = 1024;
constexpr int cNT = cB * cT;            // 16384 tokens
constexpr long cTT = (long)cT * cT;     // 1M
constexpr float LN_EPS = 1e-5f;

// ---------------- device scratch (no allocs allowed) ----------------
__device__ float g_apre[cNT * cD];
__device__ float g_a   [cNT * cD];
__device__ float g_o2 [cNT * cD];
__device__ float g_dwn[cB * 9];
__device__ float g_pwn[cB * cC];        // first: sum of squares (atomic), then inv-norm in place
__device__ float g_bkv[256];
// fp16 buffers
__device__ __half g_xh  [cNT * cD];
__device__ __half g_xl  [cNT * cD];
__device__ __half g_qh  [cNT * 128];
__device__ __half g_ql  [cNT * 128];
__device__ __half g_kvh [cNT * 256];
__device__ __half g_kvl [cNT * 256];
__device__ __half g_vTh [(long)cB * cH * 64 * cT];    // compact 64 rows per (b,h)
__device__ __half g_atth[(long)cB * cH * cTT];
__device__ __half g_ctxh[cNT * 128];
__device__ __half g_ctxl[cNT * 128];
__device__ __half g_ah  [cNT * cD];
__device__ __half g_hh  [cNT * cC];
__device__ __half g_deph[cNT * cC];
__device__ __half g_pth [cNT * cC];
__device__ __half g_pwT [(long)cB * cC * cC];
__device__ __half g_w1  [cC * cD];
__device__ __half g_w2  [cD * cC];
__device__ __half g_wq  [128 * cD];
__device__ __half g_wql [128 * cD];
__device__ __half g_wkv [256 * cD];
__device__ __half g_wkvl[256 * cD];
__device__ __half g_wo  [cD * 128];
__device__ __half g_wol [cD * 128];

// ---------------- helpers ----------------
__device__ __forceinline__ uint32_t smem_u32(const void* p) {
    uint32_t a;
    asm("{ .reg .u64 t; cvta.to.shared.u64 t, %1; cvt.u32.u64 %0, t; }" : "=r"(a) : "l"(p));
    return a;
}
#define SW128(off) ((off) ^ (((off) >> 3) & 0x70))

__device__ __forceinline__ void split_h(float v, __half& h, __half& l) {
    h = __float2half_rn(v);
    l = __float2half_rn(v - __half2float(h));
}

__device__ __forceinline__ void ldsm4(uint32_t* r, uint32_t addr) {
    asm volatile("ldmatrix.sync.aligned.m8n8.x4.shared.b16 {%0,%1,%2,%3}, [%4];"
        : "=r"(r[0]), "=r"(r[1]), "=r"(r[2]), "=r"(r[3]) : "r"(addr));
}
__device__ __forceinline__ void mma16816(float* d, const uint32_t* a, const uint32_t* b) {
    asm volatile("mma.sync.aligned.m16n8k16.row.col.f32.f16.f16.f32 "
        "{%0,%1,%2,%3}, {%4,%5,%6,%7}, {%8,%9}, {%0,%1,%2,%3};"
        : "+f"(d[0]), "+f"(d[1]), "+f"(d[2]), "+f"(d[3])
        : "r"(a[0]), "r"(a[1]), "r"(a[2]), "r"(a[3]), "r"(b[0]), "r"(b[1]));
}
__device__ __forceinline__ void cp16(uint32_t saddr, const void* gptr) {
    asm volatile("cp.async.cg.shared.global [%0], [%1], 16;"
        :: "r"(saddr), "l"(__cvta_generic_to_global(gptr)));
}
__device__ __forceinline__ void cp_commit() {
    asm volatile("cp.async.commit_group;");
}
template<int N>
__device__ __forceinline__ void cp_wait() {
    asm volatile("cp.async.wait_group %0;" :: "n"(N));
}

__device__ __forceinline__ float warpReduceSum(float v) {
#pragma unroll
    for (int o = 16; o > 0; o >>= 1) v += __shfl_xor_sync(0xffffffffu, v, o);
    return v;
}
__device__ __forceinline__ float warpReduceMax(float v) {
#pragma unroll
    for (int o = 16; o > 0; o >>= 1) v = fmaxf(v, __shfl_xor_sync(0xffffffffu, v, o));
    return v;
}

// ---------------- mma.sync fp16 GEMM body ----------------
// D[M,N] = A[M,K] @ B[N,K]^T.  Tile 128 x BN (BN=128 or 64), BK=64.
// NPROD=1: A,B single fp16 (3-stage).  NPROD=3: A and B split (2-stage).
// Per-warp: wm=M quarter (32 rows), wn=N half (BN/2 cols = NBT subtiles of 16).
// EPI: 2 = +bias[n]+aux residual -> f32 | 5 = acc*0.125 -> f32
//      6 = +bias -> fp16 split | 8 = raw -> fp16 split
//      9 = mish(acc+bias) -> fp16 single | 10 = acc*aux[n]+bias[n] -> fp16 single
constexpr int MM_SMEM1  = 3 * 32768 + 1024;            // 1-prod, BN=128, 3 stages
constexpr int MM_SMEM1N = 3 * 24576 + 1024;            // 1-prod, BN=64,  3 stages
constexpr int MM_SMEM3  = 2 * 65536 + 1024;            // 3-prod, BN=128, 2 stages

template<int EPI, int NPROD, int BN>
__device__ __forceinline__ void mma_body(
    const __half* __restrict__ Ah, const __half* __restrict__ Al,
    const __half* __restrict__ Bh, const __half* __restrict__ Bl,
    float* __restrict__ C, __half* __restrict__ Ch, __half* __restrict__ Cl,
    int Kd, int lda, int ldb, int ldc, int nLim, int zdiv,
    long aQ, long aR, long bQ, long bR, long cQ, long cR,
    long biasZ, long auxZ,
    const float* __restrict__ bias, const float* __restrict__ aux)
{
    constexpr int ASZ  = 16384;            // 128 rows x 64 cols fp16
    constexpr int BSZ  = BN * 128;
    constexpr int NAt  = (NPROD >= 2) ? 2 : 1;
    constexpr int NBt  = (NPROD == 3) ? 2 : 1;
    constexpr int BOFF = NAt * ASZ;
    constexpr int STAGE = NAt * ASZ + NBt * BSZ;
    constexpr int NSTG  = (NPROD == 1) ? 3 : 2;
    constexpr int NBT   = BN / 32;         // 16-col subtiles per warp-half (4 or 2)
    extern __shared__ char sm_raw[];
    uint32_t sb0 = smem_u32(sm_raw);
    uint32_t sb  = (sb0 + 1023u) & ~1023u;

    int z = blockIdx.z;
    int zq = z / zdiv, zr = z - zq * zdiv;
    long aoff = (long)zq * aQ + (long)zr * aR;
    long boff = (long)zq * bQ + (long)zr * bR;
    long coff = (long)zq * cQ + (long)zr * cR;
    Ah += aoff;
    if (NPROD >= 2) Al += aoff;
    Bh += boff;
    if (NPROD == 3) Bl += boff;
    if (C)  C  += coff;
    if (Ch) Ch += coff;
    if (Cl) Cl += coff;
    const float* biasp = bias ? bias + (long)zq * biasZ : nullptr;
    const float* auxp  = aux  ? aux  + (long)zq * auxZ  : nullptr;

    int m0 = blockIdx.y * 128, n0 = blockIdx.x * BN;
    int tid = threadIdx.x, wid = tid >> 5, lane = tid & 31;
    int wm = wid & 3, wn = wid >> 2;

    int lrow = tid >> 3, lcq = tid & 7;

    auto issue_stage = [&](int k0, uint32_t sbase) {
#pragma unroll
        for (int ti = 0; ti < 4; ti++) {
            int row = lrow + ti * 32;
            uint32_t soff = SW128((uint32_t)(row * 128 + lcq * 16));
            long ga = (long)(m0 + row) * lda + k0 + lcq * 8;
            cp16(sbase + soff, Ah + ga);
            if (NPROD >= 2) cp16(sbase + ASZ + soff, Al + ga);
        }
#pragma unroll
        for (int ti = 0; ti < BN / 32; ti++) {
            int row = lrow + ti * 32;
            uint32_t soff = SW128((uint32_t)(row * 128 + lcq * 16));
            long gb = (long)(n0 + row) * ldb + k0 + lcq * 8;
            cp16(sbase + BOFF + soff, Bh + gb);
            if (NPROD == 3) cp16(sbase + BOFF + BSZ + soff, Bl + gb);
        }
        cp_commit();
    };

    float acc[2][BN / 16][4];
#pragma unroll
    for (int i = 0; i < 2; i++)
#pragma unroll
        for (int j = 0; j < BN / 16; j++)
#pragma unroll
            for (int l = 0; l < 4; l++) acc[i][j][l] = 0.f;

    int nk = Kd >> 6;
#pragma unroll
    for (int s = 0; s < NSTG - 1; s++)
        if (s < nk) issue_stage(s << 6, sb + (uint32_t)s * STAGE);

    for (int i = 0; i < nk; i++) {
        uint32_t cur = sb + (uint32_t)(i % NSTG) * STAGE;
        int j = i + NSTG - 1;
        if (j < nk) issue_stage(j << 6, sb + (uint32_t)(j % NSTG) * STAGE);
        int rem = nk - 1 - i;
        if (NSTG == 3) {
            if (rem >= 2) cp_wait<2>();
            else if (rem == 1) cp_wait<1>();
            else cp_wait<0>();
        } else {
            if (rem >= 1) cp_wait<1>();
            else cp_wait<0>();
        }
        __syncthreads();

        uint32_t uAh = cur, uAl = cur + ASZ, uBh = cur + BOFF, uBl = cur + BOFF + BSZ;
#pragma unroll
        for (int ks = 0; ks < 4; ks++) {
            uint32_t afh[2][4], afl[2][4], bfh[NBT][4], bfl[NBT][4];
#pragma unroll
            for (int mt = 0; mt < 2; mt++) {
                int r = wm * 32 + mt * 16 + (lane & 15);
                int kc = ks * 2 + (lane >> 4);
                uint32_t off = SW128((uint32_t)(r * 128 + kc * 16));
                ldsm4(afh[mt], uAh + off);
                if (NPROD >= 2) ldsm4(afl[mt], uAl + off);
            }
#pragma unroll
            for (int bt = 0; bt < NBT; bt++) {
                int r = wn * (BN / 2) + bt * 16 + (lane & 7) + ((lane >> 4) << 3);
                int kc = ks * 2 + ((lane >> 3) & 1);
                uint32_t off = SW128((uint32_t)(r * 128 + kc * 16));
                ldsm4(bfh[bt], uBh + off);
                if (NPROD == 3) ldsm4(bfl[bt], uBl + off);
            }
#pragma unroll
            for (int p = 0; p < NPROD; p++)
#pragma unroll
                for (int mt = 0; mt < 2; mt++)
#pragma unroll
                    for (int bt = 0; bt < NBT; bt++)
#pragma unroll
                        for (int hh = 0; hh < 2; hh++) {
                            const uint32_t* af  = (p == 1) ? afl[mt] : afh[mt];
                            const uint32_t* bfp = (p == 2) ? &bfl[bt][hh * 2] : &bfh[bt][hh * 2];
                            mma16816(acc[mt][bt * 2 + hh], af, bfp);
                        }
        }
        __syncthreads();
    }

    // epilogue
#pragma unroll
    for (int mt = 0; mt < 2; mt++)
#pragma unroll
        for (int bt = 0; bt < NBT; bt++)
#pragma unroll
            for (int hh = 0; hh < 2; hh++) {
                float* d = acc[mt][bt * 2 + hh];
                int col = n0 + wn * (BN / 2) + bt * 16 + hh * 8 + (lane & 3) * 2;
                int r0  = m0 + wm * 32 + mt * 16 + (lane >> 2);
                if (col >= nLim) continue;
#pragma unroll
                for (int half = 0; half < 2; half++) {
                    int row = r0 + half * 8;
                    float t0 = d[half * 2 + 0], t1 = d[half * 2 + 1];
                    if (EPI == 2) {
                        t0 += biasp[col]     + auxp[(long)row * ldc + col];
                        t1 += biasp[col + 1] + auxp[(long)row * ldc + col + 1];
                        float2 v = {t0, t1};
                        *reinterpret_cast<float2*>(C + (long)row * ldc + col) = v;
                    } else if (EPI == 5) {
                        float2 v = {t0 * 0.125f, t1 * 0.125f};
                        *reinterpret_cast<float2*>(C + (long)row * ldc + col) = v;
                    } else if (EPI == 9) {
                        t0 += biasp[col];
                        t1 += biasp[col + 1];
                        float sp0 = (t0 > 20.f) ? t0 : log1pf(expf(t0));
                        float sp1 = (t1 > 20.f) ? t1 : log1pf(expf(t1));
                        t0 = t0 * tanhf(sp0);
                        t1 = t1 * tanhf(sp1);
                        __half2 hv = {__float2half_rn(t0), __float2half_rn(t1)};
                        *reinterpret_cast<__half2*>(Ch + (long)row * ldc + col) = hv;
                    } else if (EPI == 10) {
                        t0 = t0 * auxp[col]     + biasp[col];
                        t1 = t1 * auxp[col + 1] + biasp[col + 1];
                        __half2 hv = {__float2half_rn(t0), __float2half_rn(t1)};
                        *reinterpret_cast<__half2*>(Ch + (long)row * ldc + col) = hv;
                    } else { // 6, 8: fp16 split outputs
                        if (EPI == 6) {
                            t0 += biasp[col];
                            t1 += biasp[col + 1];
                        }
                        __half h0, l0, h1, l1;
                        split_h(t0, h0, l0);
                        split_h(t1, h1, l1);
                        __half2 hv = {h0, h1}, lv = {l0, l1};
                        *reinterpret_cast<__half2*>(Ch + (long)row * ldc + col) = hv;
                        *reinterpret_cast<__half2*>(Cl + (long)row * ldc + col) = lv;
                    }
                }
            }
}

template<int EPI>
__global__ void __launch_bounds__(256, 2) mma_gemm1(
    const __half* __restrict__ Ah, const __half* __restrict__ Bh,
    float* __restrict__ C, __half* __restrict__ Ch,
    int Kd, int lda, int ldb, int ldc, int nLim, int zdiv,
    long aQ, long aR, long bQ, long bR, long cQ, long cR,
    long biasZ, long auxZ,
    const float* __restrict__ bias, const float* __restrict__ aux)
{
    mma_body<EPI, 1, 128>(Ah, nullptr, Bh, nullptr, C, Ch, nullptr, Kd, lda, ldb, ldc, nLim, zdiv,
                          aQ, aR, bQ, bR, cQ, cR, biasZ, auxZ, bias, aux);
}

// 1-product, BN=64, split fp16 output (for ctx)
template<int EPI>
__global__ void __launch_bounds__(256, 2) mma_gemm1s(
    const __half* __restrict__ Ah, const __half* __restrict__ Bh,
    __half* __restrict__ Ch, __half* __restrict__ Cl,
    int Kd, int lda, int ldb, int ldc, int nLim, int zdiv,
    long aQ, long aR, long bQ, long bR, long cQ, long cR)
{
    mma_body<EPI, 1, 64>(Ah, nullptr, Bh, nullptr, nullptr, Ch, Cl, Kd, lda, ldb, ldc, nLim, zdiv,
                         aQ, aR, bQ, bR, cQ, cR, 0, 0, nullptr, nullptr);
}

template<int EPI>
__global__ void __launch_bounds__(256) mma_gemm3(
    const __half* __restrict__ Ah, const __half* __restrict__ Al,
    const __half* __restrict__ Bh, const __half* __restrict__ Bl,
    float* __restrict__ C, __half* __restrict__ Ch, __half* __restrict__ Cl,
    int Kd, int lda, int ldb, int ldc, int nLim, int zdiv,
    long aQ, long aR, long bQ, long bR, long cQ, long cR,
    long biasZ, long auxZ,
    const float* __restrict__ bias, const float* __restrict__ aux)
{
    mma_body<EPI, 3, 128>(Ah, Al, Bh, Bl, C, Ch, Cl, Kd, lda, ldb, ldc, nLim, zdiv,
                          aQ, aR, bQ, bR, cQ, cR, biasZ, auxZ, bias, aux);
}

// ---------------- softmax (in place; emits fp16 single) ----------------
__global__ void __launch_bounds__(256) softmax_k(float* __restrict__ attn,
                                                 const unsigned char* __restrict__ smask,
                                                 __half* __restrict__ ath)
{
    int i = blockIdx.x, h = blockIdx.y, b = blockIdx.z;
    long rbase = (((long)(b * cH + h)) * cT + i) * cT;
    float* row = attn + rbase;
    const unsigned char* mrow = smask + ((long)b * cT + i) * cT;
    int tid = threadIdx.x, lane = tid & 31, wid = tid >> 5;
    __shared__ float red[8];
    __shared__ float bc;

    float v[4];
    float mx = -3.4e38f;
#pragma unroll
    for (int r = 0; r < 4; r++) {
        int j = tid + r * 256;
        float s = row[j];
        if (mrow[j]) s = -1e9f;
        v[r] = s;
        mx = fmaxf(mx, s);
    }
    mx = warpReduceMax(mx);
    if (lane == 0) red[wid] = mx;
    __syncthreads();
    if (wid == 0) {
        float r = (lane < 8) ? red[lane] : -3.4e38f;
        r = warpReduceMax(r);
        if (lane == 0) bc = r;
    }
    __syncthreads();
    mx = bc;
    float sum = 0.f;
#pragma unroll
    for (int r = 0; r < 4; r++) { v[r] = expf(v[r] - mx); sum += v[r]; }
    __syncthreads();
    sum = warpReduceSum(sum);
    if (lane == 0) red[wid] = sum;
    __syncthreads();
    if (wid == 0) {
        float r = (lane < 8) ? red[lane] : 0.f;
        r = warpReduceSum(r);
        if (lane == 0) bc = r;
    }
    __syncthreads();
    float inv = 1.f / bc;
#pragma unroll
    for (int r = 0; r < 4; r++) {
        int j = tid + r * 256;
        float y = v[r] * inv;
        row[j] = y;
        ath[rbase + j] = __float2half_rn(y);
    }
}

// ---------------- LayerNorm over D=256; optional fp16 output ----------------
__global__ void __launch_bounds__(256) ln_k(const float* __restrict__ in,
                                            const float* __restrict__ g,
                                            const float* __restrict__ bta,
                                            const unsigned char* __restrict__ mask,
                                            float* __restrict__ out,
                                            __half* __restrict__ oh)
{
    long n = blockIdx.x;
    int tid = threadIdx.x, lane = tid & 31, wid = tid >> 5;
    __shared__ float red[8];
    __shared__ float stats[2];

    float x = in[n * cD + tid];
    float s = warpReduceSum(x);
    if (lane == 0) red[wid] = s;
    __syncthreads();
    if (wid == 0) {
        float r = (lane < 8) ? red[lane] : 0.f;
        r = warpReduceSum(r);
        if (lane == 0) stats[0] = r;
    }
    __syncthreads();
    float s2 = warpReduceSum(x * x);
    if (lane == 0) red[wid] = s2;
    __syncthreads();
    if (wid == 0) {
        float r = (lane < 8) ? red[lane] : 0.f;
        r = warpReduceSum(r);
        if (lane == 0) stats[1] = r;
    }
    __syncthreads();
    float mean = stats[0] * (1.f / cD);
    float var  = stats[1] * (1.f / cD) - mean * mean;
    float y = (x - mean) * rsqrtf(var + LN_EPS) * g[tid] + bta[tid];
    if (mask[n]) y = 0.f;
    out[n * cD + tid] = y;
    if (oh) oh[n * cD + tid] = __float2half_rn(y);
}

// ---------------- fused small weight prep (one launch) ----------------
// tasks (blockIdx.y): 0 Wq split, 1 Wk split, 2 Wv split, 3 Wo split,
//   4 w1 cvt, 5 w2 cvt, 6 bkv pack + pwn-sum zero, 7 dwn (per-b block)
__device__ __forceinline__ void split4_at(const float* in, __half* oh, __half* ol, long i) {
    float4 v = *reinterpret_cast<const float4*>(in + i);
    __half h0, h1, h2, h3, l0, l1, l2, l3;
    split_h(v.x, h0, l0); split_h(v.y, h1, l1);
    split_h(v.z, h2, l2); split_h(v.w, h3, l3);
    __half2 ha = {h0, h1}, hb = {h2, h3}, la = {l0, l1}, lb = {l2, l3};
    *reinterpret_cast<__half2*>(oh + i)     = ha;
    *reinterpret_cast<__half2*>(oh + i + 2) = hb;
    *reinterpret_cast<__half2*>(ol + i)     = la;
    *reinterpret_cast<__half2*>(ol + i + 2) = lb;
}
__device__ __forceinline__ void cvt4_at(const float* in, __half* o, long i) {
    float4 v = *reinterpret_cast<const float4*>(in + i);
    __half2 a = {__float2half_rn(v.x), __float2half_rn(v.y)};
    __half2 b = {__float2half_rn(v.z), __float2half_rn(v.w)};
    *reinterpret_cast<__half2*>(o + i)     = a;
    *reinterpret_cast<__half2*>(o + i + 2) = b;
}

__global__ void __launch_bounds__(256) wprep_k(
    const float* __restrict__ Wq, const float* __restrict__ Wk,
    const float* __restrict__ Wv, const float* __restrict__ Wo,
    const float* __restrict__ w1, const float* __restrict__ w2,
    const float* __restrict__ bk, const float* __restrict__ bv,
    const float* __restrict__ d_w,
    __half* __restrict__ wqh, __half* __restrict__ wql,
    __half* __restrict__ wkvh, __half* __restrict__ wkvl,
    __half* __restrict__ woh, __half* __restrict__ wol,
    __half* __restrict__ w1h, __half* __restrict__ w2h,
    float* __restrict__ bkv, float* __restrict__ pwnsum,
    float* __restrict__ dwn)
{
    int task = blockIdx.y;
    long i = ((long)blockIdx.x * 256 + threadIdx.x) * 4;
    constexpr long SZp = (long)128 * cD;  // 32768
    constexpr long SZw = (long)cC * cD;   // 262144
    if (task == 0) { if (i < SZp) split4_at(Wq, wqh, wql, i); }
    else if (task == 1) { if (i < SZp) split4_at(Wk, wkvh, wkvl, i); }
    else if (task == 2) { if (i < SZp) split4_at(Wv, wkvh + SZp, wkvl + SZp, i); }
    else if (task == 3) { if (i < SZp) split4_at(Wo, woh, wol, i); }
    else if (task == 4) { if (i < SZw) cvt4_at(w1, w1h, i); }
    else if (task == 5) { if (i < SZw) cvt4_at(w2, w2h, i); }
    else if (task == 6) {
        long t = (long)blockIdx.x * 256 + threadIdx.x;
        if (t < 128) bkv[t] = bk[t];
        else if (t < 256) bkv[t] = bv[t - 128];
        if (t < (long)cB * cC) pwnsum[t] = 0.f;
    } else { // 7: per-b depthwise weight inverse norms
        int b = blockIdx.x;
        if (b >= cB) return;
        int tid = threadIdx.x, lane = tid & 31;
        __shared__ float red9[9];
        if (tid < 9) red9[tid] = 0.f;
        __syncthreads();
        float s[9];
#pragma unroll
        for (int k = 0; k < 9; k++) s[k] = 0.f;
        for (int c = tid; c < cC; c += 256) {
            const float* wr = d_w + ((long)b * cC + c) * 9;
#pragma unroll
            for (int k = 0; k < 9; k++) { float w = wr[k]; s[k] += w * w; }
        }
#pragma unroll
        for (int k = 0; k < 9; k++) {
            float r = warpReduceSum(s[k]);
            if (lane == 0) atomicAdd(&red9[k], r);
        }
        __syncthreads();
        if (tid < 9)
            dwn[b * 9 + tid] = 1.f / fmaxf(sqrtf(red9[tid]), 1e-12f);
    }
}

// ---------------- fp32 -> fp16 hi/lo split (x) ----------------
__global__ void __launch_bounds__(256) cvt_split_h(const float* __restrict__ in,
                                                   __half* __restrict__ oh,
                                                   __half* __restrict__ ol, long n)
{
    long i = ((long)blockIdx.x * 256 + threadIdx.x) * 4;
    if (i >= n) return;
    split4_at(in, oh, ol, i);
}

// ---------------- kv cols 128..255 -> vT [(b,h)][n(64)][t] fp16 single ----------------
__global__ void __launch_bounds__(256) vT_k(const __half* __restrict__ kvh,
                                            __half* __restrict__ vTh)
{
    __shared__ __half th[32][33];
    int b = blockIdx.z;
    int t0 = blockIdx.x * 32, c0 = blockIdx.y * 32;
    int tx = threadIdx.x & 31, ty = threadIdx.x >> 5;  // 32 x 8
#pragma unroll
    for (int i = 0; i < 4; i++) {
        int t = t0 + ty + i * 8;
        th[ty + i * 8][tx] = kvh[((long)b * cT + t) * 256 + 128 + c0 + tx];
    }
    __syncthreads();
#pragma unroll
    for (int i = 0; i < 4; i++) {
        int c = c0 + ty + i * 8;
        int h = c >> 6, n = c & 63;
        vTh[((long)((b << 1) | h) * 64 + n) * cT + t0 + tx] = th[tx][ty + i * 8];
    }
}

// ---------------- p_w transpose to fp16 + fused pwn column sums ----------------
__global__ void __launch_bounds__(256) cvtT_k(const float* __restrict__ in,
                                              __half* __restrict__ oT,
                                              float* __restrict__ pwnsum)
{
    __shared__ float tile[32][33];
    __shared__ float colsum[32];
    int b = blockIdx.z;
    int o0 = blockIdx.x * 32, c0 = blockIdx.y * 32;
    int tx = threadIdx.x & 31, ty = threadIdx.x >> 5;  // 32 x 8
    const float* src = in + (long)b * cC * cC;
    if (threadIdx.x < 32) colsum[threadIdx.x] = 0.f;
    float s = 0.f;
#pragma unroll
    for (int i = 0; i < 4; i++) {
        int c = c0 + ty + i * 8;
        float v = src[(long)c * cC + o0 + tx];
        tile[ty + i * 8][tx] = v;
        s += v * v;
    }
    __syncthreads();
    atomicAdd(&colsum[tx], s);
    __half* dst = oT + (long)b * cC * cC;
#pragma unroll
    for (int i = 0; i < 4; i++) {
        int o = o0 + ty + i * 8;
        dst[(long)o * cC + c0 + tx] = __float2half_rn(tile[tx][ty + i * 8]);
    }
    __syncthreads();
    if (ty == 0) atomicAdd(&pwnsum[(long)b * cC + o0 + tx], colsum[tx]);
}

// ---------------- finish pwn: sums -> inverse norms (in place) ----------------
__global__ void __launch_bounds__(256) pwn_fin(float* __restrict__ pwn)
{
    long i = (long)blockIdx.x * 256 + threadIdx.x;
    if (i < (long)cB * cC)
        pwn[i] = 1.f / fmaxf(sqrtf(pwn[i]), 1e-12f);
}

// ---------------- tiled depthwise conv (K=9): fp16 in, fp16 out ----------------
constexpr int CV_TR = 32;   // output t-rows per block
__global__ void __launch_bounds__(256) conv2_k(const __half* __restrict__ h,
                                               const float* __restrict__ d_w,
                                               const float* __restrict__ d_g,
                                               const float* __restrict__ d_b,
                                               const float* __restrict__ p_g,
                                               const float* __restrict__ dwn,
                                               __half* __restrict__ deph)
{
    __shared__ __half hs[CV_TR + 8][256];
    __shared__ float ws[9];
    int t0 = blockIdx.x * CV_TR, c0 = blockIdx.y * 256, b = blockIdx.z;
    int tid = threadIdx.x;
    if (tid < 9) ws[tid] = dwn[b * 9 + tid];
    __syncthreads();

#pragma unroll
    for (int i = tid; i < (CV_TR + 8) * 32; i += 256) {
        int r = i >> 5, q8 = i & 31;
        int t = t0 + r - 4;
        uint4 v = make_uint4(0u, 0u, 0u, 0u);
        if (t >= 0 && t < cT)
            v = *reinterpret_cast<const uint4*>(h + ((long)b * cT + t) * cC + c0 + q8 * 8);
        *reinterpret_cast<uint4*>(&hs[r][q8 * 8]) = v;
    }

    int c = c0 + tid;
    long bc = (long)b * cC + c;
    const float* wrow = d_w + bc * 9;
    float w[9];
#pragma unroll
    for (int k = 0; k < 9; k++) w[k] = wrow[k] * ws[k];
    float dg = d_g[bc], db = d_b[bc], pg = p_g[bc];
    __syncthreads();

#pragma unroll 4
    for (int tt = 0; tt < CV_TR; tt++) {
        float acc = 0.f;
#pragma unroll
        for (int k = 0; k < 9; k++) acc += __half2float(hs[tt + k][tid]) * w[k];
        float val = (acc * dg + db) * pg;
        deph[((long)b * cT + t0 + tt) * cC + c] = __float2half_rn(val);
    }
}

// ---------------- launch ----------------
extern "C" void kernel_launch(void* const* d_in, const int* in_sizes, int n_in,
                              void* d_out, int out_size)
{
    const float* x    = (const float*)d_in[0];
    const float* d_w  = (const float*)d_in[1];
    const float* d_g  = (const float*)d_in[2];
    const float* d_b  = (const float*)d_in[3];
    const float* p_w  = (const float*)d_in[4];
    const float* p_g  = (const float*)d_in[5];
    const float* p_b  = (const float*)d_in[6];
    const unsigned char* mask  = (const unsigned char*)d_in[7];
    const unsigned char* smask = (const unsigned char*)d_in[8];
    const float* Wq = (const float*)d_in[9];
    const float* bq = (const float*)d_in[10];
    const float* Wk = (const float*)d_in[11];
    const float* bk = (const float*)d_in[12];
    const float* Wv = (const float*)d_in[13];
    const float* bv = (const float*)d_in[14];
    const float* Wo = (const float*)d_in[15];
    const float* bo = (const float*)d_in[16];
    const float* g0 = (const float*)d_in[17];
    const float* b0 = (const float*)d_in[18];
    const float* w1_w = (const float*)d_in[19];
    const float* w1_b = (const float*)d_in[20];
    const float* w2_w = (const float*)d_in[21];
    const float* w2_b = (const float*)d_in[22];
    const float* g1 = (const float*)d_in[23];
    const float* b1 = (const float*)d_in[24];

    float* out  = (float*)d_out;
    float* attn = out + (long)cNT * cD;   // output tuple: (out[B,T,D], attn[B,H,T,T])

    float *apre, *a, *o2, *dwn, *pwn, *bkv;
    __half *xh, *xl, *qh, *ql, *kvh, *kvl, *vTh, *atth, *ctxh, *ctxl;
    __half *ah, *hh, *deph, *pth, *pwT, *w1h, *w2h;
    __half *wqh, *wql, *wkvh, *wkvl, *woh, *wol;
    cudaGetSymbolAddress((void**)&apre, g_apre);
    cudaGetSymbolAddress((void**)&a,    g_a);
    cudaGetSymbolAddress((void**)&o2,   g_o2);
    cudaGetSymbolAddress((void**)&dwn,  g_dwn);
    cudaGetSymbolAddress((void**)&pwn,  g_pwn);
    cudaGetSymbolAddress((void**)&bkv,  g_bkv);
    cudaGetSymbolAddress((void**)&xh,   g_xh);
    cudaGetSymbolAddress((void**)&xl,   g_xl);
    cudaGetSymbolAddress((void**)&qh,   g_qh);
    cudaGetSymbolAddress((void**)&ql,   g_ql);
    cudaGetSymbolAddress((void**)&kvh,  g_kvh);
    cudaGetSymbolAddress((void**)&kvl,  g_kvl);
    cudaGetSymbolAddress((void**)&vTh,  g_vTh);
    cudaGetSymbolAddress((void**)&atth, g_atth);
    cudaGetSymbolAddress((void**)&ctxh, g_ctxh);
    cudaGetSymbolAddress((void**)&ctxl, g_ctxl);
    cudaGetSymbolAddress((void**)&ah,   g_ah);
    cudaGetSymbolAddress((void**)&hh,   g_hh);
    cudaGetSymbolAddress((void**)&deph, g_deph);
    cudaGetSymbolAddress((void**)&pth,  g_pth);
    cudaGetSymbolAddress((void**)&pwT,  g_pwT);
    cudaGetSymbolAddress((void**)&w1h,  g_w1);
    cudaGetSymbolAddress((void**)&w2h,  g_w2);
    cudaGetSymbolAddress((void**)&wqh,  g_wq);
    cudaGetSymbolAddress((void**)&wql,  g_wql);
    cudaGetSymbolAddress((void**)&wkvh, g_wkv);
    cudaGetSymbolAddress((void**)&wkvl, g_wkvl);
    cudaGetSymbolAddress((void**)&woh,  g_wo);
    cudaGetSymbolAddress((void**)&wol,  g_wol);

    cudaFuncSetAttribute(mma_gemm1<2>,  cudaFuncAttributeMaxDynamicSharedMemorySize, MM_SMEM1);
    cudaFuncSetAttribute(mma_gemm1<9>,  cudaFuncAttributeMaxDynamicSharedMemorySize, MM_SMEM1);
    cudaFuncSetAttribute(mma_gemm1<10>, cudaFuncAttributeMaxDynamicSharedMemorySize, MM_SMEM1);
    cudaFuncSetAttribute(mma_gemm1s<8>, cudaFuncAttributeMaxDynamicSharedMemorySize, MM_SMEM1N);
    cudaFuncSetAttribute(mma_gemm3<2>, cudaFuncAttributeMaxDynamicSharedMemorySize, MM_SMEM3);
    cudaFuncSetAttribute(mma_gemm3<5>, cudaFuncAttributeMaxDynamicSharedMemorySize, MM_SMEM3);
    cudaFuncSetAttribute(mma_gemm3<6>, cudaFuncAttributeMaxDynamicSharedMemorySize, MM_SMEM3);

    dim3 blk(256);

    // 0) prep (fused: weight cvt/splits, bkv, pwn zero, dwn)
    wprep_k<<<dim3(256, 8), blk>>>(Wq, Wk, Wv, Wo, w1_w, w2_w, bk, bv, d_w,
                                   wqh, wql, wkvh, wkvl, woh, wol, w1h, w2h, bkv, pwn, dwn);
    cvtT_k<<<dim3(32, 32, cB), blk>>>(p_w, pwT, pwn);
    pwn_fin<<<(cB * cC) / 256, blk>>>(pwn);
    cvt_split_h<<<(cNT * cD) / 1024, blk>>>(x, xh, xl, (long)cNT * cD);

    // 1) q (split out, 3-product)
    mma_gemm3<6><<<dim3(1, cNT / 128, 1), blk, MM_SMEM3>>>(
        xh, xl, wqh, wql, nullptr, qh, ql, cD, cD, cD, 128, 128, 1,
        0, 0, 0, 0, 0, 0, 0, 0, bq, nullptr);
    // 2) kv fused (split out, 3-product)
    mma_gemm3<6><<<dim3(2, cNT / 128, 1), blk, MM_SMEM3>>>(
        xh, xl, wkvh, wkvl, nullptr, kvh, kvl, cD, cD, cD, 256, 256, 1,
        0, 0, 0, 0, 0, 0, 0, 0, bkv, nullptr);

    // 3) v -> vT (fp16 single, compact 64 rows per (b,h))
    vT_k<<<dim3(32, 4, cB), blk>>>(kvh, vTh);

    // 4) scores = q k^T / 8  [3-product, z=(b,h) zdiv=2]
    mma_gemm3<5><<<dim3(8, 8, 32), blk, MM_SMEM3>>>(
        qh, ql, kvh, kvl, attn, nullptr, nullptr, cDK, 128, 256, cT, 1024, 2,
        (long)cT * 128, 64, (long)cT * 256, 64, 2 * cTT, cTT, 0, 0, nullptr, nullptr);

    // 5) masked softmax (writes final attn + fp16 single)
    softmax_k<<<dim3(cT, cH, cB), blk>>>(attn, smask, atth);

    // 6) ctx = attn @ v  [1-product, BN=64] -> exact fp16 split of fp32 result
    mma_gemm1s<8><<<dim3(1, 8, 32), blk, MM_SMEM1N>>>(
        atth, vTh, ctxh, ctxl, cT, cT, cT, 128, 64, 2,
        2 * cTT, cTT, (long)128 * cT, (long)64 * cT, (long)cT * 128, 64);

    // 7) apre = ctx @ Wo^T + bo + x  [3-product]
    mma_gemm3<2><<<dim3(2, cNT / 128, 1), blk, MM_SMEM3>>>(
        ctxh, ctxl, woh, wol, apre, nullptr, nullptr, 128, 128, 128, cD, 256, 1,
        0, 0, 0, 0, 0, 0, 0, 0, bo, x);

    // 8) a = LN(apre), masked; emit fp16 single
    ln_k<<<cNT, blk>>>(apre, g0, b0, mask, a, ah);

    // 9) h = mish(a @ w1^T + w1_b) -> fp16 single  [1-product, 3-stage, occ 2]
    mma_gemm1<9><<<dim3(cC / 128, cNT / 128, 1), blk, MM_SMEM1>>>(
        ah, w1h, nullptr, hh, cD, cD, cD, cC, 1024, 1,
        0, 0, 0, 0, 0, 0, 0, 0, w1_b, nullptr);

    // 10) tiled depthwise conv (fp16 in/out)
    conv2_k<<<dim3(cT / CV_TR, cC / 256, cB), blk>>>(hh, d_w, d_g, d_b, p_g, dwn, deph);

    // 11) pt = (dep @ pwT) * pwninv[o] + p_b -> fp16 single  [1-product, batched over b]
    mma_gemm1<10><<<dim3(cC / 128, cT / 128, cB), blk, MM_SMEM1>>>(
        deph, pwT, nullptr, pth, cC, cC, cC, cC, 1024, 1,
        (long)cT * cC, 0, (long)cC * cC, 0, (long)cT * cC, 0, cC, cC, p_b, pwn);

    // 12) o2 = pt @ w2^T + w2_b + a  [1-product]
    mma_gemm1<2><<<dim3(cD / 128, cNT / 128, 1), blk, MM_SMEM1>>>(
        pth, w2h, o2, nullptr, cC, cC, cC, cD, 256, 1,
        0, 0, 0, 0, 0, 0, 0, 0, w2_b, a);

    // 13) out = LN(o2), masked
    ln_k<<<cNT, blk>>>(o2, g1, b1, mask, out, nullptr);
}

// round 14
// speedup vs baseline: 3.9999x; 1.0188x over previous
#include <cuda_runtime.h>
#include <cuda_fp16.h>
#include <cstdint>
#include <math.h>

// ---------------- problem constants ----------------
constexpr int cB = 16, cT = 1024, cD = 256, cH = 2, cDK = 64, cC = 1024;
constexpr int cNT = cB * cT;            // 16384 tokens
constexpr long cTT = (long)cT * cT;     // 1M
constexpr float LN_EPS = 1e-5f;

// ---------------- device scratch (no allocs allowed) ----------------
__device__ float g_apre[cNT * cD];
__device__ float g_a   [cNT * cD];
__device__ float g_o2 [cNT * cD];
__device__ float g_dwn[cB * 9];
__device__ float g_pwn[cB * cC];        // first: sum of squares (atomic), then inv-norm in place
__device__ float g_bqkv[384];
// fp16 buffers
__device__ __half g_xh  [cNT * cD];
__device__ __half g_xl  [cNT * cD];
__device__ __half g_qkvh[cNT * 384];
__device__ __half g_qkvl[cNT * 384];
__device__ __half g_vTh [(long)cB * cH * 64 * cT];    // compact 64 rows per (b,h)
__device__ __half g_atth[(long)cB * cH * cTT];
__device__ __half g_ctxh[cNT * 128];
__device__ __half g_ctxl[cNT * 128];
__device__ __half g_ah  [cNT * cD];
__device__ __half g_hh  [cNT * cC];
__device__ __half g_deph[cNT * cC];
__device__ __half g_pth [cNT * cC];
__device__ __half g_pwT [(long)cB * cC * cC];
__device__ __half g_w1  [cC * cD];
__device__ __half g_w2  [cD * cC];
__device__ __half g_wqkv [384 * cD];
__device__ __half g_wqkvl[384 * cD];
__device__ __half g_wo  [cD * 128];
__device__ __half g_wol [cD * 128];

// ---------------- helpers ----------------
__device__ __forceinline__ uint32_t smem_u32(const void* p) {
    uint32_t a;
    asm("{ .reg .u64 t; cvta.to.shared.u64 t, %1; cvt.u32.u64 %0, t; }" : "=r"(a) : "l"(p));
    return a;
}
#define SW128(off) ((off) ^ (((off) >> 3) & 0x70))

__device__ __forceinline__ void split_h(float v, __half& h, __half& l) {
    h = __float2half_rn(v);
    l = __float2half_rn(v - __half2float(h));
}

__device__ __forceinline__ void ldsm4(uint32_t* r, uint32_t addr) {
    asm volatile("ldmatrix.sync.aligned.m8n8.x4.shared.b16 {%0,%1,%2,%3}, [%4];"
        : "=r"(r[0]), "=r"(r[1]), "=r"(r[2]), "=r"(r[3]) : "r"(addr));
}
__device__ __forceinline__ void mma16816(float* d, const uint32_t* a, const uint32_t* b) {
    asm volatile("mma.sync.aligned.m16n8k16.row.col.f32.f16.f16.f32 "
        "{%0,%1,%2,%3}, {%4,%5,%6,%7}, {%8,%9}, {%0,%1,%2,%3};"
        : "+f"(d[0]), "+f"(d[1]), "+f"(d[2]), "+f"(d[3])
        : "r"(a[0]), "r"(a[1]), "r"(a[2]), "r"(a[3]), "r"(b[0]), "r"(b[1]));
}
__device__ __forceinline__ void cp16(uint32_t saddr, const void* gptr) {
    asm volatile("cp.async.cg.shared.global [%0], [%1], 16;"
        :: "r"(saddr), "l"(__cvta_generic_to_global(gptr)));
}
__device__ __forceinline__ void cp_commit() {
    asm volatile("cp.async.commit_group;");
}
template<int N>
__device__ __forceinline__ void cp_wait() {
    asm volatile("cp.async.wait_group %0;" :: "n"(N));
}

__device__ __forceinline__ float warpReduceSum(float v) {
#pragma unroll
    for (int o = 16; o > 0; o >>= 1) v += __shfl_xor_sync(0xffffffffu, v, o);
    return v;
}
__device__ __forceinline__ float warpReduceMax(float v) {
#pragma unroll
    for (int o = 16; o > 0; o >>= 1) v = fmaxf(v, __shfl_xor_sync(0xffffffffu, v, o));
    return v;
}

// ---------------- mma.sync fp16 GEMM body ----------------
// D[M,N] = A[M,K] @ B[N,K]^T.  Tile 128 x BN (BN=128 or 64), BK=64.
// NPROD=1: A,B single fp16 (3-stage).  NPROD=3: A and B split (2-stage).
// Per-warp: wm=M quarter (32 rows), wn=N half (BN/2 cols = NBT subtiles of 16).
// EPI: 2 = +bias[n]+aux residual -> f32 | 5 = acc*0.125 -> f32
//      6 = +bias -> fp16 split | 8 = raw -> fp16 split
//      9 = mish(acc+bias) -> fp16 single | 10 = acc*aux[n]+bias[n] -> fp16 single
constexpr int MM_SMEM1  = 3 * 32768 + 1024;            // 1-prod, BN=128, 3 stages
constexpr int MM_SMEM1N = 3 * 24576 + 1024;            // 1-prod, BN=64,  3 stages
constexpr int MM_SMEM3  = 2 * 65536 + 1024;            // 3-prod, BN=128, 2 stages
constexpr int MM_SMEM3S = 1 * 65536 + 1024;            // 3-prod, BN=128, nk=1 (scores)

template<int EPI, int NPROD, int BN>
__device__ __forceinline__ void mma_body(
    const __half* __restrict__ Ah, const __half* __restrict__ Al,
    const __half* __restrict__ Bh, const __half* __restrict__ Bl,
    float* __restrict__ C, __half* __restrict__ Ch, __half* __restrict__ Cl,
    int Kd, int lda, int ldb, int ldc, int nLim, int zdiv,
    long aQ, long aR, long bQ, long bR, long cQ, long cR,
    long biasZ, long auxZ,
    const float* __restrict__ bias, const float* __restrict__ aux)
{
    constexpr int ASZ  = 16384;            // 128 rows x 64 cols fp16
    constexpr int BSZ  = BN * 128;
    constexpr int NAt  = (NPROD >= 2) ? 2 : 1;
    constexpr int NBt  = (NPROD == 3) ? 2 : 1;
    constexpr int BOFF = NAt * ASZ;
    constexpr int STAGE = NAt * ASZ + NBt * BSZ;
    constexpr int NSTG  = (NPROD == 1) ? 3 : 2;
    constexpr int NBT   = BN / 32;         // 16-col subtiles per warp-half (4 or 2)
    extern __shared__ char sm_raw[];
    uint32_t sb0 = smem_u32(sm_raw);
    uint32_t sb  = (sb0 + 1023u) & ~1023u;

    int z = blockIdx.z;
    int zq = z / zdiv, zr = z - zq * zdiv;
    long aoff = (long)zq * aQ + (long)zr * aR;
    long boff = (long)zq * bQ + (long)zr * bR;
    long coff = (long)zq * cQ + (long)zr * cR;
    Ah += aoff;
    if (NPROD >= 2) Al += aoff;
    Bh += boff;
    if (NPROD == 3) Bl += boff;
    if (C)  C  += coff;
    if (Ch) Ch += coff;
    if (Cl) Cl += coff;
    const float* biasp = bias ? bias + (long)zq * biasZ : nullptr;
    const float* auxp  = aux  ? aux  + (long)zq * auxZ  : nullptr;

    int m0 = blockIdx.y * 128, n0 = blockIdx.x * BN;
    int tid = threadIdx.x, wid = tid >> 5, lane = tid & 31;
    int wm = wid & 3, wn = wid >> 2;

    int lrow = tid >> 3, lcq = tid & 7;

    auto issue_stage = [&](int k0, uint32_t sbase) {
#pragma unroll
        for (int ti = 0; ti < 4; ti++) {
            int row = lrow + ti * 32;
            uint32_t soff = SW128((uint32_t)(row * 128 + lcq * 16));
            long ga = (long)(m0 + row) * lda + k0 + lcq * 8;
            cp16(sbase + soff, Ah + ga);
            if (NPROD >= 2) cp16(sbase + ASZ + soff, Al + ga);
        }
#pragma unroll
        for (int ti = 0; ti < BN / 32; ti++) {
            int row = lrow + ti * 32;
            uint32_t soff = SW128((uint32_t)(row * 128 + lcq * 16));
            long gb = (long)(n0 + row) * ldb + k0 + lcq * 8;
            cp16(sbase + BOFF + soff, Bh + gb);
            if (NPROD == 3) cp16(sbase + BOFF + BSZ + soff, Bl + gb);
        }
        cp_commit();
    };

    float acc[2][BN / 16][4];
#pragma unroll
    for (int i = 0; i < 2; i++)
#pragma unroll
        for (int j = 0; j < BN / 16; j++)
#pragma unroll
            for (int l = 0; l < 4; l++) acc[i][j][l] = 0.f;

    int nk = Kd >> 6;
#pragma unroll
    for (int s = 0; s < NSTG - 1; s++)
        if (s < nk) issue_stage(s << 6, sb + (uint32_t)s * STAGE);

    for (int i = 0; i < nk; i++) {
        uint32_t cur = sb + (uint32_t)(i % NSTG) * STAGE;
        int j = i + NSTG - 1;
        if (j < nk) issue_stage(j << 6, sb + (uint32_t)(j % NSTG) * STAGE);
        int rem = nk - 1 - i;
        if (NSTG == 3) {
            if (rem >= 2) cp_wait<2>();
            else if (rem == 1) cp_wait<1>();
            else cp_wait<0>();
        } else {
            if (rem >= 1) cp_wait<1>();
            else cp_wait<0>();
        }
        __syncthreads();

        uint32_t uAh = cur, uAl = cur + ASZ, uBh = cur + BOFF, uBl = cur + BOFF + BSZ;
#pragma unroll
        for (int ks = 0; ks < 4; ks++) {
            uint32_t afh[2][4], afl[2][4], bfh[NBT][4], bfl[NBT][4];
#pragma unroll
            for (int mt = 0; mt < 2; mt++) {
                int r = wm * 32 + mt * 16 + (lane & 15);
                int kc = ks * 2 + (lane >> 4);
                uint32_t off = SW128((uint32_t)(r * 128 + kc * 16));
                ldsm4(afh[mt], uAh + off);
                if (NPROD >= 2) ldsm4(afl[mt], uAl + off);
            }
#pragma unroll
            for (int bt = 0; bt < NBT; bt++) {
                int r = wn * (BN / 2) + bt * 16 + (lane & 7) + ((lane >> 4) << 3);
                int kc = ks * 2 + ((lane >> 3) & 1);
                uint32_t off = SW128((uint32_t)(r * 128 + kc * 16));
                ldsm4(bfh[bt], uBh + off);
                if (NPROD == 3) ldsm4(bfl[bt], uBl + off);
            }
#pragma unroll
            for (int p = 0; p < NPROD; p++)
#pragma unroll
                for (int mt = 0; mt < 2; mt++)
#pragma unroll
                    for (int bt = 0; bt < NBT; bt++)
#pragma unroll
                        for (int hh = 0; hh < 2; hh++) {
                            const uint32_t* af  = (p == 1) ? afl[mt] : afh[mt];
                            const uint32_t* bfp = (p == 2) ? &bfl[bt][hh * 2] : &bfh[bt][hh * 2];
                            mma16816(acc[mt][bt * 2 + hh], af, bfp);
                        }
        }
        __syncthreads();
    }

    // epilogue
#pragma unroll
    for (int mt = 0; mt < 2; mt++)
#pragma unroll
        for (int bt = 0; bt < NBT; bt++)
#pragma unroll
            for (int hh = 0; hh < 2; hh++) {
                float* d = acc[mt][bt * 2 + hh];
                int col = n0 + wn * (BN / 2) + bt * 16 + hh * 8 + (lane & 3) * 2;
                int r0  = m0 + wm * 32 + mt * 16 + (lane >> 2);
                if (col >= nLim) continue;
#pragma unroll
                for (int half = 0; half < 2; half++) {
                    int row = r0 + half * 8;
                    float t0 = d[half * 2 + 0], t1 = d[half * 2 + 1];
                    if (EPI == 2) {
                        t0 += biasp[col]     + auxp[(long)row * ldc + col];
                        t1 += biasp[col + 1] + auxp[(long)row * ldc + col + 1];
                        float2 v = {t0, t1};
                        *reinterpret_cast<float2*>(C + (long)row * ldc + col) = v;
                    } else if (EPI == 5) {
                        float2 v = {t0 * 0.125f, t1 * 0.125f};
                        *reinterpret_cast<float2*>(C + (long)row * ldc + col) = v;
                    } else if (EPI == 9) {
                        t0 += biasp[col];
                        t1 += biasp[col + 1];
                        float sp0 = (t0 > 20.f) ? t0 : log1pf(expf(t0));
                        float sp1 = (t1 > 20.f) ? t1 : log1pf(expf(t1));
                        t0 = t0 * tanhf(sp0);
                        t1 = t1 * tanhf(sp1);
                        __half2 hv = {__float2half_rn(t0), __float2half_rn(t1)};
                        *reinterpret_cast<__half2*>(Ch + (long)row * ldc + col) = hv;
                    } else if (EPI == 10) {
                        t0 = t0 * auxp[col]     + biasp[col];
                        t1 = t1 * auxp[col + 1] + biasp[col + 1];
                        __half2 hv = {__float2half_rn(t0), __float2half_rn(t1)};
                        *reinterpret_cast<__half2*>(Ch + (long)row * ldc + col) = hv;
                    } else { // 6, 8: fp16 split outputs
                        if (EPI == 6) {
                            t0 += biasp[col];
                            t1 += biasp[col + 1];
                        }
                        __half h0, l0, h1, l1;
                        split_h(t0, h0, l0);
                        split_h(t1, h1, l1);
                        __half2 hv = {h0, h1}, lv = {l0, l1};
                        *reinterpret_cast<__half2*>(Ch + (long)row * ldc + col) = hv;
                        *reinterpret_cast<__half2*>(Cl + (long)row * ldc + col) = lv;
                    }
                }
            }
}

template<int EPI>
__global__ void __launch_bounds__(256, 2) mma_gemm1(
    const __half* __restrict__ Ah, const __half* __restrict__ Bh,
    float* __restrict__ C, __half* __restrict__ Ch,
    int Kd, int lda, int ldb, int ldc, int nLim, int zdiv,
    long aQ, long aR, long bQ, long bR, long cQ, long cR,
    long biasZ, long auxZ,
    const float* __restrict__ bias, const float* __restrict__ aux)
{
    mma_body<EPI, 1, 128>(Ah, nullptr, Bh, nullptr, C, Ch, nullptr, Kd, lda, ldb, ldc, nLim, zdiv,
                          aQ, aR, bQ, bR, cQ, cR, biasZ, auxZ, bias, aux);
}

// 1-product, BN=64, split fp16 output (for ctx)
template<int EPI>
__global__ void __launch_bounds__(256, 2) mma_gemm1s(
    const __half* __restrict__ Ah, const __half* __restrict__ Bh,
    __half* __restrict__ Ch, __half* __restrict__ Cl,
    int Kd, int lda, int ldb, int ldc, int nLim, int zdiv,
    long aQ, long aR, long bQ, long bR, long cQ, long cR)
{
    mma_body<EPI, 1, 64>(Ah, nullptr, Bh, nullptr, nullptr, Ch, Cl, Kd, lda, ldb, ldc, nLim, zdiv,
                         aQ, aR, bQ, bR, cQ, cR, 0, 0, nullptr, nullptr);
}

template<int EPI>
__global__ void __launch_bounds__(256) mma_gemm3(
    const __half* __restrict__ Ah, const __half* __restrict__ Al,
    const __half* __restrict__ Bh, const __half* __restrict__ Bl,
    float* __restrict__ C, __half* __restrict__ Ch, __half* __restrict__ Cl,
    int Kd, int lda, int ldb, int ldc, int nLim, int zdiv,
    long aQ, long aR, long bQ, long bR, long cQ, long cR,
    long biasZ, long auxZ,
    const float* __restrict__ bias, const float* __restrict__ aux)
{
    mma_body<EPI, 3, 128>(Ah, Al, Bh, Bl, C, Ch, Cl, Kd, lda, ldb, ldc, nLim, zdiv,
                          aQ, aR, bQ, bR, cQ, cR, biasZ, auxZ, bias, aux);
}

// scores-specific: reg-capped for 2 CTAs/SM, launched with 1-stage smem (nk=1)
template<int EPI>
__global__ void __launch_bounds__(256, 2) mma_gemm3sc(
    const __half* __restrict__ Ah, const __half* __restrict__ Al,
    const __half* __restrict__ Bh, const __half* __restrict__ Bl,
    float* __restrict__ C,
    int Kd, int lda, int ldb, int ldc, int nLim, int zdiv,
    long aQ, long aR, long bQ, long bR, long cQ, long cR)
{
    mma_body<EPI, 3, 128>(Ah, Al, Bh, Bl, C, nullptr, nullptr, Kd, lda, ldb, ldc, nLim, zdiv,
                          aQ, aR, bQ, bR, cQ, cR, 0, 0, nullptr, nullptr);
}

// ---------------- softmax (in place; emits fp16 single) ----------------
__global__ void __launch_bounds__(256) softmax_k(float* __restrict__ attn,
                                                 const unsigned char* __restrict__ smask,
                                                 __half* __restrict__ ath)
{
    int i = blockIdx.x, h = blockIdx.y, b = blockIdx.z;
    long rbase = (((long)(b * cH + h)) * cT + i) * cT;
    float* row = attn + rbase;
    const unsigned char* mrow = smask + ((long)b * cT + i) * cT;
    int tid = threadIdx.x, lane = tid & 31, wid = tid >> 5;
    __shared__ float red[8];
    __shared__ float bc;

    float v[4];
    float mx = -3.4e38f;
#pragma unroll
    for (int r = 0; r < 4; r++) {
        int j = tid + r * 256;
        float s = row[j];
        if (mrow[j]) s = -1e9f;
        v[r] = s;
        mx = fmaxf(mx, s);
    }
    mx = warpReduceMax(mx);
    if (lane == 0) red[wid] = mx;
    __syncthreads();
    if (wid == 0) {
        float r = (lane < 8) ? red[lane] : -3.4e38f;
        r = warpReduceMax(r);
        if (lane == 0) bc = r;
    }
    __syncthreads();
    mx = bc;
    float sum = 0.f;
#pragma unroll
    for (int r = 0; r < 4; r++) { v[r] = expf(v[r] - mx); sum += v[r]; }
    __syncthreads();
    sum = warpReduceSum(sum);
    if (lane == 0) red[wid] = sum;
    __syncthreads();
    if (wid == 0) {
        float r = (lane < 8) ? red[lane] : 0.f;
        r = warpReduceSum(r);
        if (lane == 0) bc = r;
    }
    __syncthreads();
    float inv = 1.f / bc;
#pragma unroll
    for (int r = 0; r < 4; r++) {
        int j = tid + r * 256;
        float y = v[r] * inv;
        row[j] = y;
        ath[rbase + j] = __float2half_rn(y);
    }
}

// ---------------- LayerNorm over D=256; optional fp16 output ----------------
__global__ void __launch_bounds__(256) ln_k(const float* __restrict__ in,
                                            const float* __restrict__ g,
                                            const float* __restrict__ bta,
                                            const unsigned char* __restrict__ mask,
                                            float* __restrict__ out,
                                            __half* __restrict__ oh)
{
    long n = blockIdx.x;
    int tid = threadIdx.x, lane = tid & 31, wid = tid >> 5;
    __shared__ float red[8];
    __shared__ float stats[2];

    float x = in[n * cD + tid];
    float s = warpReduceSum(x);
    if (lane == 0) red[wid] = s;
    __syncthreads();
    if (wid == 0) {
        float r = (lane < 8) ? red[lane] : 0.f;
        r = warpReduceSum(r);
        if (lane == 0) stats[0] = r;
    }
    __syncthreads();
    float s2 = warpReduceSum(x * x);
    if (lane == 0) red[wid] = s2;
    __syncthreads();
    if (wid == 0) {
        float r = (lane < 8) ? red[lane] : 0.f;
        r = warpReduceSum(r);
        if (lane == 0) stats[1] = r;
    }
    __syncthreads();
    float mean = stats[0] * (1.f / cD);
    float var  = stats[1] * (1.f / cD) - mean * mean;
    float y = (x - mean) * rsqrtf(var + LN_EPS) * g[tid] + bta[tid];
    if (mask[n]) y = 0.f;
    out[n * cD + tid] = y;
    if (oh) oh[n * cD + tid] = __float2half_rn(y);
}

// ---------------- fused small weight prep (one launch) ----------------
// tasks (blockIdx.y): 0 Wq split, 1 Wk split, 2 Wv split, 3 Wo split,
//   4 w1 cvt, 5 w2 cvt, 6 bqkv pack + pwn-sum zero, 7 dwn (per-b block)
__device__ __forceinline__ void split4_at(const float* in, __half* oh, __half* ol, long i) {
    float4 v = *reinterpret_cast<const float4*>(in + i);
    __half h0, h1, h2, h3, l0, l1, l2, l3;
    split_h(v.x, h0, l0); split_h(v.y, h1, l1);
    split_h(v.z, h2, l2); split_h(v.w, h3, l3);
    __half2 ha = {h0, h1}, hb = {h2, h3}, la = {l0, l1}, lb = {l2, l3};
    *reinterpret_cast<__half2*>(oh + i)     = ha;
    *reinterpret_cast<__half2*>(oh + i + 2) = hb;
    *reinterpret_cast<__half2*>(ol + i)     = la;
    *reinterpret_cast<__half2*>(ol + i + 2) = lb;
}
__device__ __forceinline__ void cvt4_at(const float* in, __half* o, long i) {
    float4 v = *reinterpret_cast<const float4*>(in + i);
    __half2 a = {__float2half_rn(v.x), __float2half_rn(v.y)};
    __half2 b = {__float2half_rn(v.z), __float2half_rn(v.w)};
    *reinterpret_cast<__half2*>(o + i)     = a;
    *reinterpret_cast<__half2*>(o + i + 2) = b;
}

__global__ void __launch_bounds__(256) wprep_k(
    const float* __restrict__ Wq, const float* __restrict__ Wk,
    const float* __restrict__ Wv, const float* __restrict__ Wo,
    const float* __restrict__ w1, const float* __restrict__ w2,
    const float* __restrict__ bq, const float* __restrict__ bk,
    const float* __restrict__ bv,
    const float* __restrict__ d_w,
    __half* __restrict__ wqkvh, __half* __restrict__ wqkvl,
    __half* __restrict__ woh, __half* __restrict__ wol,
    __half* __restrict__ w1h, __half* __restrict__ w2h,
    float* __restrict__ bqkv, float* __restrict__ pwnsum,
    float* __restrict__ dwn)
{
    int task = blockIdx.y;
    long i = ((long)blockIdx.x * 256 + threadIdx.x) * 4;
    constexpr long SZp = (long)128 * cD;  // 32768
    constexpr long SZw = (long)cC * cD;   // 262144
    if (task == 0) { if (i < SZp) split4_at(Wq, wqkvh, wqkvl, i); }
    else if (task == 1) { if (i < SZp) split4_at(Wk, wqkvh + SZp, wqkvl + SZp, i); }
    else if (task == 2) { if (i < SZp) split4_at(Wv, wqkvh + 2 * SZp, wqkvl + 2 * SZp, i); }
    else if (task == 3) { if (i < SZp) split4_at(Wo, woh, wol, i); }
    else if (task == 4) { if (i < SZw) cvt4_at(w1, w1h, i); }
    else if (task == 5) { if (i < SZw) cvt4_at(w2, w2h, i); }
    else if (task == 6) {
        long t = (long)blockIdx.x * 256 + threadIdx.x;
        if (t < 128) bqkv[t] = bq[t];
        else if (t < 256) bqkv[t] = bk[t - 128];
        else if (t < 384) bqkv[t] = bv[t - 256];
        if (t < (long)cB * cC) pwnsum[t] = 0.f;
    } else { // 7: per-b depthwise weight inverse norms
        int b = blockIdx.x;
        if (b >= cB) return;
        int tid = threadIdx.x, lane = tid & 31;
        __shared__ float red9[9];
        if (tid < 9) red9[tid] = 0.f;
        __syncthreads();
        float s[9];
#pragma unroll
        for (int k = 0; k < 9; k++) s[k] = 0.f;
        for (int c = tid; c < cC; c += 256) {
            const float* wr = d_w + ((long)b * cC + c) * 9;
#pragma unroll
            for (int k = 0; k < 9; k++) { float w = wr[k]; s[k] += w * w; }
        }
#pragma unroll
        for (int k = 0; k < 9; k++) {
            float r = warpReduceSum(s[k]);
            if (lane == 0) atomicAdd(&red9[k], r);
        }
        __syncthreads();
        if (tid < 9)
            dwn[b * 9 + tid] = 1.f / fmaxf(sqrtf(red9[tid]), 1e-12f);
    }
}

// ---------------- fp32 -> fp16 hi/lo split (x) ----------------
__global__ void __launch_bounds__(256) cvt_split_h(const float* __restrict__ in,
                                                   __half* __restrict__ oh,
                                                   __half* __restrict__ ol, long n)
{
    long i = ((long)blockIdx.x * 256 + threadIdx.x) * 4;
    if (i >= n) return;
    split4_at(in, oh, ol, i);
}

// ---------------- qkv cols 256..383 (v) -> vT [(b,h)][n(64)][t] fp16 single ----------------
__global__ void __launch_bounds__(256) vT_k(const __half* __restrict__ qkvh,
                                            __half* __restrict__ vTh)
{
    __shared__ __half th[32][33];
    int b = blockIdx.z;
    int t0 = blockIdx.x * 32, c0 = blockIdx.y * 32;
    int tx = threadIdx.x & 31, ty = threadIdx.x >> 5;  // 32 x 8
#pragma unroll
    for (int i = 0; i < 4; i++) {
        int t = t0 + ty + i * 8;
        th[ty + i * 8][tx] = qkvh[((long)b * cT + t) * 384 + 256 + c0 + tx];
    }
    __syncthreads();
#pragma unroll
    for (int i = 0; i < 4; i++) {
        int c = c0 + ty + i * 8;
        int h = c >> 6, n = c & 63;
        vTh[((long)((b << 1) | h) * 64 + n) * cT + t0 + tx] = th[tx][ty + i * 8];
    }
}

// ---------------- p_w transpose to fp16 + fused pwn column sums ----------------
__global__ void __launch_bounds__(256) cvtT_k(const float* __restrict__ in,
                                              __half* __restrict__ oT,
                                              float* __restrict__ pwnsum)
{
    __shared__ float tile[32][33];
    __shared__ float colsum[32];
    int b = blockIdx.z;
    int o0 = blockIdx.x * 32, c0 = blockIdx.y * 32;
    int tx = threadIdx.x & 31, ty = threadIdx.x >> 5;  // 32 x 8
    const float* src = in + (long)b * cC * cC;
    if (threadIdx.x < 32) colsum[threadIdx.x] = 0.f;
    float s = 0.f;
#pragma unroll
    for (int i = 0; i < 4; i++) {
        int c = c0 + ty + i * 8;
        float v = src[(long)c * cC + o0 + tx];
        tile[ty + i * 8][tx] = v;
        s += v * v;
    }
    __syncthreads();
    atomicAdd(&colsum[tx], s);
    __half* dst = oT + (long)b * cC * cC;
#pragma unroll
    for (int i = 0; i < 4; i++) {
        int o = o0 + ty + i * 8;
        dst[(long)o * cC + c0 + tx] = __float2half_rn(tile[tx][ty + i * 8]);
    }
    __syncthreads();
    if (ty == 0) atomicAdd(&pwnsum[(long)b * cC + o0 + tx], colsum[tx]);
}

// ---------------- finish pwn: sums -> inverse norms (in place) ----------------
__global__ void __launch_bounds__(256) pwn_fin(float* __restrict__ pwn)
{
    long i = (long)blockIdx.x * 256 + threadIdx.x;
    if (i < (long)cB * cC)
        pwn[i] = 1.f / fmaxf(sqrtf(pwn[i]), 1e-12f);
}

// ---------------- tiled depthwise conv (K=9): fp16 in, fp16 out ----------------
constexpr int CV_TR = 32;   // output t-rows per block
__global__ void __launch_bounds__(256) conv2_k(const __half* __restrict__ h,
                                               const float* __restrict__ d_w,
                                               const float* __restrict__ d_g,
                                               const float* __restrict__ d_b,
                                               const float* __restrict__ p_g,
                                               const float* __restrict__ dwn,
                                               __half* __restrict__ deph)
{
    __shared__ __half hs[CV_TR + 8][256];
    __shared__ float ws[9];
    int t0 = blockIdx.x * CV_TR, c0 = blockIdx.y * 256, b = blockIdx.z;
    int tid = threadIdx.x;
    if (tid < 9) ws[tid] = dwn[b * 9 + tid];
    __syncthreads();

#pragma unroll
    for (int i = tid; i < (CV_TR + 8) * 32; i += 256) {
        int r = i >> 5, q8 = i & 31;
        int t = t0 + r - 4;
        uint4 v = make_uint4(0u, 0u, 0u, 0u);
        if (t >= 0 && t < cT)
            v = *reinterpret_cast<const uint4*>(h + ((long)b * cT + t) * cC + c0 + q8 * 8);
        *reinterpret_cast<uint4*>(&hs[r][q8 * 8]) = v;
    }

    int c = c0 + tid;
    long bc = (long)b * cC + c;
    const float* wrow = d_w + bc * 9;
    float w[9];
#pragma unroll
    for (int k = 0; k < 9; k++) w[k] = wrow[k] * ws[k];
    float dg = d_g[bc], db = d_b[bc], pg = p_g[bc];
    __syncthreads();

#pragma unroll 4
    for (int tt = 0; tt < CV_TR; tt++) {
        float acc = 0.f;
#pragma unroll
        for (int k = 0; k < 9; k++) acc += __half2float(hs[tt + k][tid]) * w[k];
        float val = (acc * dg + db) * pg;
        deph[((long)b * cT + t0 + tt) * cC + c] = __float2half_rn(val);
    }
}

// ---------------- launch ----------------
extern "C" void kernel_launch(void* const* d_in, const int* in_sizes, int n_in,
                              void* d_out, int out_size)
{
    const float* x    = (const float*)d_in[0];
    const float* d_w  = (const float*)d_in[1];
    const float* d_g  = (const float*)d_in[2];
    const float* d_b  = (const float*)d_in[3];
    const float* p_w  = (const float*)d_in[4];
    const float* p_g  = (const float*)d_in[5];
    const float* p_b  = (const float*)d_in[6];
    const unsigned char* mask  = (const unsigned char*)d_in[7];
    const unsigned char* smask = (const unsigned char*)d_in[8];
    const float* Wq = (const float*)d_in[9];
    const float* bq = (const float*)d_in[10];
    const float* Wk = (const float*)d_in[11];
    const float* bk = (const float*)d_in[12];
    const float* Wv = (const float*)d_in[13];
    const float* bv = (const float*)d_in[14];
    const float* Wo = (const float*)d_in[15];
    const float* bo = (const float*)d_in[16];
    const float* g0 = (const float*)d_in[17];
    const float* b0 = (const float*)d_in[18];
    const float* w1_w = (const float*)d_in[19];
    const float* w1_b = (const float*)d_in[20];
    const float* w2_w = (const float*)d_in[21];
    const float* w2_b = (const float*)d_in[22];
    const float* g1 = (const float*)d_in[23];
    const float* b1 = (const float*)d_in[24];

    float* out  = (float*)d_out;
    float* attn = out + (long)cNT * cD;   // output tuple: (out[B,T,D], attn[B,H,T,T])

    float *apre, *a, *o2, *dwn, *pwn, *bqkv;
    __half *xh, *xl, *qkvh, *qkvl, *vTh, *atth, *ctxh, *ctxl;
    __half *ah, *hh, *deph, *pth, *pwT, *w1h, *w2h;
    __half *wqkvh, *wqkvl, *woh, *wol;
    cudaGetSymbolAddress((void**)&apre, g_apre);
    cudaGetSymbolAddress((void**)&a,    g_a);
    cudaGetSymbolAddress((void**)&o2,   g_o2);
    cudaGetSymbolAddress((void**)&dwn,  g_dwn);
    cudaGetSymbolAddress((void**)&pwn,  g_pwn);
    cudaGetSymbolAddress((void**)&bqkv, g_bqkv);
    cudaGetSymbolAddress((void**)&xh,   g_xh);
    cudaGetSymbolAddress((void**)&xl,   g_xl);
    cudaGetSymbolAddress((void**)&qkvh, g_qkvh);
    cudaGetSymbolAddress((void**)&qkvl, g_qkvl);
    cudaGetSymbolAddress((void**)&vTh,  g_vTh);
    cudaGetSymbolAddress((void**)&atth, g_atth);
    cudaGetSymbolAddress((void**)&ctxh, g_ctxh);
    cudaGetSymbolAddress((void**)&ctxl, g_ctxl);
    cudaGetSymbolAddress((void**)&ah,   g_ah);
    cudaGetSymbolAddress((void**)&hh,   g_hh);
    cudaGetSymbolAddress((void**)&deph, g_deph);
    cudaGetSymbolAddress((void**)&pth,  g_pth);
    cudaGetSymbolAddress((void**)&pwT,  g_pwT);
    cudaGetSymbolAddress((void**)&w1h,  g_w1);
    cudaGetSymbolAddress((void**)&w2h,  g_w2);
    cudaGetSymbolAddress((void**)&wqkvh, g_wqkv);
    cudaGetSymbolAddress((void**)&wqkvl, g_wqkvl);
    cudaGetSymbolAddress((void**)&woh,  g_wo);
    cudaGetSymbolAddress((void**)&wol,  g_wol);

    cudaFuncSetAttribute(mma_gemm1<2>,  cudaFuncAttributeMaxDynamicSharedMemorySize, MM_SMEM1);
    cudaFuncSetAttribute(mma_gemm1<9>,  cudaFuncAttributeMaxDynamicSharedMemorySize, MM_SMEM1);
    cudaFuncSetAttribute(mma_gemm1<10>, cudaFuncAttributeMaxDynamicSharedMemorySize, MM_SMEM1);
    cudaFuncSetAttribute(mma_gemm1s<8>, cudaFuncAttributeMaxDynamicSharedMemorySize, MM_SMEM1N);
    cudaFuncSetAttribute(mma_gemm3<2>, cudaFuncAttributeMaxDynamicSharedMemorySize, MM_SMEM3);
    cudaFuncSetAttribute(mma_gemm3<6>, cudaFuncAttributeMaxDynamicSharedMemorySize, MM_SMEM3);
    cudaFuncSetAttribute(mma_gemm3sc<5>, cudaFuncAttributeMaxDynamicSharedMemorySize, MM_SMEM3S);

    dim3 blk(256);

    // 0) prep (fused: weight cvt/splits, bqkv, pwn zero, dwn)
    wprep_k<<<dim3(256, 8), blk>>>(Wq, Wk, Wv, Wo, w1_w, w2_w, bq, bk, bv, d_w,
                                   wqkvh, wqkvl, woh, wol, w1h, w2h, bqkv, pwn, dwn);
    cvtT_k<<<dim3(32, 32, cB), blk>>>(p_w, pwT, pwn);
    pwn_fin<<<(cB * cC) / 256, blk>>>(pwn);
    cvt_split_h<<<(cNT * cD) / 1024, blk>>>(x, xh, xl, (long)cNT * cD);

    // 1) fused qkv projection (split out, 3-product): [16384,256] @ [384,256]^T
    mma_gemm3<6><<<dim3(3, cNT / 128, 1), blk, MM_SMEM3>>>(
        xh, xl, wqkvh, wqkvl, nullptr, qkvh, qkvl, cD, cD, cD, 384, 384, 1,
        0, 0, 0, 0, 0, 0, 0, 0, bqkv, nullptr);

    // 2) v -> vT (fp16 single, compact 64 rows per (b,h))
    vT_k<<<dim3(32, 4, cB), blk>>>(qkvh, vTh);

    // 3) scores = q k^T / 8  [3-product, nk=1 -> 1-stage smem, occ 2]
    mma_gemm3sc<5><<<dim3(8, 8, 32), blk, MM_SMEM3S>>>(
        qkvh, qkvl, qkvh + 128, qkvl + 128, attn, cDK, 384, 384, cT, 1024, 2,
        (long)cT * 384, 64, (long)cT * 384, 64, 2 * cTT, cTT);

    // 4) masked softmax (writes final attn + fp16 single)
    softmax_k<<<dim3(cT, cH, cB), blk>>>(attn, smask, atth);

    // 5) ctx = attn @ v  [1-product, BN=64] -> exact fp16 split of fp32 result
    mma_gemm1s<8><<<dim3(1, 8, 32), blk, MM_SMEM1N>>>(
        atth, vTh, ctxh, ctxl, cT, cT, cT, 128, 64, 2,
        2 * cTT, cTT, (long)128 * cT, (long)64 * cT, (long)cT * 128, 64);

    // 6) apre = ctx @ Wo^T + bo + x  [3-product]
    mma_gemm3<2><<<dim3(2, cNT / 128, 1), blk, MM_SMEM3>>>(
        ctxh, ctxl, woh, wol, apre, nullptr, nullptr, 128, 128, 128, cD, 256, 1,
        0, 0, 0, 0, 0, 0, 0, 0, bo, x);

    // 7) a = LN(apre), masked; emit fp16 single
    ln_k<<<cNT, blk>>>(apre, g0, b0, mask, a, ah);

    // 8) h = mish(a @ w1^T + w1_b) -> fp16 single  [1-product, 3-stage, occ 2]
    mma_gemm1<9><<<dim3(cC / 128, cNT / 128, 1), blk, MM_SMEM1>>>(
        ah, w1h, nullptr, hh, cD, cD, cD, cC, 1024, 1,
        0, 0, 0, 0, 0, 0, 0, 0, w1_b, nullptr);

    // 9) tiled depthwise conv (fp16 in/out)
    conv2_k<<<dim3(cT / CV_TR, cC / 256, cB), blk>>>(hh, d_w, d_g, d_b, p_g, dwn, deph);

    // 10) pt = (dep @ pwT) * pwninv[o] + p_b -> fp16 single  [1-product, batched over b]
    mma_gemm1<10><<<dim3(cC / 128, cT / 128, cB), blk, MM_SMEM1>>>(
        deph, pwT, nullptr, pth, cC, cC, cC, cC, 1024, 1,
        (long)cT * cC, 0, (long)cC * cC, 0, (long)cT * cC, 0, cC, cC, p_b, pwn);

    // 11) o2 = pt @ w2^T + w2_b + a  [1-product]
    mma_gemm1<2><<<dim3(cD / 128, cNT / 128, 1), blk, MM_SMEM1>>>(
        pth, w2h, o2, nullptr, cC, cC, cC, cD, 256, 1,
        0, 0, 0, 0, 0, 0, 0, 0, w2_b, a);

    // 12) out = LN(o2), masked
    ln_k<<<cNT, blk>>>(o2, g1, b1, mask, out, nullptr);
}